// round 1
// baseline (speedup 1.0000x reference)
#include <cuda_runtime.h>
#include <math.h>

#define S_LEN 2048
#define BATCH 4
#define HID   1024
#define NH    16
#define DH    64
#define M_TOT (BATCH * S_LEN)      // 8192
#define FILLV (-10000000000000.0f)

// Scratch (device globals: no allocations allowed)
__device__ float g_Q[M_TOT * HID];
__device__ float g_K[M_TOT * HID];
__device__ float g_V[M_TOT * HID];
__device__ float g_A[M_TOT * HID];

// ---------------------------------------------------------------------------
// GEMM: C[M,N] = A[M,K] * W[N,K]^T + bias[N]
// 128x128 tile, BK=16, 256 threads, 8x8 per-thread microtile, fp32.
// ---------------------------------------------------------------------------
__global__ void __launch_bounds__(256)
gemm_nt_bias(const float* __restrict__ A, const float* __restrict__ W,
             const float* __restrict__ bias, float* __restrict__ C,
             int M, int N, int K)
{
    __shared__ float As[16][132];
    __shared__ float Ws[16][132];

    const int tid = threadIdx.x;
    const int tx = tid & 15;
    const int ty = tid >> 4;
    const int bm = blockIdx.y * 128;
    const int bn = blockIdx.x * 128;

    float acc[8][8];
#pragma unroll
    for (int i = 0; i < 8; i++)
#pragma unroll
        for (int j = 0; j < 8; j++) acc[i][j] = 0.0f;

    const int lrow = tid >> 2;   // 0..63
    const int lc4  = tid & 3;    // 0..3

    const float* Ap0 = A + (size_t)(bm + lrow)      * K + lc4 * 4;
    const float* Ap1 = A + (size_t)(bm + 64 + lrow) * K + lc4 * 4;
    const float* Wp0 = W + (size_t)(bn + lrow)      * K + lc4 * 4;
    const float* Wp1 = W + (size_t)(bn + 64 + lrow) * K + lc4 * 4;

    for (int k0 = 0; k0 < K; k0 += 16) {
        float4 a0 = *(const float4*)(Ap0 + k0);
        float4 a1 = *(const float4*)(Ap1 + k0);
        float4 w0 = *(const float4*)(Wp0 + k0);
        float4 w1 = *(const float4*)(Wp1 + k0);

        __syncthreads();   // previous tile fully consumed

        As[lc4*4+0][lrow]      = a0.x; As[lc4*4+1][lrow]      = a0.y;
        As[lc4*4+2][lrow]      = a0.z; As[lc4*4+3][lrow]      = a0.w;
        As[lc4*4+0][64+lrow]   = a1.x; As[lc4*4+1][64+lrow]   = a1.y;
        As[lc4*4+2][64+lrow]   = a1.z; As[lc4*4+3][64+lrow]   = a1.w;
        Ws[lc4*4+0][lrow]      = w0.x; Ws[lc4*4+1][lrow]      = w0.y;
        Ws[lc4*4+2][lrow]      = w0.z; Ws[lc4*4+3][lrow]      = w0.w;
        Ws[lc4*4+0][64+lrow]   = w1.x; Ws[lc4*4+1][64+lrow]   = w1.y;
        Ws[lc4*4+2][64+lrow]   = w1.z; Ws[lc4*4+3][64+lrow]   = w1.w;

        __syncthreads();

#pragma unroll
        for (int k = 0; k < 16; k++) {
            float af[8], wf[8];
            *(float4*)&af[0] = *(const float4*)&As[k][ty * 4];
            *(float4*)&af[4] = *(const float4*)&As[k][64 + ty * 4];
            *(float4*)&wf[0] = *(const float4*)&Ws[k][tx * 4];
            *(float4*)&wf[4] = *(const float4*)&Ws[k][64 + tx * 4];
#pragma unroll
            for (int i = 0; i < 8; i++)
#pragma unroll
                for (int j = 0; j < 8; j++)
                    acc[i][j] = fmaf(af[i], wf[j], acc[i][j]);
        }
    }

    float4 blo = *(const float4*)&bias[bn + tx * 4];
    float4 bhi = *(const float4*)&bias[bn + 64 + tx * 4];
    float bl[8] = {blo.x, blo.y, blo.z, blo.w, bhi.x, bhi.y, bhi.z, bhi.w};

#pragma unroll
    for (int i = 0; i < 8; i++) {
        int row = bm + ((i < 4) ? (ty * 4 + i) : (64 + ty * 4 + (i - 4)));
        float4 v0 = make_float4(acc[i][0] + bl[0], acc[i][1] + bl[1],
                                acc[i][2] + bl[2], acc[i][3] + bl[3]);
        float4 v1 = make_float4(acc[i][4] + bl[4], acc[i][5] + bl[5],
                                acc[i][6] + bl[6], acc[i][7] + bl[7]);
        *(float4*)(C + (size_t)row * N + bn + tx * 4)      = v0;
        *(float4*)(C + (size_t)row * N + bn + 64 + tx * 4) = v1;
    }
}

// ---------------------------------------------------------------------------
// Fused causal flash attention (fp32 SIMT).
// grid = (32 q-blocks, 16 heads, 4 batch), 256 threads.
// Qt/Kt stored d-major with XOR float4 swizzle; P tile aliases the K tile.
// smem = 3 * 16KB = 48KB exactly.
// ---------------------------------------------------------------------------
__global__ void __launch_bounds__(256)
flash_attn(const float* __restrict__ Q, const float* __restrict__ Kg,
           const float* __restrict__ Vg, const float* __restrict__ maskg,
           float* __restrict__ Og)
{
    __shared__ float Qt[64 * 64];   // [d][i], swizzled
    __shared__ float KP[64 * 64];   // Kt [d][j] (swizzled) then Pt [j][i] (swizzled)
    __shared__ float Vs[64 * 64];   // [j][n], natural

    const int tid = threadIdx.x;
    const int tx = tid & 15;        // col group
    const int ty = tid >> 4;        // row group
    const int qb = blockIdx.x;
    const int h  = blockIdx.y;
    const int b  = blockIdx.z;
    const int q0 = qb * 64;
    const size_t base = ((size_t)b * S_LEN) * HID + (size_t)h * DH;

    // Load Q tile transposed + swizzled: row d = 4*c4+q, unit-swizzle by (d>>2)=c4.
#pragma unroll
    for (int r = 0; r < 4; r++) {
        int id = tid + r * 256;
        int i  = id >> 4;           // 0..63
        int c4 = id & 15;           // 0..15
        float4 v = *(const float4*)(Q + base + (size_t)(q0 + i) * HID + c4 * 4);
        int i4 = i >> 2, ib = i & 3;
        int u = ((i4 ^ c4) << 2) + ib;
        Qt[(4 * c4 + 0) * 64 + u] = v.x;
        Qt[(4 * c4 + 1) * 64 + u] = v.y;
        Qt[(4 * c4 + 2) * 64 + u] = v.z;
        Qt[(4 * c4 + 3) * 64 + u] = v.w;
    }

    float m_i[4], l_i[4], o[4][4];
#pragma unroll
    for (int a = 0; a < 4; a++) {
        m_i[a] = -INFINITY; l_i[a] = 0.0f;
#pragma unroll
        for (int c = 0; c < 4; c++) o[a][c] = 0.0f;
    }

    for (int jb = 0; jb <= qb; jb++) {
        const int k0 = jb * 64;
        __syncthreads();   // prev-iter PV readers done; also Qt visible on iter 0

        // Load K (transposed+swizzled into KP) and V (natural into Vs)
#pragma unroll
        for (int r = 0; r < 4; r++) {
            int id = tid + r * 256;
            int j  = id >> 4;
            int c4 = id & 15;
            float4 kv = *(const float4*)(Kg + base + (size_t)(k0 + j) * HID + c4 * 4);
            int j4 = j >> 2, jb3 = j & 3;
            int u = ((j4 ^ c4) << 2) + jb3;
            KP[(4 * c4 + 0) * 64 + u] = kv.x;
            KP[(4 * c4 + 1) * 64 + u] = kv.y;
            KP[(4 * c4 + 2) * 64 + u] = kv.z;
            KP[(4 * c4 + 3) * 64 + u] = kv.w;
            float4 vv = *(const float4*)(Vg + base + (size_t)(k0 + j) * HID + c4 * 4);
            *(float4*)&Vs[j * 64 + c4 * 4] = vv;
        }
        __syncthreads();

        // S = Q K^T (4x4 per thread)
        float s[4][4];
#pragma unroll
        for (int a = 0; a < 4; a++)
#pragma unroll
            for (int bb = 0; bb < 4; bb++) s[a][bb] = 0.0f;

#pragma unroll
        for (int d = 0; d < 64; d++) {
            int d4 = d >> 2;
            float qv[4], kv4[4];
            *(float4*)qv  = *(const float4*)&Qt[d * 64 + ((ty ^ d4) << 2)];
            *(float4*)kv4 = *(const float4*)&KP[d * 64 + ((tx ^ d4) << 2)];
#pragma unroll
            for (int a = 0; a < 4; a++)
#pragma unroll
                for (int bb = 0; bb < 4; bb++)
                    s[a][bb] = fmaf(qv[a], kv4[bb], s[a][bb]);
        }

        // scale + causal + padding mask (match reference FILL semantics)
        float mk[4];
#pragma unroll
        for (int bb = 0; bb < 4; bb++)
            mk[bb] = maskg[(size_t)b * S_LEN + k0 + 4 * tx + bb];
#pragma unroll
        for (int a = 0; a < 4; a++) {
            int ig = q0 + 4 * ty + a;
#pragma unroll
            for (int bb = 0; bb < 4; bb++) {
                int jg = k0 + 4 * tx + bb;
                float val = s[a][bb] * 0.125f;
                s[a][bb] = (jg > ig || mk[bb] == 0.0f) ? FILLV : val;
            }
        }

        // online softmax, row state replicated across the 16-lane row group
#pragma unroll
        for (int a = 0; a < 4; a++) {
            float rmax = fmaxf(fmaxf(s[a][0], s[a][1]), fmaxf(s[a][2], s[a][3]));
#pragma unroll
            for (int off = 8; off >= 1; off >>= 1)
                rmax = fmaxf(rmax, __shfl_xor_sync(0xffffffffu, rmax, off));
            float mnew = fmaxf(m_i[a], rmax);
            float corr = __expf(m_i[a] - mnew);
            float rsum = 0.0f;
#pragma unroll
            for (int bb = 0; bb < 4; bb++) {
                s[a][bb] = __expf(s[a][bb] - mnew);
                rsum += s[a][bb];
            }
#pragma unroll
            for (int off = 8; off >= 1; off >>= 1)
                rsum += __shfl_xor_sync(0xffffffffu, rsum, off);
            l_i[a] = l_i[a] * corr + rsum;
            m_i[a] = mnew;
#pragma unroll
            for (int c = 0; c < 4; c++) o[a][c] *= corr;
        }

        __syncthreads();   // all threads done reading KP as K before P overwrite

        // write P transposed+swizzled into KP: Pt[j][i], j>>2 == tx
#pragma unroll
        for (int bb = 0; bb < 4; bb++) {
            int j = 4 * tx + bb;
            float4 pv = make_float4(s[0][bb], s[1][bb], s[2][bb], s[3][bb]);
            *(float4*)&KP[j * 64 + ((ty ^ tx) << 2)] = pv;
        }
        __syncthreads();

        // O += P * V
#pragma unroll
        for (int j = 0; j < 64; j++) {
            float pf[4], vf[4];
            *(float4*)pf = *(const float4*)&KP[j * 64 + ((ty ^ (j >> 2)) << 2)];
            *(float4*)vf = *(const float4*)&Vs[j * 64 + 4 * tx];
#pragma unroll
            for (int a = 0; a < 4; a++)
#pragma unroll
                for (int c = 0; c < 4; c++)
                    o[a][c] = fmaf(pf[a], vf[c], o[a][c]);
        }
    }

    // epilogue: normalize and store
#pragma unroll
    for (int a = 0; a < 4; a++) {
        float inv = 1.0f / l_i[a];
        float4 out = make_float4(o[a][0] * inv, o[a][1] * inv,
                                 o[a][2] * inv, o[a][3] * inv);
        *(float4*)(Og + base + (size_t)(q0 + 4 * ty + a) * HID + 4 * tx) = out;
    }
}

// ---------------------------------------------------------------------------
extern "C" void kernel_launch(void* const* d_in, const int* in_sizes, int n_in,
                              void* d_out, int out_size)
{
    const float* q    = (const float*)d_in[0];
    const float* k    = (const float*)d_in[1];
    const float* v    = (const float*)d_in[2];
    const float* mask = (const float*)d_in[3];
    const float* Wq   = (const float*)d_in[4];
    const float* bq   = (const float*)d_in[5];
    const float* Wk   = (const float*)d_in[6];
    const float* bk   = (const float*)d_in[7];
    const float* Wv   = (const float*)d_in[8];
    const float* bv   = (const float*)d_in[9];
    const float* Wo   = (const float*)d_in[10];
    const float* bo   = (const float*)d_in[11];
    float* out = (float*)d_out;

    float *pQ, *pK, *pV, *pA;
    cudaGetSymbolAddress((void**)&pQ, g_Q);
    cudaGetSymbolAddress((void**)&pK, g_K);
    cudaGetSymbolAddress((void**)&pV, g_V);
    cudaGetSymbolAddress((void**)&pA, g_A);

    dim3 ggrid(HID / 128, M_TOT / 128);   // (8, 64)
    gemm_nt_bias<<<ggrid, 256>>>(q, Wq, bq, pQ, M_TOT, HID, HID);
    gemm_nt_bias<<<ggrid, 256>>>(k, Wk, bk, pK, M_TOT, HID, HID);
    gemm_nt_bias<<<ggrid, 256>>>(v, Wv, bv, pV, M_TOT, HID, HID);

    flash_attn<<<dim3(S_LEN / 64, NH, BATCH), 256>>>(pQ, pK, pV, mask, pA);

    gemm_nt_bias<<<ggrid, 256>>>(pA, Wo, bo, out, M_TOT, HID, HID);
}

// round 3
// speedup vs baseline: 1.5432x; 1.5432x over previous
#include <cuda_runtime.h>
#include <cuda_bf16.h>
#include <cstdint>
#include <math.h>

#define S_LEN 2048
#define BATCH 4
#define HID   1024
#define NH    16
#define DH    64
#define M_TOT (BATCH * S_LEN)      // 8192
#define FILLV (-10000000000000.0f)

// Scratch (device globals: no allocations allowed)
__device__ float g_Q[M_TOT * HID];
__device__ float g_K[M_TOT * HID];
__device__ float g_V[M_TOT * HID];
__device__ float g_A[M_TOT * HID];

// ===========================================================================
// helpers
// ===========================================================================
__device__ __forceinline__ uint32_t smem_u32(const void* p) {
    uint32_t a;
    asm("{ .reg .u64 t; cvta.to.shared.u64 t, %1; cvt.u32.u64 %0, t; }"
        : "=r"(a) : "l"(p));
    return a;
}

#define LDSM_X4(r0, r1, r2, r3, addr)                                         \
    asm volatile("ldmatrix.sync.aligned.m8n8.x4.shared.b16 {%0,%1,%2,%3}, [%4];" \
                 : "=r"(r0), "=r"(r1), "=r"(r2), "=r"(r3) : "r"(addr))

#define MMA16816(d, a0, a1, a2, a3, b0, b1)                                   \
    asm volatile("mma.sync.aligned.m16n8k16.row.col.f32.bf16.bf16.f32 "       \
                 "{%0,%1,%2,%3}, {%4,%5,%6,%7}, {%8,%9}, {%0,%1,%2,%3};"      \
                 : "+f"((d)[0]), "+f"((d)[1]), "+f"((d)[2]), "+f"((d)[3])     \
                 : "r"(a0), "r"(a1), "r"(a2), "r"(a3), "r"(b0), "r"(b1))

__device__ __forceinline__ uint32_t pack_bf2(float x, float y) {
    __nv_bfloat16 bx = __float2bfloat16_rn(x);
    __nv_bfloat16 by = __float2bfloat16_rn(y);
    return (uint32_t)__bfloat16_as_ushort(bx)
         | ((uint32_t)__bfloat16_as_ushort(by) << 16);
}

// split float4 into bf16 hi-pack and lo-pack (2-term split)
__device__ __forceinline__ void split4(const float4& v, uint2& hi, uint2& lo) {
    __nv_bfloat16 h0 = __float2bfloat16_rn(v.x);
    __nv_bfloat16 h1 = __float2bfloat16_rn(v.y);
    __nv_bfloat16 h2 = __float2bfloat16_rn(v.z);
    __nv_bfloat16 h3 = __float2bfloat16_rn(v.w);
    float l0 = v.x - __bfloat162float(h0);
    float l1 = v.y - __bfloat162float(h1);
    float l2 = v.z - __bfloat162float(h2);
    float l3 = v.w - __bfloat162float(h3);
    hi.x = (uint32_t)__bfloat16_as_ushort(h0)
         | ((uint32_t)__bfloat16_as_ushort(h1) << 16);
    hi.y = (uint32_t)__bfloat16_as_ushort(h2)
         | ((uint32_t)__bfloat16_as_ushort(h3) << 16);
    lo.x = pack_bf2(l0, l1);
    lo.y = pack_bf2(l2, l3);
}

// ===========================================================================
// GEMM: C[M=8192, N=1024] = A * W^T + bias via mma.sync bf16 2-term split.
// CTA 128x128, BK=16, 8 warps (2x4), warp tile 64x32, double-buffered smem.
// smem stage layout (16KB): Ah[4KB] Al[4KB] Wh[4KB] Wl[4KB], rows of 32B,
// swizzle phys(row,g) = row*32 + ((g ^ ((row>>2)&1))<<4).
// ===========================================================================
#define GK 1024
#define NC 64               // 1024 / 16
#define STAGE_B 16384

__global__ void __launch_bounds__(256)
gemm_mma(const float* __restrict__ A, const float* __restrict__ W,
         const float* __restrict__ bias, float* __restrict__ C)
{
    __shared__ __align__(128) uint8_t sm[2 * STAGE_B];
    const uint32_t sb = smem_u32(sm);
    const int tid  = threadIdx.x;
    const int lane = tid & 31;
    const int warp = tid >> 5;
    const int wm   = warp >> 2;     // 0..1
    const int wn   = warp & 3;      // 0..3
    const int bm   = blockIdx.y * 128;
    const int bn   = blockIdx.x * 128;

    // ldmatrix per-lane byte offsets (within one term's 4KB tile)
    const int lr = lane & 7;
    const int ml = lane >> 3;
    uint32_t offA[4], offW[2];
#pragma unroll
    for (int mt = 0; mt < 4; mt++) {
        int row = wm * 64 + mt * 16 + (ml & 1) * 8 + lr;
        int g   = ml >> 1;
        offA[mt] = row * 32 + ((uint32_t)(g ^ ((row >> 2) & 1)) << 4);
    }
#pragma unroll
    for (int p = 0; p < 2; p++) {
        int row = wn * 32 + p * 16 + (ml >> 1) * 8 + lr;
        int g   = ml & 1;
        offW[p] = row * 32 + ((uint32_t)(g ^ ((row >> 2) & 1)) << 4);
    }

    // STS slots: flat f = tid + j*256 over 512 float4 per matrix
    int srow[2], sq[2], ssw[2];
#pragma unroll
    for (int j = 0; j < 2; j++) {
        int f = tid + j * 256;
        srow[j] = f >> 2;
        sq[j]   = f & 3;
        int g   = sq[j] >> 1;
        ssw[j]  = srow[j] * 32 + ((g ^ ((srow[j] >> 2) & 1)) << 4)
                + (sq[j] & 1) * 8;
    }

    const float* Ab = A + (size_t)bm * GK;
    const float* Wb = W + (size_t)bn * GK;

    float acc[4][4][4];
#pragma unroll
    for (int mt = 0; mt < 4; mt++)
#pragma unroll
        for (int nt = 0; nt < 4; nt++)
#pragma unroll
            for (int r = 0; r < 4; r++) acc[mt][nt][r] = 0.0f;

    float4 av[2], wv[2];
    // prologue: load + store chunk 0
#pragma unroll
    for (int j = 0; j < 2; j++) {
        av[j] = *(const float4*)(Ab + (size_t)srow[j] * GK + sq[j] * 4);
        wv[j] = *(const float4*)(Wb + (size_t)srow[j] * GK + sq[j] * 4);
    }
#pragma unroll
    for (int j = 0; j < 2; j++) {
        uint2 hi, lo;
        split4(av[j], hi, lo);
        *(uint2*)(sm + ssw[j])        = hi;
        *(uint2*)(sm + 4096 + ssw[j]) = lo;
        split4(wv[j], hi, lo);
        *(uint2*)(sm + 8192 + ssw[j])  = hi;
        *(uint2*)(sm + 12288 + ssw[j]) = lo;
    }
    __syncthreads();

    for (int c = 0; c < NC; c++) {
        // prefetch next chunk
        if (c < NC - 1) {
            int k0 = (c + 1) * 16;
#pragma unroll
            for (int j = 0; j < 2; j++) {
                av[j] = *(const float4*)(Ab + (size_t)srow[j] * GK + k0 + sq[j] * 4);
                wv[j] = *(const float4*)(Wb + (size_t)srow[j] * GK + k0 + sq[j] * 4);
            }
        }

        // compute current stage
        {
            const uint32_t sA = sb + (uint32_t)(c & 1) * STAGE_B;
            uint32_t ah[4][4], al[4][4], wh[2][4], wl[2][4];
#pragma unroll
            for (int mt = 0; mt < 4; mt++) {
                LDSM_X4(ah[mt][0], ah[mt][1], ah[mt][2], ah[mt][3], sA + offA[mt]);
                LDSM_X4(al[mt][0], al[mt][1], al[mt][2], al[mt][3], sA + 4096 + offA[mt]);
            }
#pragma unroll
            for (int p = 0; p < 2; p++) {
                LDSM_X4(wh[p][0], wh[p][1], wh[p][2], wh[p][3], sA + 8192 + offW[p]);
                LDSM_X4(wl[p][0], wl[p][1], wl[p][2], wl[p][3], sA + 12288 + offW[p]);
            }
#pragma unroll
            for (int mt = 0; mt < 4; mt++)
#pragma unroll
                for (int p = 0; p < 2; p++)
#pragma unroll
                    for (int j2 = 0; j2 < 2; j2++) {
                        int nt = 2 * p + j2;
                        MMA16816(acc[mt][nt], ah[mt][0], ah[mt][1], ah[mt][2], ah[mt][3],
                                 wh[p][2 * j2], wh[p][2 * j2 + 1]);
                        MMA16816(acc[mt][nt], ah[mt][0], ah[mt][1], ah[mt][2], ah[mt][3],
                                 wl[p][2 * j2], wl[p][2 * j2 + 1]);
                        MMA16816(acc[mt][nt], al[mt][0], al[mt][1], al[mt][2], al[mt][3],
                                 wh[p][2 * j2], wh[p][2 * j2 + 1]);
                    }
        }

        // store next stage
        if (c < NC - 1) {
            uint8_t* st = sm + ((c + 1) & 1) * STAGE_B;
#pragma unroll
            for (int j = 0; j < 2; j++) {
                uint2 hi, lo;
                split4(av[j], hi, lo);
                *(uint2*)(st + ssw[j])        = hi;
                *(uint2*)(st + 4096 + ssw[j]) = lo;
                split4(wv[j], hi, lo);
                *(uint2*)(st + 8192 + ssw[j])  = hi;
                *(uint2*)(st + 12288 + ssw[j]) = lo;
            }
        }
        __syncthreads();
    }

    // epilogue: acc layout c0,c1 -> row = lane>>2, cols 2*(lane&3); c2,c3 -> row+8
#pragma unroll
    for (int mt = 0; mt < 4; mt++) {
        int r0 = bm + wm * 64 + mt * 16 + (lane >> 2);
#pragma unroll
        for (int nt = 0; nt < 4; nt++) {
            int cg = bn + wn * 32 + nt * 8 + (lane & 3) * 2;
            float2 bz = *(const float2*)(bias + cg);
            float2 v0 = make_float2(acc[mt][nt][0] + bz.x, acc[mt][nt][1] + bz.y);
            float2 v1 = make_float2(acc[mt][nt][2] + bz.x, acc[mt][nt][3] + bz.y);
            *(float2*)(C + (size_t)r0 * HID + cg)       = v0;
            *(float2*)(C + (size_t)(r0 + 8) * HID + cg) = v1;
        }
    }
}

// ---------------------------------------------------------------------------
// Fused causal flash attention (fp32 SIMT) — unchanged from round 1.
// ---------------------------------------------------------------------------
__global__ void __launch_bounds__(256)
flash_attn(const float* __restrict__ Q, const float* __restrict__ Kg,
           const float* __restrict__ Vg, const float* __restrict__ maskg,
           float* __restrict__ Og)
{
    __shared__ float Qt[64 * 64];
    __shared__ float KP[64 * 64];
    __shared__ float Vs[64 * 64];

    const int tid = threadIdx.x;
    const int tx = tid & 15;
    const int ty = tid >> 4;
    const int qb = blockIdx.x;
    const int h  = blockIdx.y;
    const int b  = blockIdx.z;
    const int q0 = qb * 64;
    const size_t base = ((size_t)b * S_LEN) * HID + (size_t)h * DH;

#pragma unroll
    for (int r = 0; r < 4; r++) {
        int id = tid + r * 256;
        int i  = id >> 4;
        int c4 = id & 15;
        float4 v = *(const float4*)(Q + base + (size_t)(q0 + i) * HID + c4 * 4);
        int i4 = i >> 2, ib = i & 3;
        int u = ((i4 ^ c4) << 2) + ib;
        Qt[(4 * c4 + 0) * 64 + u] = v.x;
        Qt[(4 * c4 + 1) * 64 + u] = v.y;
        Qt[(4 * c4 + 2) * 64 + u] = v.z;
        Qt[(4 * c4 + 3) * 64 + u] = v.w;
    }

    float m_i[4], l_i[4], o[4][4];
#pragma unroll
    for (int a = 0; a < 4; a++) {
        m_i[a] = -INFINITY; l_i[a] = 0.0f;
#pragma unroll
        for (int c = 0; c < 4; c++) o[a][c] = 0.0f;
    }

    for (int jb = 0; jb <= qb; jb++) {
        const int k0 = jb * 64;
        __syncthreads();

#pragma unroll
        for (int r = 0; r < 4; r++) {
            int id = tid + r * 256;
            int j  = id >> 4;
            int c4 = id & 15;
            float4 kv = *(const float4*)(Kg + base + (size_t)(k0 + j) * HID + c4 * 4);
            int j4 = j >> 2, jb3 = j & 3;
            int u = ((j4 ^ c4) << 2) + jb3;
            KP[(4 * c4 + 0) * 64 + u] = kv.x;
            KP[(4 * c4 + 1) * 64 + u] = kv.y;
            KP[(4 * c4 + 2) * 64 + u] = kv.z;
            KP[(4 * c4 + 3) * 64 + u] = kv.w;
            float4 vv = *(const float4*)(Vg + base + (size_t)(k0 + j) * HID + c4 * 4);
            *(float4*)&Vs[j * 64 + c4 * 4] = vv;
        }
        __syncthreads();

        float s[4][4];
#pragma unroll
        for (int a = 0; a < 4; a++)
#pragma unroll
            for (int bb = 0; bb < 4; bb++) s[a][bb] = 0.0f;

#pragma unroll
        for (int d = 0; d < 64; d++) {
            int d4 = d >> 2;
            float qv[4], kv4[4];
            *(float4*)qv  = *(const float4*)&Qt[d * 64 + ((ty ^ d4) << 2)];
            *(float4*)kv4 = *(const float4*)&KP[d * 64 + ((tx ^ d4) << 2)];
#pragma unroll
            for (int a = 0; a < 4; a++)
#pragma unroll
                for (int bb = 0; bb < 4; bb++)
                    s[a][bb] = fmaf(qv[a], kv4[bb], s[a][bb]);
        }

        float mk[4];
#pragma unroll
        for (int bb = 0; bb < 4; bb++)
            mk[bb] = maskg[(size_t)b * S_LEN + k0 + 4 * tx + bb];
#pragma unroll
        for (int a = 0; a < 4; a++) {
            int ig = q0 + 4 * ty + a;
#pragma unroll
            for (int bb = 0; bb < 4; bb++) {
                int jg = k0 + 4 * tx + bb;
                float val = s[a][bb] * 0.125f;
                s[a][bb] = (jg > ig || mk[bb] == 0.0f) ? FILLV : val;
            }
        }

#pragma unroll
        for (int a = 0; a < 4; a++) {
            float rmax = fmaxf(fmaxf(s[a][0], s[a][1]), fmaxf(s[a][2], s[a][3]));
#pragma unroll
            for (int off = 8; off >= 1; off >>= 1)
                rmax = fmaxf(rmax, __shfl_xor_sync(0xffffffffu, rmax, off));
            float mnew = fmaxf(m_i[a], rmax);
            float corr = __expf(m_i[a] - mnew);
            float rsum = 0.0f;
#pragma unroll
            for (int bb = 0; bb < 4; bb++) {
                s[a][bb] = __expf(s[a][bb] - mnew);
                rsum += s[a][bb];
            }
#pragma unroll
            for (int off = 8; off >= 1; off >>= 1)
                rsum += __shfl_xor_sync(0xffffffffu, rsum, off);
            l_i[a] = l_i[a] * corr + rsum;
            m_i[a] = mnew;
#pragma unroll
            for (int c = 0; c < 4; c++) o[a][c] *= corr;
        }

        __syncthreads();

#pragma unroll
        for (int bb = 0; bb < 4; bb++) {
            int j = 4 * tx + bb;
            float4 pv = make_float4(s[0][bb], s[1][bb], s[2][bb], s[3][bb]);
            *(float4*)&KP[j * 64 + ((ty ^ tx) << 2)] = pv;
        }
        __syncthreads();

#pragma unroll
        for (int j = 0; j < 64; j++) {
            float pf[4], vf[4];
            *(float4*)pf = *(const float4*)&KP[j * 64 + ((ty ^ (j >> 2)) << 2)];
            *(float4*)vf = *(const float4*)&Vs[j * 64 + 4 * tx];
#pragma unroll
            for (int a = 0; a < 4; a++)
#pragma unroll
                for (int c = 0; c < 4; c++)
                    o[a][c] = fmaf(pf[a], vf[c], o[a][c]);
        }
    }

#pragma unroll
    for (int a = 0; a < 4; a++) {
        float inv = 1.0f / l_i[a];
        float4 out = make_float4(o[a][0] * inv, o[a][1] * inv,
                                 o[a][2] * inv, o[a][3] * inv);
        *(float4*)(Og + base + (size_t)(q0 + 4 * ty + a) * HID + 4 * tx) = out;
    }
}

// ---------------------------------------------------------------------------
extern "C" void kernel_launch(void* const* d_in, const int* in_sizes, int n_in,
                              void* d_out, int out_size)
{
    const float* q    = (const float*)d_in[0];
    const float* k    = (const float*)d_in[1];
    const float* v    = (const float*)d_in[2];
    const float* mask = (const float*)d_in[3];
    const float* Wq   = (const float*)d_in[4];
    const float* bq   = (const float*)d_in[5];
    const float* Wk   = (const float*)d_in[6];
    const float* bk   = (const float*)d_in[7];
    const float* Wv   = (const float*)d_in[8];
    const float* bv   = (const float*)d_in[9];
    const float* Wo   = (const float*)d_in[10];
    const float* bo   = (const float*)d_in[11];
    float* out = (float*)d_out;

    float *pQ, *pK, *pV, *pA;
    cudaGetSymbolAddress((void**)&pQ, g_Q);
    cudaGetSymbolAddress((void**)&pK, g_K);
    cudaGetSymbolAddress((void**)&pV, g_V);
    cudaGetSymbolAddress((void**)&pA, g_A);

    dim3 ggrid(HID / 128, M_TOT / 128);   // (8, 64)
    gemm_mma<<<ggrid, 256>>>(q, Wq, bq, pQ);
    gemm_mma<<<ggrid, 256>>>(k, Wk, bk, pK);
    gemm_mma<<<ggrid, 256>>>(v, Wv, bv, pV);

    flash_attn<<<dim3(S_LEN / 64, NH, BATCH), 256>>>(pQ, pK, pV, mask, pA);

    gemm_mma<<<ggrid, 256>>>(pA, Wo, bo, out);
}

// round 4
// speedup vs baseline: 2.2102x; 1.4322x over previous
#include <cuda_runtime.h>
#include <cuda_bf16.h>
#include <cstdint>
#include <math.h>

#define S_LEN 2048
#define BATCH 4
#define HID   1024
#define NH    16
#define DH    64
#define M_TOT (BATCH * S_LEN)      // 8192
#define FILLV (-10000000000000.0f)

// Scratch (device globals: no allocations allowed)
__device__ float g_Q[M_TOT * HID];
__device__ float g_K[M_TOT * HID];
__device__ float g_V[M_TOT * HID];
__device__ float g_A[M_TOT * HID];

// ===========================================================================
// helpers
// ===========================================================================
__device__ __forceinline__ uint32_t smem_u32(const void* p) {
    uint32_t a;
    asm("{ .reg .u64 t; cvta.to.shared.u64 t, %1; cvt.u32.u64 %0, t; }"
        : "=r"(a) : "l"(p));
    return a;
}

#define LDSM_X4(r0, r1, r2, r3, addr)                                         \
    asm volatile("ldmatrix.sync.aligned.m8n8.x4.shared.b16 {%0,%1,%2,%3}, [%4];" \
                 : "=r"(r0), "=r"(r1), "=r"(r2), "=r"(r3) : "r"(addr))

#define LDSM_X4_T(r0, r1, r2, r3, addr)                                       \
    asm volatile("ldmatrix.sync.aligned.m8n8.x4.trans.shared.b16 {%0,%1,%2,%3}, [%4];" \
                 : "=r"(r0), "=r"(r1), "=r"(r2), "=r"(r3) : "r"(addr))

#define MMA16816(d, a0, a1, a2, a3, b0, b1)                                   \
    asm volatile("mma.sync.aligned.m16n8k16.row.col.f32.bf16.bf16.f32 "       \
                 "{%0,%1,%2,%3}, {%4,%5,%6,%7}, {%8,%9}, {%0,%1,%2,%3};"      \
                 : "+f"((d)[0]), "+f"((d)[1]), "+f"((d)[2]), "+f"((d)[3])     \
                 : "r"(a0), "r"(a1), "r"(a2), "r"(a3), "r"(b0), "r"(b1))

__device__ __forceinline__ uint32_t pack_bf2(float x, float y) {
    __nv_bfloat16 bx = __float2bfloat16_rn(x);
    __nv_bfloat16 by = __float2bfloat16_rn(y);
    return (uint32_t)__bfloat16_as_ushort(bx)
         | ((uint32_t)__bfloat16_as_ushort(by) << 16);
}

// split float4 into bf16 hi-pack and lo-pack (2-term split)
__device__ __forceinline__ void split4(const float4& v, uint2& hi, uint2& lo) {
    __nv_bfloat16 h0 = __float2bfloat16_rn(v.x);
    __nv_bfloat16 h1 = __float2bfloat16_rn(v.y);
    __nv_bfloat16 h2 = __float2bfloat16_rn(v.z);
    __nv_bfloat16 h3 = __float2bfloat16_rn(v.w);
    float l0 = v.x - __bfloat162float(h0);
    float l1 = v.y - __bfloat162float(h1);
    float l2 = v.z - __bfloat162float(h2);
    float l3 = v.w - __bfloat162float(h3);
    hi.x = (uint32_t)__bfloat16_as_ushort(h0)
         | ((uint32_t)__bfloat16_as_ushort(h1) << 16);
    hi.y = (uint32_t)__bfloat16_as_ushort(h2)
         | ((uint32_t)__bfloat16_as_ushort(h3) << 16);
    lo.x = pack_bf2(l0, l1);
    lo.y = pack_bf2(l2, l3);
}

__device__ __forceinline__ void split2(float x, float y, uint32_t& hi, uint32_t& lo) {
    __nv_bfloat16 hx = __float2bfloat16_rn(x);
    __nv_bfloat16 hy = __float2bfloat16_rn(y);
    hi = (uint32_t)__bfloat16_as_ushort(hx)
       | ((uint32_t)__bfloat16_as_ushort(hy) << 16);
    lo = pack_bf2(x - __bfloat162float(hx), y - __bfloat162float(hy));
}

// ===========================================================================
// GEMM: C[M=8192, N=1024] = A * W^T + bias via mma.sync bf16 2-term split.
// (unchanged from round 3 — verified)
// ===========================================================================
#define GK 1024
#define NC 64
#define STAGE_B 16384

__global__ void __launch_bounds__(256)
gemm_mma(const float* __restrict__ A, const float* __restrict__ W,
         const float* __restrict__ bias, float* __restrict__ C)
{
    __shared__ __align__(128) uint8_t sm[2 * STAGE_B];
    const uint32_t sb = smem_u32(sm);
    const int tid  = threadIdx.x;
    const int lane = tid & 31;
    const int warp = tid >> 5;
    const int wm   = warp >> 2;
    const int wn   = warp & 3;
    const int bm   = blockIdx.y * 128;
    const int bn   = blockIdx.x * 128;

    const int lr = lane & 7;
    const int ml = lane >> 3;
    uint32_t offA[4], offW[2];
#pragma unroll
    for (int mt = 0; mt < 4; mt++) {
        int row = wm * 64 + mt * 16 + (ml & 1) * 8 + lr;
        int g   = ml >> 1;
        offA[mt] = row * 32 + ((uint32_t)(g ^ ((row >> 2) & 1)) << 4);
    }
#pragma unroll
    for (int p = 0; p < 2; p++) {
        int row = wn * 32 + p * 16 + (ml >> 1) * 8 + lr;
        int g   = ml & 1;
        offW[p] = row * 32 + ((uint32_t)(g ^ ((row >> 2) & 1)) << 4);
    }

    int srow[2], sq[2], ssw[2];
#pragma unroll
    for (int j = 0; j < 2; j++) {
        int f = tid + j * 256;
        srow[j] = f >> 2;
        sq[j]   = f & 3;
        int g   = sq[j] >> 1;
        ssw[j]  = srow[j] * 32 + ((g ^ ((srow[j] >> 2) & 1)) << 4)
                + (sq[j] & 1) * 8;
    }

    const float* Ab = A + (size_t)bm * GK;
    const float* Wb = W + (size_t)bn * GK;

    float acc[4][4][4];
#pragma unroll
    for (int mt = 0; mt < 4; mt++)
#pragma unroll
        for (int nt = 0; nt < 4; nt++)
#pragma unroll
            for (int r = 0; r < 4; r++) acc[mt][nt][r] = 0.0f;

    float4 av[2], wv[2];
#pragma unroll
    for (int j = 0; j < 2; j++) {
        av[j] = *(const float4*)(Ab + (size_t)srow[j] * GK + sq[j] * 4);
        wv[j] = *(const float4*)(Wb + (size_t)srow[j] * GK + sq[j] * 4);
    }
#pragma unroll
    for (int j = 0; j < 2; j++) {
        uint2 hi, lo;
        split4(av[j], hi, lo);
        *(uint2*)(sm + ssw[j])        = hi;
        *(uint2*)(sm + 4096 + ssw[j]) = lo;
        split4(wv[j], hi, lo);
        *(uint2*)(sm + 8192 + ssw[j])  = hi;
        *(uint2*)(sm + 12288 + ssw[j]) = lo;
    }
    __syncthreads();

    for (int c = 0; c < NC; c++) {
        if (c < NC - 1) {
            int k0 = (c + 1) * 16;
#pragma unroll
            for (int j = 0; j < 2; j++) {
                av[j] = *(const float4*)(Ab + (size_t)srow[j] * GK + k0 + sq[j] * 4);
                wv[j] = *(const float4*)(Wb + (size_t)srow[j] * GK + k0 + sq[j] * 4);
            }
        }
        {
            const uint32_t sA = sb + (uint32_t)(c & 1) * STAGE_B;
            uint32_t ah[4][4], al[4][4], wh[2][4], wl[2][4];
#pragma unroll
            for (int mt = 0; mt < 4; mt++) {
                LDSM_X4(ah[mt][0], ah[mt][1], ah[mt][2], ah[mt][3], sA + offA[mt]);
                LDSM_X4(al[mt][0], al[mt][1], al[mt][2], al[mt][3], sA + 4096 + offA[mt]);
            }
#pragma unroll
            for (int p = 0; p < 2; p++) {
                LDSM_X4(wh[p][0], wh[p][1], wh[p][2], wh[p][3], sA + 8192 + offW[p]);
                LDSM_X4(wl[p][0], wl[p][1], wl[p][2], wl[p][3], sA + 12288 + offW[p]);
            }
#pragma unroll
            for (int mt = 0; mt < 4; mt++)
#pragma unroll
                for (int p = 0; p < 2; p++)
#pragma unroll
                    for (int j2 = 0; j2 < 2; j2++) {
                        int nt = 2 * p + j2;
                        MMA16816(acc[mt][nt], ah[mt][0], ah[mt][1], ah[mt][2], ah[mt][3],
                                 wh[p][2 * j2], wh[p][2 * j2 + 1]);
                        MMA16816(acc[mt][nt], ah[mt][0], ah[mt][1], ah[mt][2], ah[mt][3],
                                 wl[p][2 * j2], wl[p][2 * j2 + 1]);
                        MMA16816(acc[mt][nt], al[mt][0], al[mt][1], al[mt][2], al[mt][3],
                                 wh[p][2 * j2], wh[p][2 * j2 + 1]);
                    }
        }
        if (c < NC - 1) {
            uint8_t* st = sm + ((c + 1) & 1) * STAGE_B;
#pragma unroll
            for (int j = 0; j < 2; j++) {
                uint2 hi, lo;
                split4(av[j], hi, lo);
                *(uint2*)(st + ssw[j])        = hi;
                *(uint2*)(st + 4096 + ssw[j]) = lo;
                split4(wv[j], hi, lo);
                *(uint2*)(st + 8192 + ssw[j])  = hi;
                *(uint2*)(st + 12288 + ssw[j]) = lo;
            }
        }
        __syncthreads();
    }

#pragma unroll
    for (int mt = 0; mt < 4; mt++) {
        int r0 = bm + wm * 64 + mt * 16 + (lane >> 2);
#pragma unroll
        for (int nt = 0; nt < 4; nt++) {
            int cg = bn + wn * 32 + nt * 8 + (lane & 3) * 2;
            float2 bz = *(const float2*)(bias + cg);
            float2 v0 = make_float2(acc[mt][nt][0] + bz.x, acc[mt][nt][1] + bz.y);
            float2 v1 = make_float2(acc[mt][nt][2] + bz.x, acc[mt][nt][3] + bz.y);
            *(float2*)(C + (size_t)r0 * HID + cg)       = v0;
            *(float2*)(C + (size_t)(r0 + 8) * HID + cg) = v1;
        }
    }
}

// ===========================================================================
// Tensor-core causal flash attention (mma.sync bf16 2-term split).
// BQ=128, BKV=64, 8 warps (warp w owns rows 16w..16w+16), grid (16,16,4).
// smem rows are 128B with unit-XOR swizzle phys = row*128 + ((u^(row&7))<<4).
// ===========================================================================
__global__ void __launch_bounds__(256)
flash_mma(const float* __restrict__ Qg, const float* __restrict__ Kg,
          const float* __restrict__ Vg, const float* __restrict__ maskg,
          float* __restrict__ Og)
{
    __shared__ __align__(128) uint8_t sbuf[33024];
    // regions: Kh @0 (8KB), Kl @8192, Vh @16384, Vl @24576, mask @32768
    // Q staging (prologue only): Qh @0 (16KB), Ql @16384 (16KB)
    float* smask = (float*)(sbuf + 32768);

    const int tid  = threadIdx.x;
    const int lane = tid & 31;
    const int w    = tid >> 5;
    const int lr   = lane & 7;
    const int ml   = lane >> 3;
    const int qb   = blockIdx.x;
    const int h    = blockIdx.y;
    const int b    = blockIdx.z;
    const int q0   = qb * 128;
    const size_t base = ((size_t)b * S_LEN) * HID + (size_t)h * DH;

    // ---- stage Q (fp32 -> bf16 hi/lo, swizzled) ----
#pragma unroll
    for (int j = 0; j < 8; j++) {
        int f = tid + j * 256;              // 2048 float4 = 128 rows x 16
        int row = f >> 4, q = f & 15;
        float4 v = *(const float4*)(Qg + base + (size_t)(q0 + row) * HID + q * 4);
        uint2 hi, lo;
        split4(v, hi, lo);
        int off = row * 128 + (((q >> 1) ^ (row & 7)) << 4) + (q & 1) * 8;
        *(uint2*)(sbuf + off)         = hi;
        *(uint2*)(sbuf + 16384 + off) = lo;
    }
    __syncthreads();

    // ---- Q A-frags (loop-invariant) ----
    uint32_t qh[4][4], ql[4][4];
    {
        const uint32_t sQh = smem_u32(sbuf);
        const uint32_t sQl = sQh + 16384;
        int row = w * 16 + (ml & 1) * 8 + lr;
#pragma unroll
        for (int ks = 0; ks < 4; ks++) {
            int u = ks * 2 + (ml >> 1);
            uint32_t off = row * 128 + (((uint32_t)(u ^ (row & 7))) << 4);
            LDSM_X4(qh[ks][0], qh[ks][1], qh[ks][2], qh[ks][3], sQh + off);
            LDSM_X4(ql[ks][0], ql[ks][1], ql[ks][2], ql[ks][3], sQl + off);
        }
    }
    __syncthreads();    // Q staging consumed; smem now free for K/V

    const uint32_t sKh = smem_u32(sbuf);
    const uint32_t sKl = sKh + 8192;
    const uint32_t sVh = sKh + 16384;
    const uint32_t sVl = sKh + 24576;

    float oacc[8][4];
#pragma unroll
    for (int ns = 0; ns < 8; ns++)
#pragma unroll
        for (int r = 0; r < 4; r++) oacc[ns][r] = 0.0f;
    float m0 = -INFINITY, m1 = -INFINITY, l0 = 0.0f, l1 = 0.0f;

    const int jmax = 2 * qb + 1;
    const int r0g  = q0 + w * 16 + (lane >> 2);   // global row of acc c0/c1
    const int cloc = (lane & 3) * 2;              // local col base within n-tile

    for (int jb = 0; jb <= jmax; jb++) {
        const int k0 = jb * 64;

        // gmem loads (issue before sync to overlap with prior compute tail)
        float4 kr[4], vr[4];
#pragma unroll
        for (int j = 0; j < 4; j++) {
            int f = tid + j * 256;                // 1024 float4 = 64 rows x 16
            int row = f >> 4, q = f & 15;
            kr[j] = *(const float4*)(Kg + base + (size_t)(k0 + row) * HID + q * 4);
            vr[j] = *(const float4*)(Vg + base + (size_t)(k0 + row) * HID + q * 4);
        }
        float4 mreg;
        if (tid < 16)
            mreg = *(const float4*)(maskg + (size_t)b * S_LEN + k0 + tid * 4);

        __syncthreads();   // previous iter's smem reads complete

#pragma unroll
        for (int j = 0; j < 4; j++) {
            int f = tid + j * 256;
            int row = f >> 4, q = f & 15;
            int off = row * 128 + (((q >> 1) ^ (row & 7)) << 4) + (q & 1) * 8;
            uint2 hi, lo;
            split4(kr[j], hi, lo);
            *(uint2*)(sbuf + off)         = hi;
            *(uint2*)(sbuf + 8192 + off)  = lo;
            split4(vr[j], hi, lo);
            *(uint2*)(sbuf + 16384 + off) = hi;
            *(uint2*)(sbuf + 24576 + off) = lo;
        }
        if (tid < 16) *(float4*)&smask[tid * 4] = mreg;
        __syncthreads();

        // ---- S = Q K^T (3-term split) ----
        float sacc[8][4];
#pragma unroll
        for (int nt = 0; nt < 8; nt++)
#pragma unroll
            for (int r = 0; r < 4; r++) sacc[nt][r] = 0.0f;

#pragma unroll
        for (int ks = 0; ks < 4; ks++) {
            uint32_t kh[4][4], kl[4][4];
            int rowb = (ml >> 1) * 8 + lr;
            int u    = ks * 2 + (ml & 1);
#pragma unroll
            for (int g = 0; g < 4; g++) {
                int row = g * 16 + rowb;
                uint32_t off = row * 128 + (((uint32_t)(u ^ (row & 7))) << 4);
                LDSM_X4(kh[g][0], kh[g][1], kh[g][2], kh[g][3], sKh + off);
                LDSM_X4(kl[g][0], kl[g][1], kl[g][2], kl[g][3], sKl + off);
            }
#pragma unroll
            for (int g = 0; g < 4; g++)
#pragma unroll
                for (int j2 = 0; j2 < 2; j2++)
                    MMA16816(sacc[2 * g + j2], qh[ks][0], qh[ks][1], qh[ks][2], qh[ks][3],
                             kh[g][2 * j2], kh[g][2 * j2 + 1]);
#pragma unroll
            for (int g = 0; g < 4; g++)
#pragma unroll
                for (int j2 = 0; j2 < 2; j2++)
                    MMA16816(sacc[2 * g + j2], qh[ks][0], qh[ks][1], qh[ks][2], qh[ks][3],
                             kl[g][2 * j2], kl[g][2 * j2 + 1]);
#pragma unroll
            for (int g = 0; g < 4; g++)
#pragma unroll
                for (int j2 = 0; j2 < 2; j2++)
                    MMA16816(sacc[2 * g + j2], ql[ks][0], ql[ks][1], ql[ks][2], ql[ks][3],
                             kh[g][2 * j2], kh[g][2 * j2 + 1]);
        }

        // ---- scale + mask + online softmax ----
        float rm0 = -INFINITY, rm1 = -INFINITY;
#pragma unroll
        for (int nt = 0; nt < 8; nt++) {
            int c0 = nt * 8 + cloc;
            float mk0 = smask[c0], mk1 = smask[c0 + 1];
            int jg0 = k0 + c0, jg1 = jg0 + 1;
            sacc[nt][0] = (jg0 > r0g     || mk0 == 0.0f) ? FILLV : sacc[nt][0] * 0.125f;
            sacc[nt][1] = (jg1 > r0g     || mk1 == 0.0f) ? FILLV : sacc[nt][1] * 0.125f;
            sacc[nt][2] = (jg0 > r0g + 8 || mk0 == 0.0f) ? FILLV : sacc[nt][2] * 0.125f;
            sacc[nt][3] = (jg1 > r0g + 8 || mk1 == 0.0f) ? FILLV : sacc[nt][3] * 0.125f;
            rm0 = fmaxf(rm0, fmaxf(sacc[nt][0], sacc[nt][1]));
            rm1 = fmaxf(rm1, fmaxf(sacc[nt][2], sacc[nt][3]));
        }
        rm0 = fmaxf(rm0, __shfl_xor_sync(0xffffffffu, rm0, 1));
        rm0 = fmaxf(rm0, __shfl_xor_sync(0xffffffffu, rm0, 2));
        rm1 = fmaxf(rm1, __shfl_xor_sync(0xffffffffu, rm1, 1));
        rm1 = fmaxf(rm1, __shfl_xor_sync(0xffffffffu, rm1, 2));

        float mn0 = fmaxf(m0, rm0), mn1 = fmaxf(m1, rm1);
        float corr0 = __expf(m0 - mn0), corr1 = __expf(m1 - mn1);
        m0 = mn0; m1 = mn1;

        float rs0 = 0.0f, rs1 = 0.0f;
#pragma unroll
        for (int nt = 0; nt < 8; nt++) {
            sacc[nt][0] = __expf(sacc[nt][0] - mn0);
            sacc[nt][1] = __expf(sacc[nt][1] - mn0);
            sacc[nt][2] = __expf(sacc[nt][2] - mn1);
            sacc[nt][3] = __expf(sacc[nt][3] - mn1);
            rs0 += sacc[nt][0] + sacc[nt][1];
            rs1 += sacc[nt][2] + sacc[nt][3];
        }
        rs0 += __shfl_xor_sync(0xffffffffu, rs0, 1);
        rs0 += __shfl_xor_sync(0xffffffffu, rs0, 2);
        rs1 += __shfl_xor_sync(0xffffffffu, rs1, 1);
        rs1 += __shfl_xor_sync(0xffffffffu, rs1, 2);
        l0 = l0 * corr0 + rs0;
        l1 = l1 * corr1 + rs1;
#pragma unroll
        for (int ns = 0; ns < 8; ns++) {
            oacc[ns][0] *= corr0; oacc[ns][1] *= corr0;
            oacc[ns][2] *= corr1; oacc[ns][3] *= corr1;
        }

        // ---- O += P V (3-term split, V via ldmatrix.trans) ----
#pragma unroll
        for (int ks = 0; ks < 4; ks++) {
            uint32_t ph[4], pl[4];
            split2(sacc[2 * ks][0],     sacc[2 * ks][1],     ph[0], pl[0]);
            split2(sacc[2 * ks][2],     sacc[2 * ks][3],     ph[1], pl[1]);
            split2(sacc[2 * ks + 1][0], sacc[2 * ks + 1][1], ph[2], pl[2]);
            split2(sacc[2 * ks + 1][2], sacc[2 * ks + 1][3], ph[3], pl[3]);

            int rowv = ks * 16 + (ml & 1) * 8 + lr;
#pragma unroll
            for (int np = 0; np < 4; np++) {
                int u = np * 2 + (ml >> 1);
                uint32_t off = rowv * 128 + (((uint32_t)(u ^ (rowv & 7))) << 4);
                uint32_t vh[4], vl[4];
                LDSM_X4_T(vh[0], vh[1], vh[2], vh[3], sVh + off);
                LDSM_X4_T(vl[0], vl[1], vl[2], vl[3], sVl + off);
                MMA16816(oacc[2 * np],     ph[0], ph[1], ph[2], ph[3], vh[0], vh[1]);
                MMA16816(oacc[2 * np + 1], ph[0], ph[1], ph[2], ph[3], vh[2], vh[3]);
                MMA16816(oacc[2 * np],     ph[0], ph[1], ph[2], ph[3], vl[0], vl[1]);
                MMA16816(oacc[2 * np + 1], ph[0], ph[1], ph[2], ph[3], vl[2], vl[3]);
                MMA16816(oacc[2 * np],     pl[0], pl[1], pl[2], pl[3], vh[0], vh[1]);
                MMA16816(oacc[2 * np + 1], pl[0], pl[1], pl[2], pl[3], vh[2], vh[3]);
            }
        }
    }

    // ---- epilogue ----
    float inv0 = 1.0f / l0, inv1 = 1.0f / l1;
#pragma unroll
    for (int ns = 0; ns < 8; ns++) {
        int col = ns * 8 + cloc;
        float2 v0 = make_float2(oacc[ns][0] * inv0, oacc[ns][1] * inv0);
        float2 v1 = make_float2(oacc[ns][2] * inv1, oacc[ns][3] * inv1);
        *(float2*)(Og + base + (size_t)r0g * HID + col)       = v0;
        *(float2*)(Og + base + (size_t)(r0g + 8) * HID + col) = v1;
    }
}

// ---------------------------------------------------------------------------
extern "C" void kernel_launch(void* const* d_in, const int* in_sizes, int n_in,
                              void* d_out, int out_size)
{
    const float* q    = (const float*)d_in[0];
    const float* k    = (const float*)d_in[1];
    const float* v    = (const float*)d_in[2];
    const float* mask = (const float*)d_in[3];
    const float* Wq   = (const float*)d_in[4];
    const float* bq   = (const float*)d_in[5];
    const float* Wk   = (const float*)d_in[6];
    const float* bk   = (const float*)d_in[7];
    const float* Wv   = (const float*)d_in[8];
    const float* bv   = (const float*)d_in[9];
    const float* Wo   = (const float*)d_in[10];
    const float* bo   = (const float*)d_in[11];
    float* out = (float*)d_out;

    float *pQ, *pK, *pV, *pA;
    cudaGetSymbolAddress((void**)&pQ, g_Q);
    cudaGetSymbolAddress((void**)&pK, g_K);
    cudaGetSymbolAddress((void**)&pV, g_V);
    cudaGetSymbolAddress((void**)&pA, g_A);

    dim3 ggrid(HID / 128, M_TOT / 128);   // (8, 64)
    gemm_mma<<<ggrid, 256>>>(q, Wq, bq, pQ);
    gemm_mma<<<ggrid, 256>>>(k, Wk, bk, pK);
    gemm_mma<<<ggrid, 256>>>(v, Wv, bv, pV);

    flash_mma<<<dim3(S_LEN / 128, NH, BATCH), 256>>>(pQ, pK, pV, mask, pA);

    gemm_mma<<<ggrid, 256>>>(pA, Wo, bo, out);
}

// round 5
// speedup vs baseline: 2.3953x; 1.0837x over previous
#include <cuda_runtime.h>
#include <cuda_bf16.h>
#include <cstdint>
#include <math.h>

#define S_LEN 2048
#define BATCH 4
#define HID   1024
#define NH    16
#define DH    64
#define M_TOT (BATCH * S_LEN)      // 8192
#define FILLV (-10000000000000.0f)

// Scratch (device globals: no allocations allowed)
__device__ __nv_bfloat16 g_Qh[M_TOT * HID];
__device__ __nv_bfloat16 g_Ql[M_TOT * HID];
__device__ __nv_bfloat16 g_Kh[M_TOT * HID];
__device__ __nv_bfloat16 g_Kl[M_TOT * HID];
__device__ __nv_bfloat16 g_Vh[M_TOT * HID];
__device__ __nv_bfloat16 g_Vl[M_TOT * HID];
__device__ float         g_A [M_TOT * HID];

// ===========================================================================
// helpers
// ===========================================================================
__device__ __forceinline__ uint32_t smem_u32(const void* p) {
    uint32_t a;
    asm("{ .reg .u64 t; cvta.to.shared.u64 t, %1; cvt.u32.u64 %0, t; }"
        : "=r"(a) : "l"(p));
    return a;
}

#define LDSM_X4(r0, r1, r2, r3, addr)                                         \
    asm volatile("ldmatrix.sync.aligned.m8n8.x4.shared.b16 {%0,%1,%2,%3}, [%4];" \
                 : "=r"(r0), "=r"(r1), "=r"(r2), "=r"(r3) : "r"(addr))

#define LDSM_X4_T(r0, r1, r2, r3, addr)                                       \
    asm volatile("ldmatrix.sync.aligned.m8n8.x4.trans.shared.b16 {%0,%1,%2,%3}, [%4];" \
                 : "=r"(r0), "=r"(r1), "=r"(r2), "=r"(r3) : "r"(addr))

#define MMA16816(d, a0, a1, a2, a3, b0, b1)                                   \
    asm volatile("mma.sync.aligned.m16n8k16.row.col.f32.bf16.bf16.f32 "       \
                 "{%0,%1,%2,%3}, {%4,%5,%6,%7}, {%8,%9}, {%0,%1,%2,%3};"      \
                 : "+f"((d)[0]), "+f"((d)[1]), "+f"((d)[2]), "+f"((d)[3])     \
                 : "r"(a0), "r"(a1), "r"(a2), "r"(a3), "r"(b0), "r"(b1))

#define CP_ASYNC16(dst, src)                                                  \
    asm volatile("cp.async.cg.shared.global [%0], [%1], 16;"                  \
                 :: "r"(dst), "l"(src) : "memory")
#define CP_COMMIT() asm volatile("cp.async.commit_group;" ::: "memory")
#define CP_WAIT(n)  asm volatile("cp.async.wait_group %0;" :: "n"(n) : "memory")

__device__ __forceinline__ uint32_t pack_bf2(float x, float y) {
    __nv_bfloat16 bx = __float2bfloat16_rn(x);
    __nv_bfloat16 by = __float2bfloat16_rn(y);
    return (uint32_t)__bfloat16_as_ushort(bx)
         | ((uint32_t)__bfloat16_as_ushort(by) << 16);
}

__device__ __forceinline__ void split4(const float4& v, uint2& hi, uint2& lo) {
    __nv_bfloat16 h0 = __float2bfloat16_rn(v.x);
    __nv_bfloat16 h1 = __float2bfloat16_rn(v.y);
    __nv_bfloat16 h2 = __float2bfloat16_rn(v.z);
    __nv_bfloat16 h3 = __float2bfloat16_rn(v.w);
    float l0 = v.x - __bfloat162float(h0);
    float l1 = v.y - __bfloat162float(h1);
    float l2 = v.z - __bfloat162float(h2);
    float l3 = v.w - __bfloat162float(h3);
    hi.x = (uint32_t)__bfloat16_as_ushort(h0)
         | ((uint32_t)__bfloat16_as_ushort(h1) << 16);
    hi.y = (uint32_t)__bfloat16_as_ushort(h2)
         | ((uint32_t)__bfloat16_as_ushort(h3) << 16);
    lo.x = pack_bf2(l0, l1);
    lo.y = pack_bf2(l2, l3);
}

__device__ __forceinline__ void split2(float x, float y, uint32_t& hi, uint32_t& lo) {
    __nv_bfloat16 hx = __float2bfloat16_rn(x);
    __nv_bfloat16 hy = __float2bfloat16_rn(y);
    hi = (uint32_t)__bfloat16_as_ushort(hx)
       | ((uint32_t)__bfloat16_as_ushort(hy) << 16);
    lo = pack_bf2(x - __bfloat162float(hx), y - __bfloat162float(hy));
}

// ===========================================================================
// GEMM: C[M=8192, N=1024] = A * W^T + bias via mma.sync bf16 2-term split.
// Mainloop verified (rounds 3/4). Epilogue templated: fp32 C or bf16 hi/lo.
// ===========================================================================
#define GK 1024
#define NC 64
#define STAGE_B 16384

template<bool BF16OUT>
__global__ void __launch_bounds__(256)
gemm_mma(const float* __restrict__ A, const float* __restrict__ W,
         const float* __restrict__ bias, float* __restrict__ C,
         __nv_bfloat16* __restrict__ Ch, __nv_bfloat16* __restrict__ Cl)
{
    __shared__ __align__(128) uint8_t sm[2 * STAGE_B];
    const uint32_t sb = smem_u32(sm);
    const int tid  = threadIdx.x;
    const int lane = tid & 31;
    const int warp = tid >> 5;
    const int wm   = warp >> 2;
    const int wn   = warp & 3;
    const int bm   = blockIdx.y * 128;
    const int bn   = blockIdx.x * 128;

    const int lr = lane & 7;
    const int ml = lane >> 3;
    uint32_t offA[4], offW[2];
#pragma unroll
    for (int mt = 0; mt < 4; mt++) {
        int row = wm * 64 + mt * 16 + (ml & 1) * 8 + lr;
        int g   = ml >> 1;
        offA[mt] = row * 32 + ((uint32_t)(g ^ ((row >> 2) & 1)) << 4);
    }
#pragma unroll
    for (int p = 0; p < 2; p++) {
        int row = wn * 32 + p * 16 + (ml >> 1) * 8 + lr;
        int g   = ml & 1;
        offW[p] = row * 32 + ((uint32_t)(g ^ ((row >> 2) & 1)) << 4);
    }

    int srow[2], sq[2], ssw[2];
#pragma unroll
    for (int j = 0; j < 2; j++) {
        int f = tid + j * 256;
        srow[j] = f >> 2;
        sq[j]   = f & 3;
        int g   = sq[j] >> 1;
        ssw[j]  = srow[j] * 32 + ((g ^ ((srow[j] >> 2) & 1)) << 4)
                + (sq[j] & 1) * 8;
    }

    const float* Ab = A + (size_t)bm * GK;
    const float* Wb = W + (size_t)bn * GK;

    float acc[4][4][4];
#pragma unroll
    for (int mt = 0; mt < 4; mt++)
#pragma unroll
        for (int nt = 0; nt < 4; nt++)
#pragma unroll
            for (int r = 0; r < 4; r++) acc[mt][nt][r] = 0.0f;

    float4 av[2], wv[2];
#pragma unroll
    for (int j = 0; j < 2; j++) {
        av[j] = *(const float4*)(Ab + (size_t)srow[j] * GK + sq[j] * 4);
        wv[j] = *(const float4*)(Wb + (size_t)srow[j] * GK + sq[j] * 4);
    }
#pragma unroll
    for (int j = 0; j < 2; j++) {
        uint2 hi, lo;
        split4(av[j], hi, lo);
        *(uint2*)(sm + ssw[j])        = hi;
        *(uint2*)(sm + 4096 + ssw[j]) = lo;
        split4(wv[j], hi, lo);
        *(uint2*)(sm + 8192 + ssw[j])  = hi;
        *(uint2*)(sm + 12288 + ssw[j]) = lo;
    }
    __syncthreads();

    for (int c = 0; c < NC; c++) {
        if (c < NC - 1) {
            int k0 = (c + 1) * 16;
#pragma unroll
            for (int j = 0; j < 2; j++) {
                av[j] = *(const float4*)(Ab + (size_t)srow[j] * GK + k0 + sq[j] * 4);
                wv[j] = *(const float4*)(Wb + (size_t)srow[j] * GK + k0 + sq[j] * 4);
            }
        }
        {
            const uint32_t sA = sb + (uint32_t)(c & 1) * STAGE_B;
            uint32_t ah[4][4], al[4][4], wh[2][4], wl[2][4];
#pragma unroll
            for (int mt = 0; mt < 4; mt++) {
                LDSM_X4(ah[mt][0], ah[mt][1], ah[mt][2], ah[mt][3], sA + offA[mt]);
                LDSM_X4(al[mt][0], al[mt][1], al[mt][2], al[mt][3], sA + 4096 + offA[mt]);
            }
#pragma unroll
            for (int p = 0; p < 2; p++) {
                LDSM_X4(wh[p][0], wh[p][1], wh[p][2], wh[p][3], sA + 8192 + offW[p]);
                LDSM_X4(wl[p][0], wl[p][1], wl[p][2], wl[p][3], sA + 12288 + offW[p]);
            }
#pragma unroll
            for (int mt = 0; mt < 4; mt++)
#pragma unroll
                for (int p = 0; p < 2; p++)
#pragma unroll
                    for (int j2 = 0; j2 < 2; j2++) {
                        int nt = 2 * p + j2;
                        MMA16816(acc[mt][nt], ah[mt][0], ah[mt][1], ah[mt][2], ah[mt][3],
                                 wh[p][2 * j2], wh[p][2 * j2 + 1]);
                        MMA16816(acc[mt][nt], ah[mt][0], ah[mt][1], ah[mt][2], ah[mt][3],
                                 wl[p][2 * j2], wl[p][2 * j2 + 1]);
                        MMA16816(acc[mt][nt], al[mt][0], al[mt][1], al[mt][2], al[mt][3],
                                 wh[p][2 * j2], wh[p][2 * j2 + 1]);
                    }
        }
        if (c < NC - 1) {
            uint8_t* st = sm + ((c + 1) & 1) * STAGE_B;
#pragma unroll
            for (int j = 0; j < 2; j++) {
                uint2 hi, lo;
                split4(av[j], hi, lo);
                *(uint2*)(st + ssw[j])        = hi;
                *(uint2*)(st + 4096 + ssw[j]) = lo;
                split4(wv[j], hi, lo);
                *(uint2*)(st + 8192 + ssw[j])  = hi;
                *(uint2*)(st + 12288 + ssw[j]) = lo;
            }
        }
        __syncthreads();
    }

#pragma unroll
    for (int mt = 0; mt < 4; mt++) {
        int r0 = bm + wm * 64 + mt * 16 + (lane >> 2);
#pragma unroll
        for (int nt = 0; nt < 4; nt++) {
            int cg = bn + wn * 32 + nt * 8 + (lane & 3) * 2;
            float2 bz = *(const float2*)(bias + cg);
            float2 v0 = make_float2(acc[mt][nt][0] + bz.x, acc[mt][nt][1] + bz.y);
            float2 v1 = make_float2(acc[mt][nt][2] + bz.x, acc[mt][nt][3] + bz.y);
            if (BF16OUT) {
                uint32_t hi, lo;
                split2(v0.x, v0.y, hi, lo);
                *(uint32_t*)(Ch + (size_t)r0 * HID + cg) = hi;
                *(uint32_t*)(Cl + (size_t)r0 * HID + cg) = lo;
                split2(v1.x, v1.y, hi, lo);
                *(uint32_t*)(Ch + (size_t)(r0 + 8) * HID + cg) = hi;
                *(uint32_t*)(Cl + (size_t)(r0 + 8) * HID + cg) = lo;
            } else {
                *(float2*)(C + (size_t)r0 * HID + cg)       = v0;
                *(float2*)(C + (size_t)(r0 + 8) * HID + cg) = v1;
            }
        }
    }
}

// ===========================================================================
// Tensor-core causal flash attention, bf16-split inputs, cp.async pipeline.
// BQ=128, BKV=64, 8 warps, grid (16,16,4).
// Dynamic smem: stage s (s=0,1) at s*32768: Kh+0 Kl+8192 Vh+16384 Vl+24576.
// mask at 65536 + s*256. Q staged once in [0,32768) before the loop.
// Row layout: 64 bf16 = 128B rows, swizzle phys = row*128 + ((u^(row&7))<<4).
// ===========================================================================
#define FLASH_SMEM (65536 + 512)

__global__ void __launch_bounds__(256)
flash_cp(const __nv_bfloat16* __restrict__ Qhp, const __nv_bfloat16* __restrict__ Qlp,
         const __nv_bfloat16* __restrict__ Khp, const __nv_bfloat16* __restrict__ Klp,
         const __nv_bfloat16* __restrict__ Vhp, const __nv_bfloat16* __restrict__ Vlp,
         const float* __restrict__ maskg, float* __restrict__ Og)
{
    extern __shared__ __align__(128) uint8_t sbuf[];
    const uint32_t sb = smem_u32(sbuf);

    const int tid  = threadIdx.x;
    const int lane = tid & 31;
    const int w    = tid >> 5;
    const int lr   = lane & 7;
    const int ml   = lane >> 3;
    const int qb   = blockIdx.x;
    const int h    = blockIdx.y;
    const int b    = blockIdx.z;
    const int q0   = qb * 128;
    const size_t base = ((size_t)b * S_LEN) * HID + (size_t)h * DH;

    // ---- stage Q via cp.async (hi at 0, lo at 16384) ----
#pragma unroll
    for (int j = 0; j < 8; j++) {
        int f = tid + j * 256;
        int term = j >> 2;                 // 0 = hi, 1 = lo
        int c = f & 1023;
        int row = c >> 3, qq = c & 7;
        uint32_t dst = sb + (uint32_t)term * 16384 + row * 128
                     + (((uint32_t)(qq ^ (row & 7))) << 4);
        const __nv_bfloat16* src = (term ? Qlp : Qhp) + base
                                 + (size_t)(q0 + row) * HID + qq * 8;
        CP_ASYNC16(dst, src);
    }
    CP_COMMIT();
    CP_WAIT(0);
    __syncthreads();

    // ---- Q A-frags (loop-invariant) ----
    uint32_t qh[4][4], ql[4][4];
    {
        int row = w * 16 + (ml & 1) * 8 + lr;
#pragma unroll
        for (int ks = 0; ks < 4; ks++) {
            int u = ks * 2 + (ml >> 1);
            uint32_t off = row * 128 + (((uint32_t)(u ^ (row & 7))) << 4);
            LDSM_X4(qh[ks][0], qh[ks][1], qh[ks][2], qh[ks][3], sb + off);
            LDSM_X4(ql[ks][0], ql[ks][1], ql[ks][2], ql[ks][3], sb + 16384 + off);
        }
    }
    __syncthreads();

    const int jmax = 2 * qb + 1;

    auto issue_tile = [&](int t) {
        const int k0t = t * 64;
        const __nv_bfloat16* bases[4] = {
            Khp + base + (size_t)k0t * HID,
            Klp + base + (size_t)k0t * HID,
            Vhp + base + (size_t)k0t * HID,
            Vlp + base + (size_t)k0t * HID };
        const uint32_t stg = sb + (uint32_t)(t & 1) * 32768;
#pragma unroll
        for (int j = 0; j < 8; j++) {
            int f = tid + j * 256;
            int row = (f >> 3) & 63, qq = f & 7;
            uint32_t dst = stg + (uint32_t)(j >> 1) * 8192 + row * 128
                         + (((uint32_t)(qq ^ (row & 7))) << 4);
            CP_ASYNC16(dst, bases[j >> 1] + (size_t)row * HID + qq * 8);
        }
        if (tid < 16)
            CP_ASYNC16(sb + 65536 + (uint32_t)(t & 1) * 256 + tid * 16,
                       maskg + (size_t)b * S_LEN + k0t + tid * 4);
        CP_COMMIT();
    };

    issue_tile(0);
    issue_tile(1);          // jmax >= 1 always

    float oacc[8][4];
#pragma unroll
    for (int ns = 0; ns < 8; ns++)
#pragma unroll
        for (int r = 0; r < 4; r++) oacc[ns][r] = 0.0f;
    float m0 = -INFINITY, m1 = -INFINITY, l0 = 0.0f, l1 = 0.0f;

    const int r0g  = q0 + w * 16 + (lane >> 2);
    const int cloc = (lane & 3) * 2;

    for (int jb = 0; jb <= jmax; jb++) {
        const int k0 = jb * 64;
        CP_WAIT(1);
        __syncthreads();

        const uint32_t stg = sb + (uint32_t)(jb & 1) * 32768;
        const uint32_t sKh = stg, sKl = stg + 8192;
        const uint32_t sVh = stg + 16384, sVl = stg + 24576;
        const float* smask = (const float*)(sbuf + 65536 + (jb & 1) * 256);

        // ---- S = Q K^T (3-term split) ----
        float sacc[8][4];
#pragma unroll
        for (int nt = 0; nt < 8; nt++)
#pragma unroll
            for (int r = 0; r < 4; r++) sacc[nt][r] = 0.0f;

#pragma unroll
        for (int ks = 0; ks < 4; ks++) {
            uint32_t kh[4][4], kl[4][4];
            int rowb = (ml >> 1) * 8 + lr;
            int u    = ks * 2 + (ml & 1);
#pragma unroll
            for (int g = 0; g < 4; g++) {
                int row = g * 16 + rowb;
                uint32_t off = row * 128 + (((uint32_t)(u ^ (row & 7))) << 4);
                LDSM_X4(kh[g][0], kh[g][1], kh[g][2], kh[g][3], sKh + off);
                LDSM_X4(kl[g][0], kl[g][1], kl[g][2], kl[g][3], sKl + off);
            }
#pragma unroll
            for (int g = 0; g < 4; g++)
#pragma unroll
                for (int j2 = 0; j2 < 2; j2++)
                    MMA16816(sacc[2 * g + j2], qh[ks][0], qh[ks][1], qh[ks][2], qh[ks][3],
                             kh[g][2 * j2], kh[g][2 * j2 + 1]);
#pragma unroll
            for (int g = 0; g < 4; g++)
#pragma unroll
                for (int j2 = 0; j2 < 2; j2++)
                    MMA16816(sacc[2 * g + j2], qh[ks][0], qh[ks][1], qh[ks][2], qh[ks][3],
                             kl[g][2 * j2], kl[g][2 * j2 + 1]);
#pragma unroll
            for (int g = 0; g < 4; g++)
#pragma unroll
                for (int j2 = 0; j2 < 2; j2++)
                    MMA16816(sacc[2 * g + j2], ql[ks][0], ql[ks][1], ql[ks][2], ql[ks][3],
                             kh[g][2 * j2], kh[g][2 * j2 + 1]);
        }

        // ---- scale + mask + online softmax ----
        float rm0 = -INFINITY, rm1 = -INFINITY;
#pragma unroll
        for (int nt = 0; nt < 8; nt++) {
            int c0 = nt * 8 + cloc;
            float mk0 = smask[c0], mk1 = smask[c0 + 1];
            int jg0 = k0 + c0, jg1 = jg0 + 1;
            sacc[nt][0] = (jg0 > r0g     || mk0 == 0.0f) ? FILLV : sacc[nt][0] * 0.125f;
            sacc[nt][1] = (jg1 > r0g     || mk1 == 0.0f) ? FILLV : sacc[nt][1] * 0.125f;
            sacc[nt][2] = (jg0 > r0g + 8 || mk0 == 0.0f) ? FILLV : sacc[nt][2] * 0.125f;
            sacc[nt][3] = (jg1 > r0g + 8 || mk1 == 0.0f) ? FILLV : sacc[nt][3] * 0.125f;
            rm0 = fmaxf(rm0, fmaxf(sacc[nt][0], sacc[nt][1]));
            rm1 = fmaxf(rm1, fmaxf(sacc[nt][2], sacc[nt][3]));
        }
        rm0 = fmaxf(rm0, __shfl_xor_sync(0xffffffffu, rm0, 1));
        rm0 = fmaxf(rm0, __shfl_xor_sync(0xffffffffu, rm0, 2));
        rm1 = fmaxf(rm1, __shfl_xor_sync(0xffffffffu, rm1, 1));
        rm1 = fmaxf(rm1, __shfl_xor_sync(0xffffffffu, rm1, 2));

        float mn0 = fmaxf(m0, rm0), mn1 = fmaxf(m1, rm1);
        float corr0 = __expf(m0 - mn0), corr1 = __expf(m1 - mn1);
        m0 = mn0; m1 = mn1;

        float rs0 = 0.0f, rs1 = 0.0f;
#pragma unroll
        for (int nt = 0; nt < 8; nt++) {
            sacc[nt][0] = __expf(sacc[nt][0] - mn0);
            sacc[nt][1] = __expf(sacc[nt][1] - mn0);
            sacc[nt][2] = __expf(sacc[nt][2] - mn1);
            sacc[nt][3] = __expf(sacc[nt][3] - mn1);
            rs0 += sacc[nt][0] + sacc[nt][1];
            rs1 += sacc[nt][2] + sacc[nt][3];
        }
        rs0 += __shfl_xor_sync(0xffffffffu, rs0, 1);
        rs0 += __shfl_xor_sync(0xffffffffu, rs0, 2);
        rs1 += __shfl_xor_sync(0xffffffffu, rs1, 1);
        rs1 += __shfl_xor_sync(0xffffffffu, rs1, 2);
        l0 = l0 * corr0 + rs0;
        l1 = l1 * corr1 + rs1;
#pragma unroll
        for (int ns = 0; ns < 8; ns++) {
            oacc[ns][0] *= corr0; oacc[ns][1] *= corr0;
            oacc[ns][2] *= corr1; oacc[ns][3] *= corr1;
        }

        // ---- O += P V (3-term split, V via ldmatrix.trans) ----
#pragma unroll
        for (int ks = 0; ks < 4; ks++) {
            uint32_t ph[4], pl[4];
            split2(sacc[2 * ks][0],     sacc[2 * ks][1],     ph[0], pl[0]);
            split2(sacc[2 * ks][2],     sacc[2 * ks][3],     ph[1], pl[1]);
            split2(sacc[2 * ks + 1][0], sacc[2 * ks + 1][1], ph[2], pl[2]);
            split2(sacc[2 * ks + 1][2], sacc[2 * ks + 1][3], ph[3], pl[3]);

            int rowv = ks * 16 + (ml & 1) * 8 + lr;
#pragma unroll
            for (int np = 0; np < 4; np++) {
                int u = np * 2 + (ml >> 1);
                uint32_t off = rowv * 128 + (((uint32_t)(u ^ (rowv & 7))) << 4);
                uint32_t vh[4], vl[4];
                LDSM_X4_T(vh[0], vh[1], vh[2], vh[3], sVh + off);
                LDSM_X4_T(vl[0], vl[1], vl[2], vl[3], sVl + off);
                MMA16816(oacc[2 * np],     ph[0], ph[1], ph[2], ph[3], vh[0], vh[1]);
                MMA16816(oacc[2 * np + 1], ph[0], ph[1], ph[2], ph[3], vh[2], vh[3]);
                MMA16816(oacc[2 * np],     ph[0], ph[1], ph[2], ph[3], vl[0], vl[1]);
                MMA16816(oacc[2 * np + 1], ph[0], ph[1], ph[2], ph[3], vl[2], vl[3]);
                MMA16816(oacc[2 * np],     pl[0], pl[1], pl[2], pl[3], vh[0], vh[1]);
                MMA16816(oacc[2 * np + 1], pl[0], pl[1], pl[2], pl[3], vh[2], vh[3]);
            }
        }

        __syncthreads();
        if (jb + 2 <= jmax) issue_tile(jb + 2);
        else                CP_COMMIT();   // keep group count uniform
    }

    // ---- epilogue ----
    float inv0 = 1.0f / l0, inv1 = 1.0f / l1;
#pragma unroll
    for (int ns = 0; ns < 8; ns++) {
        int col = ns * 8 + cloc;
        float2 v0 = make_float2(oacc[ns][0] * inv0, oacc[ns][1] * inv0);
        float2 v1 = make_float2(oacc[ns][2] * inv1, oacc[ns][3] * inv1);
        *(float2*)(Og + base + (size_t)r0g * HID + col)       = v0;
        *(float2*)(Og + base + (size_t)(r0g + 8) * HID + col) = v1;
    }
}

// ---------------------------------------------------------------------------
extern "C" void kernel_launch(void* const* d_in, const int* in_sizes, int n_in,
                              void* d_out, int out_size)
{
    const float* q    = (const float*)d_in[0];
    const float* k    = (const float*)d_in[1];
    const float* v    = (const float*)d_in[2];
    const float* mask = (const float*)d_in[3];
    const float* Wq   = (const float*)d_in[4];
    const float* bq   = (const float*)d_in[5];
    const float* Wk   = (const float*)d_in[6];
    const float* bk   = (const float*)d_in[7];
    const float* Wv   = (const float*)d_in[8];
    const float* bv   = (const float*)d_in[9];
    const float* Wo   = (const float*)d_in[10];
    const float* bo   = (const float*)d_in[11];
    float* out = (float*)d_out;

    __nv_bfloat16 *pQh, *pQl, *pKh, *pKl, *pVh, *pVl;
    float *pA;
    cudaGetSymbolAddress((void**)&pQh, g_Qh);
    cudaGetSymbolAddress((void**)&pQl, g_Ql);
    cudaGetSymbolAddress((void**)&pKh, g_Kh);
    cudaGetSymbolAddress((void**)&pKl, g_Kl);
    cudaGetSymbolAddress((void**)&pVh, g_Vh);
    cudaGetSymbolAddress((void**)&pVl, g_Vl);
    cudaGetSymbolAddress((void**)&pA,  g_A);

    cudaFuncSetAttribute(flash_cp, cudaFuncAttributeMaxDynamicSharedMemorySize,
                         FLASH_SMEM);

    dim3 ggrid(HID / 128, M_TOT / 128);   // (8, 64)
    gemm_mma<true ><<<ggrid, 256>>>(q, Wq, bq, nullptr, pQh, pQl);
    gemm_mma<true ><<<ggrid, 256>>>(k, Wk, bk, nullptr, pKh, pKl);
    gemm_mma<true ><<<ggrid, 256>>>(v, Wv, bv, nullptr, pVh, pVl);

    flash_cp<<<dim3(S_LEN / 128, NH, BATCH), 256, FLASH_SMEM>>>(
        pQh, pQl, pKh, pKl, pVh, pVl, mask, pA);

    gemm_mma<false><<<ggrid, 256>>>(pA, Wo, bo, out, nullptr, nullptr);
}

// round 6
// speedup vs baseline: 2.4134x; 1.0076x over previous
#include <cuda_runtime.h>
#include <cuda_bf16.h>
#include <cstdint>
#include <math.h>

#define S_LEN 2048
#define BATCH 4
#define HID   1024
#define NH    16
#define DH    64
#define M_TOT (BATCH * S_LEN)      // 8192
#define FILLV (-10000000000000.0f)

// Scratch (device globals: no allocations allowed)
// pre-split inputs
__device__ __nv_bfloat16 g_xqh[M_TOT * HID], g_xql[M_TOT * HID];
__device__ __nv_bfloat16 g_xkh[M_TOT * HID], g_xkl[M_TOT * HID];
__device__ __nv_bfloat16 g_xvh[M_TOT * HID], g_xvl[M_TOT * HID];
// pre-split weights
__device__ __nv_bfloat16 g_wqh[HID * HID], g_wql[HID * HID];
__device__ __nv_bfloat16 g_wkh[HID * HID], g_wkl[HID * HID];
__device__ __nv_bfloat16 g_wvh[HID * HID], g_wvl[HID * HID];
__device__ __nv_bfloat16 g_woh[HID * HID], g_wol[HID * HID];
// projections
__device__ __nv_bfloat16 g_Qh[M_TOT * HID], g_Ql[M_TOT * HID];
__device__ __nv_bfloat16 g_Kh[M_TOT * HID], g_Kl[M_TOT * HID];
__device__ __nv_bfloat16 g_Vh[M_TOT * HID], g_Vl[M_TOT * HID];
// attention output
__device__ __nv_bfloat16 g_Ah[M_TOT * HID], g_Al[M_TOT * HID];

// ===========================================================================
// helpers
// ===========================================================================
__device__ __forceinline__ uint32_t smem_u32(const void* p) {
    uint32_t a;
    asm("{ .reg .u64 t; cvta.to.shared.u64 t, %1; cvt.u32.u64 %0, t; }"
        : "=r"(a) : "l"(p));
    return a;
}

#define LDSM_X4(r0, r1, r2, r3, addr)                                         \
    asm volatile("ldmatrix.sync.aligned.m8n8.x4.shared.b16 {%0,%1,%2,%3}, [%4];" \
                 : "=r"(r0), "=r"(r1), "=r"(r2), "=r"(r3) : "r"(addr))

#define LDSM_X4_T(r0, r1, r2, r3, addr)                                       \
    asm volatile("ldmatrix.sync.aligned.m8n8.x4.trans.shared.b16 {%0,%1,%2,%3}, [%4];" \
                 : "=r"(r0), "=r"(r1), "=r"(r2), "=r"(r3) : "r"(addr))

#define MMA16816(d, a0, a1, a2, a3, b0, b1)                                   \
    asm volatile("mma.sync.aligned.m16n8k16.row.col.f32.bf16.bf16.f32 "       \
                 "{%0,%1,%2,%3}, {%4,%5,%6,%7}, {%8,%9}, {%0,%1,%2,%3};"      \
                 : "+f"((d)[0]), "+f"((d)[1]), "+f"((d)[2]), "+f"((d)[3])     \
                 : "r"(a0), "r"(a1), "r"(a2), "r"(a3), "r"(b0), "r"(b1))

#define CP_ASYNC16(dst, src)                                                  \
    asm volatile("cp.async.cg.shared.global [%0], [%1], 16;"                  \
                 :: "r"(dst), "l"(src) : "memory")
#define CP_COMMIT() asm volatile("cp.async.commit_group;" ::: "memory")
#define CP_WAIT(n)  asm volatile("cp.async.wait_group %0;" :: "n"(n) : "memory")

__device__ __forceinline__ uint32_t pack_bf2(float x, float y) {
    __nv_bfloat16 bx = __float2bfloat16_rn(x);
    __nv_bfloat16 by = __float2bfloat16_rn(y);
    return (uint32_t)__bfloat16_as_ushort(bx)
         | ((uint32_t)__bfloat16_as_ushort(by) << 16);
}

__device__ __forceinline__ void split4(const float4& v, uint2& hi, uint2& lo) {
    __nv_bfloat16 h0 = __float2bfloat16_rn(v.x);
    __nv_bfloat16 h1 = __float2bfloat16_rn(v.y);
    __nv_bfloat16 h2 = __float2bfloat16_rn(v.z);
    __nv_bfloat16 h3 = __float2bfloat16_rn(v.w);
    float l0 = v.x - __bfloat162float(h0);
    float l1 = v.y - __bfloat162float(h1);
    float l2 = v.z - __bfloat162float(h2);
    float l3 = v.w - __bfloat162float(h3);
    hi.x = (uint32_t)__bfloat16_as_ushort(h0)
         | ((uint32_t)__bfloat16_as_ushort(h1) << 16);
    hi.y = (uint32_t)__bfloat16_as_ushort(h2)
         | ((uint32_t)__bfloat16_as_ushort(h3) << 16);
    lo.x = pack_bf2(l0, l1);
    lo.y = pack_bf2(l2, l3);
}

__device__ __forceinline__ void split2(float x, float y, uint32_t& hi, uint32_t& lo) {
    __nv_bfloat16 hx = __float2bfloat16_rn(x);
    __nv_bfloat16 hy = __float2bfloat16_rn(y);
    hi = (uint32_t)__bfloat16_as_ushort(hx)
       | ((uint32_t)__bfloat16_as_ushort(hy) << 16);
    lo = pack_bf2(x - __bfloat162float(hx), y - __bfloat162float(hy));
}

// ===========================================================================
// split pass: fp32 -> bf16 hi/lo
// ===========================================================================
__global__ void __launch_bounds__(256)
split_f32(const float* __restrict__ x, __nv_bfloat16* __restrict__ xh,
          __nv_bfloat16* __restrict__ xl, int n4)
{
    int i = blockIdx.x * 256 + threadIdx.x;
    if (i < n4) {
        float4 v = ((const float4*)x)[i];
        uint2 hi, lo;
        split4(v, hi, lo);
        ((uint2*)xh)[i] = hi;
        ((uint2*)xl)[i] = lo;
    }
}

// ===========================================================================
// GEMM: C[8192,1024] = A*W^T + bias, pre-split bf16 inputs, 3-term split.
// CTA 128x128, BK=32, 3-stage cp.async pipeline, 8 warps (2x4), warp 64x32.
// Stage (32KB): Ah@0 Al@8192 Wh@16384 Wl@24576. Rows = 32 bf16 = 64B.
// Swizzle: phys = row*64 + ((g ^ ((row>>1)&3))<<4), g = 16B granule 0..3.
// ===========================================================================
#define GK 1024
#define NCH 32                       // 1024 / 32
#define GSTAGE 32768
#define GEMM_SMEM (3 * GSTAGE)

__device__ __forceinline__ uint32_t sw64(int row, int g) {
    return (uint32_t)(row * 64 + (((g ^ ((row >> 1) & 3))) << 4));
}

template<bool BF16OUT>
__global__ void __launch_bounds__(256)
gemm_bf(const __nv_bfloat16* __restrict__ Ahp, const __nv_bfloat16* __restrict__ Alp,
        const __nv_bfloat16* __restrict__ Whp, const __nv_bfloat16* __restrict__ Wlp,
        const float* __restrict__ bias, float* __restrict__ C,
        __nv_bfloat16* __restrict__ Ch, __nv_bfloat16* __restrict__ Cl)
{
    extern __shared__ __align__(128) uint8_t smg[];
    const uint32_t sb = smem_u32(smg);
    const int tid  = threadIdx.x;
    const int lane = tid & 31;
    const int warp = tid >> 5;
    const int wm   = warp >> 2;
    const int wn   = warp & 3;
    const int bm   = blockIdx.y * 128;
    const int bn   = blockIdx.x * 128;
    const int lr   = lane & 7;
    const int ml   = lane >> 3;

    // cp.async slots: granule j -> row r0 + 64j, granule col g0
    const int r0 = tid >> 2, g0 = tid & 3;
    const uint32_t swd0 = sw64(r0, g0);
    const uint32_t swd1 = sw64(r0 + 64, g0);

    const __nv_bfloat16* srcs[4] = {
        Ahp + (size_t)bm * GK, Alp + (size_t)bm * GK,
        Whp + (size_t)bn * GK, Wlp + (size_t)bn * GK };

    // frag row bases + swizzle xor bits
    int rowA[4], xorA[4];
#pragma unroll
    for (int mt = 0; mt < 4; mt++) {
        int row = wm * 64 + mt * 16 + (ml & 1) * 8 + lr;
        rowA[mt] = row * 64;
        xorA[mt] = (row >> 1) & 3;
    }
    int rowW[2], xorW[2];
#pragma unroll
    for (int p = 0; p < 2; p++) {
        int row = wn * 32 + p * 16 + (ml >> 1) * 8 + lr;
        rowW[p] = row * 64;
        xorW[p] = (row >> 1) & 3;
    }
    const int gA = ml >> 1;   // + ks*2
    const int gW = ml & 1;    // + ks*2

    float acc[4][4][4];
#pragma unroll
    for (int mt = 0; mt < 4; mt++)
#pragma unroll
        for (int nt = 0; nt < 4; nt++)
#pragma unroll
            for (int r = 0; r < 4; r++) acc[mt][nt][r] = 0.0f;

    auto issue = [&](int t) {
        int st = t; while (st >= 3) st -= 3;
        const uint32_t stg = sb + (uint32_t)st * GSTAGE;
        const int kc = t * 32;
#pragma unroll
        for (int m = 0; m < 4; m++) {
            const __nv_bfloat16* s = srcs[m] + kc + g0 * 8;
            CP_ASYNC16(stg + m * 8192 + swd0, s + (size_t)r0 * GK);
            CP_ASYNC16(stg + m * 8192 + swd1, s + (size_t)(r0 + 64) * GK);
        }
        CP_COMMIT();
    };

    issue(0);
    issue(1);

    for (int c = 0; c < NCH; c++) {
        CP_WAIT(1);
        __syncthreads();
        if (c + 2 < NCH) issue(c + 2);
        else             CP_COMMIT();

        int st = c; while (st >= 3) st -= 3;
        const uint32_t stg = sb + (uint32_t)st * GSTAGE;

#pragma unroll
        for (int ks = 0; ks < 2; ks++) {
            uint32_t ah[4][4], al[4][4], wh[2][4], wl[2][4];
#pragma unroll
            for (int mt = 0; mt < 4; mt++) {
                uint32_t off = (uint32_t)rowA[mt]
                             + (((uint32_t)((ks * 2 + gA) ^ xorA[mt])) << 4);
                LDSM_X4(ah[mt][0], ah[mt][1], ah[mt][2], ah[mt][3], stg + off);
                LDSM_X4(al[mt][0], al[mt][1], al[mt][2], al[mt][3], stg + 8192 + off);
            }
#pragma unroll
            for (int p = 0; p < 2; p++) {
                uint32_t off = (uint32_t)rowW[p]
                             + (((uint32_t)((ks * 2 + gW) ^ xorW[p])) << 4);
                LDSM_X4(wh[p][0], wh[p][1], wh[p][2], wh[p][3], stg + 16384 + off);
                LDSM_X4(wl[p][0], wl[p][1], wl[p][2], wl[p][3], stg + 24576 + off);
            }
#pragma unroll
            for (int mt = 0; mt < 4; mt++)
#pragma unroll
                for (int p = 0; p < 2; p++)
#pragma unroll
                    for (int j2 = 0; j2 < 2; j2++) {
                        int nt = 2 * p + j2;
                        MMA16816(acc[mt][nt], ah[mt][0], ah[mt][1], ah[mt][2], ah[mt][3],
                                 wh[p][2 * j2], wh[p][2 * j2 + 1]);
                        MMA16816(acc[mt][nt], ah[mt][0], ah[mt][1], ah[mt][2], ah[mt][3],
                                 wl[p][2 * j2], wl[p][2 * j2 + 1]);
                        MMA16816(acc[mt][nt], al[mt][0], al[mt][1], al[mt][2], al[mt][3],
                                 wh[p][2 * j2], wh[p][2 * j2 + 1]);
                    }
        }
    }

#pragma unroll
    for (int mt = 0; mt < 4; mt++) {
        int r0g = bm + wm * 64 + mt * 16 + (lane >> 2);
#pragma unroll
        for (int nt = 0; nt < 4; nt++) {
            int cg = bn + wn * 32 + nt * 8 + (lane & 3) * 2;
            float2 bz = *(const float2*)(bias + cg);
            float2 v0 = make_float2(acc[mt][nt][0] + bz.x, acc[mt][nt][1] + bz.y);
            float2 v1 = make_float2(acc[mt][nt][2] + bz.x, acc[mt][nt][3] + bz.y);
            if (BF16OUT) {
                uint32_t hi, lo;
                split2(v0.x, v0.y, hi, lo);
                *(uint32_t*)(Ch + (size_t)r0g * HID + cg) = hi;
                *(uint32_t*)(Cl + (size_t)r0g * HID + cg) = lo;
                split2(v1.x, v1.y, hi, lo);
                *(uint32_t*)(Ch + (size_t)(r0g + 8) * HID + cg) = hi;
                *(uint32_t*)(Cl + (size_t)(r0g + 8) * HID + cg) = lo;
            } else {
                *(float2*)(C + (size_t)r0g * HID + cg)       = v0;
                *(float2*)(C + (size_t)(r0g + 8) * HID + cg) = v1;
            }
        }
    }
}

// ===========================================================================
// Tensor-core causal flash attention (round-5 structure, bf16 hi/lo output).
// ===========================================================================
#define FLASH_SMEM (65536 + 512)

__global__ void __launch_bounds__(256)
flash_cp(const __nv_bfloat16* __restrict__ Qhp, const __nv_bfloat16* __restrict__ Qlp,
         const __nv_bfloat16* __restrict__ Khp, const __nv_bfloat16* __restrict__ Klp,
         const __nv_bfloat16* __restrict__ Vhp, const __nv_bfloat16* __restrict__ Vlp,
         const float* __restrict__ maskg,
         __nv_bfloat16* __restrict__ Ahp, __nv_bfloat16* __restrict__ Alp)
{
    extern __shared__ __align__(128) uint8_t sbuf[];
    const uint32_t sb = smem_u32(sbuf);

    const int tid  = threadIdx.x;
    const int lane = tid & 31;
    const int w    = tid >> 5;
    const int lr   = lane & 7;
    const int ml   = lane >> 3;
    const int qb   = blockIdx.x;
    const int h    = blockIdx.y;
    const int b    = blockIdx.z;
    const int q0   = qb * 128;
    const size_t base = ((size_t)b * S_LEN) * HID + (size_t)h * DH;

    // ---- stage Q via cp.async (hi at 0, lo at 16384) ----
#pragma unroll
    for (int j = 0; j < 8; j++) {
        int f = tid + j * 256;
        int term = j >> 2;
        int c = f & 1023;
        int row = c >> 3, qq = c & 7;
        uint32_t dst = sb + (uint32_t)term * 16384 + row * 128
                     + (((uint32_t)(qq ^ (row & 7))) << 4);
        const __nv_bfloat16* src = (term ? Qlp : Qhp) + base
                                 + (size_t)(q0 + row) * HID + qq * 8;
        CP_ASYNC16(dst, src);
    }
    CP_COMMIT();
    CP_WAIT(0);
    __syncthreads();

    uint32_t qh[4][4], ql[4][4];
    {
        int row = w * 16 + (ml & 1) * 8 + lr;
#pragma unroll
        for (int ks = 0; ks < 4; ks++) {
            int u = ks * 2 + (ml >> 1);
            uint32_t off = row * 128 + (((uint32_t)(u ^ (row & 7))) << 4);
            LDSM_X4(qh[ks][0], qh[ks][1], qh[ks][2], qh[ks][3], sb + off);
            LDSM_X4(ql[ks][0], ql[ks][1], ql[ks][2], ql[ks][3], sb + 16384 + off);
        }
    }
    __syncthreads();

    const int jmax = 2 * qb + 1;

    auto issue_tile = [&](int t) {
        const int k0t = t * 64;
        const __nv_bfloat16* bases[4] = {
            Khp + base + (size_t)k0t * HID,
            Klp + base + (size_t)k0t * HID,
            Vhp + base + (size_t)k0t * HID,
            Vlp + base + (size_t)k0t * HID };
        const uint32_t stg = sb + (uint32_t)(t & 1) * 32768;
#pragma unroll
        for (int j = 0; j < 8; j++) {
            int f = tid + j * 256;
            int row = (f >> 3) & 63, qq = f & 7;
            uint32_t dst = stg + (uint32_t)(j >> 1) * 8192 + row * 128
                         + (((uint32_t)(qq ^ (row & 7))) << 4);
            CP_ASYNC16(dst, bases[j >> 1] + (size_t)row * HID + qq * 8);
        }
        if (tid < 16)
            CP_ASYNC16(sb + 65536 + (uint32_t)(t & 1) * 256 + tid * 16,
                       maskg + (size_t)b * S_LEN + k0t + tid * 4);
        CP_COMMIT();
    };

    issue_tile(0);
    issue_tile(1);

    float oacc[8][4];
#pragma unroll
    for (int ns = 0; ns < 8; ns++)
#pragma unroll
        for (int r = 0; r < 4; r++) oacc[ns][r] = 0.0f;
    float m0 = -INFINITY, m1 = -INFINITY, l0 = 0.0f, l1 = 0.0f;

    const int r0g  = q0 + w * 16 + (lane >> 2);
    const int cloc = (lane & 3) * 2;

    for (int jb = 0; jb <= jmax; jb++) {
        const int k0 = jb * 64;
        CP_WAIT(1);
        __syncthreads();

        const uint32_t stg = sb + (uint32_t)(jb & 1) * 32768;
        const uint32_t sKh = stg, sKl = stg + 8192;
        const uint32_t sVh = stg + 16384, sVl = stg + 24576;
        const float* smask = (const float*)(sbuf + 65536 + (jb & 1) * 256);

        float sacc[8][4];
#pragma unroll
        for (int nt = 0; nt < 8; nt++)
#pragma unroll
            for (int r = 0; r < 4; r++) sacc[nt][r] = 0.0f;

#pragma unroll
        for (int ks = 0; ks < 4; ks++) {
            uint32_t kh[4][4], kl[4][4];
            int rowb = (ml >> 1) * 8 + lr;
            int u    = ks * 2 + (ml & 1);
#pragma unroll
            for (int g = 0; g < 4; g++) {
                int row = g * 16 + rowb;
                uint32_t off = row * 128 + (((uint32_t)(u ^ (row & 7))) << 4);
                LDSM_X4(kh[g][0], kh[g][1], kh[g][2], kh[g][3], sKh + off);
                LDSM_X4(kl[g][0], kl[g][1], kl[g][2], kl[g][3], sKl + off);
            }
#pragma unroll
            for (int g = 0; g < 4; g++)
#pragma unroll
                for (int j2 = 0; j2 < 2; j2++)
                    MMA16816(sacc[2 * g + j2], qh[ks][0], qh[ks][1], qh[ks][2], qh[ks][3],
                             kh[g][2 * j2], kh[g][2 * j2 + 1]);
#pragma unroll
            for (int g = 0; g < 4; g++)
#pragma unroll
                for (int j2 = 0; j2 < 2; j2++)
                    MMA16816(sacc[2 * g + j2], qh[ks][0], qh[ks][1], qh[ks][2], qh[ks][3],
                             kl[g][2 * j2], kl[g][2 * j2 + 1]);
#pragma unroll
            for (int g = 0; g < 4; g++)
#pragma unroll
                for (int j2 = 0; j2 < 2; j2++)
                    MMA16816(sacc[2 * g + j2], ql[ks][0], ql[ks][1], ql[ks][2], ql[ks][3],
                             kh[g][2 * j2], kh[g][2 * j2 + 1]);
        }

        float rm0 = -INFINITY, rm1 = -INFINITY;
#pragma unroll
        for (int nt = 0; nt < 8; nt++) {
            int c0 = nt * 8 + cloc;
            float mk0 = smask[c0], mk1 = smask[c0 + 1];
            int jg0 = k0 + c0, jg1 = jg0 + 1;
            sacc[nt][0] = (jg0 > r0g     || mk0 == 0.0f) ? FILLV : sacc[nt][0] * 0.125f;
            sacc[nt][1] = (jg1 > r0g     || mk1 == 0.0f) ? FILLV : sacc[nt][1] * 0.125f;
            sacc[nt][2] = (jg0 > r0g + 8 || mk0 == 0.0f) ? FILLV : sacc[nt][2] * 0.125f;
            sacc[nt][3] = (jg1 > r0g + 8 || mk1 == 0.0f) ? FILLV : sacc[nt][3] * 0.125f;
            rm0 = fmaxf(rm0, fmaxf(sacc[nt][0], sacc[nt][1]));
            rm1 = fmaxf(rm1, fmaxf(sacc[nt][2], sacc[nt][3]));
        }
        rm0 = fmaxf(rm0, __shfl_xor_sync(0xffffffffu, rm0, 1));
        rm0 = fmaxf(rm0, __shfl_xor_sync(0xffffffffu, rm0, 2));
        rm1 = fmaxf(rm1, __shfl_xor_sync(0xffffffffu, rm1, 1));
        rm1 = fmaxf(rm1, __shfl_xor_sync(0xffffffffu, rm1, 2));

        float mn0 = fmaxf(m0, rm0), mn1 = fmaxf(m1, rm1);
        float corr0 = __expf(m0 - mn0), corr1 = __expf(m1 - mn1);
        m0 = mn0; m1 = mn1;

        float rs0 = 0.0f, rs1 = 0.0f;
#pragma unroll
        for (int nt = 0; nt < 8; nt++) {
            sacc[nt][0] = __expf(sacc[nt][0] - mn0);
            sacc[nt][1] = __expf(sacc[nt][1] - mn0);
            sacc[nt][2] = __expf(sacc[nt][2] - mn1);
            sacc[nt][3] = __expf(sacc[nt][3] - mn1);
            rs0 += sacc[nt][0] + sacc[nt][1];
            rs1 += sacc[nt][2] + sacc[nt][3];
        }
        rs0 += __shfl_xor_sync(0xffffffffu, rs0, 1);
        rs0 += __shfl_xor_sync(0xffffffffu, rs0, 2);
        rs1 += __shfl_xor_sync(0xffffffffu, rs1, 1);
        rs1 += __shfl_xor_sync(0xffffffffu, rs1, 2);
        l0 = l0 * corr0 + rs0;
        l1 = l1 * corr1 + rs1;
#pragma unroll
        for (int ns = 0; ns < 8; ns++) {
            oacc[ns][0] *= corr0; oacc[ns][1] *= corr0;
            oacc[ns][2] *= corr1; oacc[ns][3] *= corr1;
        }

#pragma unroll
        for (int ks = 0; ks < 4; ks++) {
            uint32_t ph[4], pl[4];
            split2(sacc[2 * ks][0],     sacc[2 * ks][1],     ph[0], pl[0]);
            split2(sacc[2 * ks][2],     sacc[2 * ks][3],     ph[1], pl[1]);
            split2(sacc[2 * ks + 1][0], sacc[2 * ks + 1][1], ph[2], pl[2]);
            split2(sacc[2 * ks + 1][2], sacc[2 * ks + 1][3], ph[3], pl[3]);

            int rowv = ks * 16 + (ml & 1) * 8 + lr;
#pragma unroll
            for (int np = 0; np < 4; np++) {
                int u = np * 2 + (ml >> 1);
                uint32_t off = rowv * 128 + (((uint32_t)(u ^ (rowv & 7))) << 4);
                uint32_t vh[4], vl[4];
                LDSM_X4_T(vh[0], vh[1], vh[2], vh[3], sVh + off);
                LDSM_X4_T(vl[0], vl[1], vl[2], vl[3], sVl + off);
                MMA16816(oacc[2 * np],     ph[0], ph[1], ph[2], ph[3], vh[0], vh[1]);
                MMA16816(oacc[2 * np + 1], ph[0], ph[1], ph[2], ph[3], vh[2], vh[3]);
                MMA16816(oacc[2 * np],     ph[0], ph[1], ph[2], ph[3], vl[0], vl[1]);
                MMA16816(oacc[2 * np + 1], ph[0], ph[1], ph[2], ph[3], vl[2], vl[3]);
                MMA16816(oacc[2 * np],     pl[0], pl[1], pl[2], pl[3], vh[0], vh[1]);
                MMA16816(oacc[2 * np + 1], pl[0], pl[1], pl[2], pl[3], vh[2], vh[3]);
            }
        }

        __syncthreads();
        if (jb + 2 <= jmax) issue_tile(jb + 2);
        else                CP_COMMIT();
    }

    // ---- epilogue: normalize + bf16 hi/lo split ----
    float inv0 = 1.0f / l0, inv1 = 1.0f / l1;
#pragma unroll
    for (int ns = 0; ns < 8; ns++) {
        int col = ns * 8 + cloc;
        uint32_t hi, lo;
        split2(oacc[ns][0] * inv0, oacc[ns][1] * inv0, hi, lo);
        *(uint32_t*)(Ahp + base + (size_t)r0g * HID + col) = hi;
        *(uint32_t*)(Alp + base + (size_t)r0g * HID + col) = lo;
        split2(oacc[ns][2] * inv1, oacc[ns][3] * inv1, hi, lo);
        *(uint32_t*)(Ahp + base + (size_t)(r0g + 8) * HID + col) = hi;
        *(uint32_t*)(Alp + base + (size_t)(r0g + 8) * HID + col) = lo;
    }
}

// ---------------------------------------------------------------------------
extern "C" void kernel_launch(void* const* d_in, const int* in_sizes, int n_in,
                              void* d_out, int out_size)
{
    const float* q    = (const float*)d_in[0];
    const float* k    = (const float*)d_in[1];
    const float* v    = (const float*)d_in[2];
    const float* mask = (const float*)d_in[3];
    const float* Wq   = (const float*)d_in[4];
    const float* bq   = (const float*)d_in[5];
    const float* Wk   = (const float*)d_in[6];
    const float* bk   = (const float*)d_in[7];
    const float* Wv   = (const float*)d_in[8];
    const float* bv   = (const float*)d_in[9];
    const float* Wo   = (const float*)d_in[10];
    const float* bo   = (const float*)d_in[11];
    float* out = (float*)d_out;

    __nv_bfloat16 *xqh, *xql, *xkh, *xkl, *xvh, *xvl;
    __nv_bfloat16 *wqh, *wql, *wkh, *wkl, *wvh, *wvl, *woh, *wol;
    __nv_bfloat16 *Qh, *Ql, *Kh, *Kl, *Vh, *Vl, *Ah, *Al;
    cudaGetSymbolAddress((void**)&xqh, g_xqh); cudaGetSymbolAddress((void**)&xql, g_xql);
    cudaGetSymbolAddress((void**)&xkh, g_xkh); cudaGetSymbolAddress((void**)&xkl, g_xkl);
    cudaGetSymbolAddress((void**)&xvh, g_xvh); cudaGetSymbolAddress((void**)&xvl, g_xvl);
    cudaGetSymbolAddress((void**)&wqh, g_wqh); cudaGetSymbolAddress((void**)&wql, g_wql);
    cudaGetSymbolAddress((void**)&wkh, g_wkh); cudaGetSymbolAddress((void**)&wkl, g_wkl);
    cudaGetSymbolAddress((void**)&wvh, g_wvh); cudaGetSymbolAddress((void**)&wvl, g_wvl);
    cudaGetSymbolAddress((void**)&woh, g_woh); cudaGetSymbolAddress((void**)&wol, g_wol);
    cudaGetSymbolAddress((void**)&Qh,  g_Qh);  cudaGetSymbolAddress((void**)&Ql,  g_Ql);
    cudaGetSymbolAddress((void**)&Kh,  g_Kh);  cudaGetSymbolAddress((void**)&Kl,  g_Kl);
    cudaGetSymbolAddress((void**)&Vh,  g_Vh);  cudaGetSymbolAddress((void**)&Vl,  g_Vl);
    cudaGetSymbolAddress((void**)&Ah,  g_Ah);  cudaGetSymbolAddress((void**)&Al,  g_Al);

    cudaFuncSetAttribute(flash_cp, cudaFuncAttributeMaxDynamicSharedMemorySize,
                         FLASH_SMEM);
    cudaFuncSetAttribute(gemm_bf<true>,  cudaFuncAttributeMaxDynamicSharedMemorySize,
                         GEMM_SMEM);
    cudaFuncSetAttribute(gemm_bf<false>, cudaFuncAttributeMaxDynamicSharedMemorySize,
                         GEMM_SMEM);

    const int n4x = M_TOT * HID / 4;   // 2097152
    const int n4w = HID * HID / 4;     // 262144
    split_f32<<<n4x / 256, 256>>>(q,  xqh, xql, n4x);
    split_f32<<<n4x / 256, 256>>>(k,  xkh, xkl, n4x);
    split_f32<<<n4x / 256, 256>>>(v,  xvh, xvl, n4x);
    split_f32<<<n4w / 256, 256>>>(Wq, wqh, wql, n4w);
    split_f32<<<n4w / 256, 256>>>(Wk, wkh, wkl, n4w);
    split_f32<<<n4w / 256, 256>>>(Wv, wvh, wvl, n4w);
    split_f32<<<n4w / 256, 256>>>(Wo, woh, wol, n4w);

    dim3 ggrid(HID / 128, M_TOT / 128);   // (8, 64)
    gemm_bf<true ><<<ggrid, 256, GEMM_SMEM>>>(xqh, xql, wqh, wql, bq, nullptr, Qh, Ql);
    gemm_bf<true ><<<ggrid, 256, GEMM_SMEM>>>(xkh, xkl, wkh, wkl, bk, nullptr, Kh, Kl);
    gemm_bf<true ><<<ggrid, 256, GEMM_SMEM>>>(xvh, xvl, wvh, wvl, bv, nullptr, Vh, Vl);

    flash_cp<<<dim3(S_LEN / 128, NH, BATCH), 256, FLASH_SMEM>>>(
        Qh, Ql, Kh, Kl, Vh, Vl, mask, Ah, Al);

    gemm_bf<false><<<ggrid, 256, GEMM_SMEM>>>(Ah, Al, woh, wol, bo, out, nullptr, nullptr);
}

// round 7
// speedup vs baseline: 2.6909x; 1.1150x over previous
#include <cuda_runtime.h>
#include <cuda_bf16.h>
#include <cstdint>
#include <math.h>

#define S_LEN 2048
#define BATCH 4
#define HID   1024
#define NH    16
#define DH    64
#define M_TOT (BATCH * S_LEN)      // 8192
#define FILLV (-10000000000000.0f)

// Scratch (device globals: no allocations allowed)
__device__ __nv_bfloat16 g_xqh[M_TOT * HID], g_xql[M_TOT * HID];
__device__ __nv_bfloat16 g_xkh[M_TOT * HID], g_xkl[M_TOT * HID];
__device__ __nv_bfloat16 g_xvh[M_TOT * HID], g_xvl[M_TOT * HID];
__device__ __nv_bfloat16 g_wqh[HID * HID], g_wql[HID * HID];
__device__ __nv_bfloat16 g_wkh[HID * HID], g_wkl[HID * HID];
__device__ __nv_bfloat16 g_wvh[HID * HID], g_wvl[HID * HID];
__device__ __nv_bfloat16 g_woh[HID * HID], g_wol[HID * HID];
__device__ __nv_bfloat16 g_Qh[M_TOT * HID], g_Ql[M_TOT * HID];
__device__ __nv_bfloat16 g_Kh[M_TOT * HID], g_Kl[M_TOT * HID];
__device__ __nv_bfloat16 g_Vh[M_TOT * HID], g_Vl[M_TOT * HID];
__device__ __nv_bfloat16 g_Ah[M_TOT * HID], g_Al[M_TOT * HID];

// ===========================================================================
// helpers
// ===========================================================================
__device__ __forceinline__ uint32_t smem_u32(const void* p) {
    uint32_t a;
    asm("{ .reg .u64 t; cvta.to.shared.u64 t, %1; cvt.u32.u64 %0, t; }"
        : "=r"(a) : "l"(p));
    return a;
}

#define LDSM_X4(r0, r1, r2, r3, addr)                                         \
    asm volatile("ldmatrix.sync.aligned.m8n8.x4.shared.b16 {%0,%1,%2,%3}, [%4];" \
                 : "=r"(r0), "=r"(r1), "=r"(r2), "=r"(r3) : "r"(addr))

#define LDSM_X4_T(r0, r1, r2, r3, addr)                                       \
    asm volatile("ldmatrix.sync.aligned.m8n8.x4.trans.shared.b16 {%0,%1,%2,%3}, [%4];" \
                 : "=r"(r0), "=r"(r1), "=r"(r2), "=r"(r3) : "r"(addr))

#define MMA16816(d, a0, a1, a2, a3, b0, b1)                                   \
    asm volatile("mma.sync.aligned.m16n8k16.row.col.f32.bf16.bf16.f32 "       \
                 "{%0,%1,%2,%3}, {%4,%5,%6,%7}, {%8,%9}, {%0,%1,%2,%3};"      \
                 : "+f"((d)[0]), "+f"((d)[1]), "+f"((d)[2]), "+f"((d)[3])     \
                 : "r"(a0), "r"(a1), "r"(a2), "r"(a3), "r"(b0), "r"(b1))

#define CP_ASYNC16(dst, src)                                                  \
    asm volatile("cp.async.cg.shared.global [%0], [%1], 16;"                  \
                 :: "r"(dst), "l"(src) : "memory")
#define CP_COMMIT() asm volatile("cp.async.commit_group;" ::: "memory")
#define CP_WAIT(n)  asm volatile("cp.async.wait_group %0;" :: "n"(n) : "memory")

__device__ __forceinline__ uint32_t pack_bf2(float x, float y) {
    __nv_bfloat16 bx = __float2bfloat16_rn(x);
    __nv_bfloat16 by = __float2bfloat16_rn(y);
    return (uint32_t)__bfloat16_as_ushort(bx)
         | ((uint32_t)__bfloat16_as_ushort(by) << 16);
}

__device__ __forceinline__ void split4(const float4& v, uint2& hi, uint2& lo) {
    __nv_bfloat16 h0 = __float2bfloat16_rn(v.x);
    __nv_bfloat16 h1 = __float2bfloat16_rn(v.y);
    __nv_bfloat16 h2 = __float2bfloat16_rn(v.z);
    __nv_bfloat16 h3 = __float2bfloat16_rn(v.w);
    float l0 = v.x - __bfloat162float(h0);
    float l1 = v.y - __bfloat162float(h1);
    float l2 = v.z - __bfloat162float(h2);
    float l3 = v.w - __bfloat162float(h3);
    hi.x = (uint32_t)__bfloat16_as_ushort(h0)
         | ((uint32_t)__bfloat16_as_ushort(h1) << 16);
    hi.y = (uint32_t)__bfloat16_as_ushort(h2)
         | ((uint32_t)__bfloat16_as_ushort(h3) << 16);
    lo.x = pack_bf2(l0, l1);
    lo.y = pack_bf2(l2, l3);
}

__device__ __forceinline__ void split2(float x, float y, uint32_t& hi, uint32_t& lo) {
    __nv_bfloat16 hx = __float2bfloat16_rn(x);
    __nv_bfloat16 hy = __float2bfloat16_rn(y);
    hi = (uint32_t)__bfloat16_as_ushort(hx)
       | ((uint32_t)__bfloat16_as_ushort(hy) << 16);
    lo = pack_bf2(x - __bfloat162float(hx), y - __bfloat162float(hy));
}

// 128-byte-row XOR swizzle (same family as the verified flash tiles)
__device__ __forceinline__ uint32_t off128(int row, int u) {
    return (uint32_t)(row * 128 + (((u ^ (row & 7))) << 4));
}

// ===========================================================================
// fused split pass: all 7 fp32 tensors -> bf16 hi/lo in one launch
// ===========================================================================
struct SplitBatch {
    const float*   src[7];
    __nv_bfloat16* dh[7];
    __nv_bfloat16* dl[7];
    int            n4[7];
};

__global__ void __launch_bounds__(256)
split_all(SplitBatch s)
{
    const int t = blockIdx.y;
    const int i = blockIdx.x * 256 + threadIdx.x;
    if (i < s.n4[t]) {
        float4 v = ((const float4*)s.src[t])[i];
        uint2 hi, lo;
        split4(v, hi, lo);
        ((uint2*)s.dh[t])[i] = hi;
        ((uint2*)s.dl[t])[i] = lo;
    }
}

// ===========================================================================
// GEMM v3: C[8192,1024] = A*W^T + bias, pre-split bf16, 3-term split.
// CTA 128x128, BK=64, 3-stage cp.async (192KB smem), 8 warps (2x4).
// blockIdx.z selects the (A, W, bias, C) tuple -> QKV fused in one launch.
// Stage (64KB): Ah@0 Al@16384 Wh@32768 Wl@49152; rows = 64 bf16 = 128B.
// ===========================================================================
#define GK 1024
#define NCH2 16                      // 1024 / 64
#define GSTAGE2 65536
#define GEMM_SMEM2 (3 * GSTAGE2)     // 196608

struct GemmBatch {
    const __nv_bfloat16* ah[3];
    const __nv_bfloat16* al[3];
    const __nv_bfloat16* wh[3];
    const __nv_bfloat16* wl[3];
    const float*         bias[3];
    __nv_bfloat16*       ch[3];
    __nv_bfloat16*       cl[3];
    float*               c32[3];
};

template<bool BF16OUT>
__global__ void __launch_bounds__(256)
gemm_bf2(GemmBatch gb)
{
    extern __shared__ __align__(128) uint8_t smg[];
    const uint32_t sb = smem_u32(smg);
    const int tid  = threadIdx.x;
    const int lane = tid & 31;
    const int warp = tid >> 5;
    const int wm   = warp >> 2;
    const int wn   = warp & 3;
    const int bm   = blockIdx.y * 128;
    const int bn   = blockIdx.x * 128;
    const int z    = blockIdx.z;
    const int lr   = lane & 7;
    const int ml   = lane >> 3;

    const __nv_bfloat16* srcs[4] = {
        gb.ah[z] + (size_t)bm * GK, gb.al[z] + (size_t)bm * GK,
        gb.wh[z] + (size_t)bn * GK, gb.wl[z] + (size_t)bn * GK };

    // cp.async slots: f = tid + j*256 over 1024 granules = 128 rows x 8
    const int r0 = tid >> 3, g0 = tid & 7;

    // frag row bases + xor bits
    int rowA[4], xorA[4];
#pragma unroll
    for (int mt = 0; mt < 4; mt++) {
        int row = wm * 64 + mt * 16 + (ml & 1) * 8 + lr;
        rowA[mt] = row * 128;
        xorA[mt] = row & 7;
    }
    int rowW[2], xorW[2];
#pragma unroll
    for (int p = 0; p < 2; p++) {
        int row = wn * 32 + p * 16 + (ml >> 1) * 8 + lr;
        rowW[p] = row * 128;
        xorW[p] = row & 7;
    }
    const int gA = ml >> 1;   // + ks*2
    const int gW = ml & 1;    // + ks*2

    float acc[4][4][4];
#pragma unroll
    for (int mt = 0; mt < 4; mt++)
#pragma unroll
        for (int nt = 0; nt < 4; nt++)
#pragma unroll
            for (int r = 0; r < 4; r++) acc[mt][nt][r] = 0.0f;

    auto issue = [&](int t) {
        int st = t; while (st >= 3) st -= 3;
        const uint32_t stg = sb + (uint32_t)st * GSTAGE2;
        const int kc = t * 64;
#pragma unroll
        for (int m = 0; m < 4; m++) {
            const __nv_bfloat16* s = srcs[m] + kc + g0 * 8;
#pragma unroll
            for (int j = 0; j < 4; j++) {
                int row = r0 + j * 32;
                CP_ASYNC16(stg + m * 16384 + off128(row, g0),
                           s + (size_t)row * GK);
            }
        }
        CP_COMMIT();
    };

    issue(0);
    issue(1);

    for (int c = 0; c < NCH2; c++) {
        CP_WAIT(1);
        __syncthreads();
        if (c + 2 < NCH2) issue(c + 2);
        else              CP_COMMIT();

        int st = c; while (st >= 3) st -= 3;
        const uint32_t stg = sb + (uint32_t)st * GSTAGE2;

#pragma unroll
        for (int ks = 0; ks < 4; ks++) {
            uint32_t ah[4][4], al[4][4], wh[2][4], wl[2][4];
#pragma unroll
            for (int mt = 0; mt < 4; mt++) {
                uint32_t off = (uint32_t)rowA[mt]
                             + (((uint32_t)((ks * 2 + gA) ^ xorA[mt])) << 4);
                LDSM_X4(ah[mt][0], ah[mt][1], ah[mt][2], ah[mt][3], stg + off);
                LDSM_X4(al[mt][0], al[mt][1], al[mt][2], al[mt][3], stg + 16384 + off);
            }
#pragma unroll
            for (int p = 0; p < 2; p++) {
                uint32_t off = (uint32_t)rowW[p]
                             + (((uint32_t)((ks * 2 + gW) ^ xorW[p])) << 4);
                LDSM_X4(wh[p][0], wh[p][1], wh[p][2], wh[p][3], stg + 32768 + off);
                LDSM_X4(wl[p][0], wl[p][1], wl[p][2], wl[p][3], stg + 49152 + off);
            }
#pragma unroll
            for (int mt = 0; mt < 4; mt++)
#pragma unroll
                for (int p = 0; p < 2; p++)
#pragma unroll
                    for (int j2 = 0; j2 < 2; j2++) {
                        int nt = 2 * p + j2;
                        MMA16816(acc[mt][nt], ah[mt][0], ah[mt][1], ah[mt][2], ah[mt][3],
                                 wh[p][2 * j2], wh[p][2 * j2 + 1]);
                        MMA16816(acc[mt][nt], ah[mt][0], ah[mt][1], ah[mt][2], ah[mt][3],
                                 wl[p][2 * j2], wl[p][2 * j2 + 1]);
                        MMA16816(acc[mt][nt], al[mt][0], al[mt][1], al[mt][2], al[mt][3],
                                 wh[p][2 * j2], wh[p][2 * j2 + 1]);
                    }
        }
    }

    const float* bias = gb.bias[z];
#pragma unroll
    for (int mt = 0; mt < 4; mt++) {
        int r0g = bm + wm * 64 + mt * 16 + (lane >> 2);
#pragma unroll
        for (int nt = 0; nt < 4; nt++) {
            int cg = bn + wn * 32 + nt * 8 + (lane & 3) * 2;
            float2 bz = *(const float2*)(bias + cg);
            float2 v0 = make_float2(acc[mt][nt][0] + bz.x, acc[mt][nt][1] + bz.y);
            float2 v1 = make_float2(acc[mt][nt][2] + bz.x, acc[mt][nt][3] + bz.y);
            if (BF16OUT) {
                uint32_t hi, lo;
                split2(v0.x, v0.y, hi, lo);
                *(uint32_t*)(gb.ch[z] + (size_t)r0g * HID + cg) = hi;
                *(uint32_t*)(gb.cl[z] + (size_t)r0g * HID + cg) = lo;
                split2(v1.x, v1.y, hi, lo);
                *(uint32_t*)(gb.ch[z] + (size_t)(r0g + 8) * HID + cg) = hi;
                *(uint32_t*)(gb.cl[z] + (size_t)(r0g + 8) * HID + cg) = lo;
            } else {
                *(float2*)(gb.c32[z] + (size_t)r0g * HID + cg)       = v0;
                *(float2*)(gb.c32[z] + (size_t)(r0g + 8) * HID + cg) = v1;
            }
        }
    }
}

// ===========================================================================
// Tensor-core causal flash attention (round-6 verified, bf16 hi/lo output).
// ===========================================================================
#define FLASH_SMEM (65536 + 512)

__global__ void __launch_bounds__(256)
flash_cp(const __nv_bfloat16* __restrict__ Qhp, const __nv_bfloat16* __restrict__ Qlp,
         const __nv_bfloat16* __restrict__ Khp, const __nv_bfloat16* __restrict__ Klp,
         const __nv_bfloat16* __restrict__ Vhp, const __nv_bfloat16* __restrict__ Vlp,
         const float* __restrict__ maskg,
         __nv_bfloat16* __restrict__ Ahp, __nv_bfloat16* __restrict__ Alp)
{
    extern __shared__ __align__(128) uint8_t sbuf[];
    const uint32_t sb = smem_u32(sbuf);

    const int tid  = threadIdx.x;
    const int lane = tid & 31;
    const int w    = tid >> 5;
    const int lr   = lane & 7;
    const int ml   = lane >> 3;
    const int qb   = blockIdx.x;
    const int h    = blockIdx.y;
    const int b    = blockIdx.z;
    const int q0   = qb * 128;
    const size_t base = ((size_t)b * S_LEN) * HID + (size_t)h * DH;

#pragma unroll
    for (int j = 0; j < 8; j++) {
        int f = tid + j * 256;
        int term = j >> 2;
        int c = f & 1023;
        int row = c >> 3, qq = c & 7;
        uint32_t dst = sb + (uint32_t)term * 16384 + off128(row, qq);
        const __nv_bfloat16* src = (term ? Qlp : Qhp) + base
                                 + (size_t)(q0 + row) * HID + qq * 8;
        CP_ASYNC16(dst, src);
    }
    CP_COMMIT();
    CP_WAIT(0);
    __syncthreads();

    uint32_t qh[4][4], ql[4][4];
    {
        int row = w * 16 + (ml & 1) * 8 + lr;
#pragma unroll
        for (int ks = 0; ks < 4; ks++) {
            int u = ks * 2 + (ml >> 1);
            uint32_t off = off128(row, u);
            LDSM_X4(qh[ks][0], qh[ks][1], qh[ks][2], qh[ks][3], sb + off);
            LDSM_X4(ql[ks][0], ql[ks][1], ql[ks][2], ql[ks][3], sb + 16384 + off);
        }
    }
    __syncthreads();

    const int jmax = 2 * qb + 1;

    auto issue_tile = [&](int t) {
        const int k0t = t * 64;
        const __nv_bfloat16* bases[4] = {
            Khp + base + (size_t)k0t * HID,
            Klp + base + (size_t)k0t * HID,
            Vhp + base + (size_t)k0t * HID,
            Vlp + base + (size_t)k0t * HID };
        const uint32_t stg = sb + (uint32_t)(t & 1) * 32768;
#pragma unroll
        for (int j = 0; j < 8; j++) {
            int f = tid + j * 256;
            int row = (f >> 3) & 63, qq = f & 7;
            uint32_t dst = stg + (uint32_t)(j >> 1) * 8192 + off128(row, qq);
            CP_ASYNC16(dst, bases[j >> 1] + (size_t)row * HID + qq * 8);
        }
        if (tid < 16)
            CP_ASYNC16(sb + 65536 + (uint32_t)(t & 1) * 256 + tid * 16,
                       maskg + (size_t)b * S_LEN + k0t + tid * 4);
        CP_COMMIT();
    };

    issue_tile(0);
    issue_tile(1);

    float oacc[8][4];
#pragma unroll
    for (int ns = 0; ns < 8; ns++)
#pragma unroll
        for (int r = 0; r < 4; r++) oacc[ns][r] = 0.0f;
    float m0 = -INFINITY, m1 = -INFINITY, l0 = 0.0f, l1 = 0.0f;

    const int r0g  = q0 + w * 16 + (lane >> 2);
    const int cloc = (lane & 3) * 2;

    for (int jb = 0; jb <= jmax; jb++) {
        const int k0 = jb * 64;
        CP_WAIT(1);
        __syncthreads();

        const uint32_t stg = sb + (uint32_t)(jb & 1) * 32768;
        const uint32_t sKh = stg, sKl = stg + 8192;
        const uint32_t sVh = stg + 16384, sVl = stg + 24576;
        const float* smask = (const float*)(sbuf + 65536 + (jb & 1) * 256);

        float sacc[8][4];
#pragma unroll
        for (int nt = 0; nt < 8; nt++)
#pragma unroll
            for (int r = 0; r < 4; r++) sacc[nt][r] = 0.0f;

#pragma unroll
        for (int ks = 0; ks < 4; ks++) {
            uint32_t kh[4][4], kl[4][4];
            int rowb = (ml >> 1) * 8 + lr;
            int u    = ks * 2 + (ml & 1);
#pragma unroll
            for (int g = 0; g < 4; g++) {
                int row = g * 16 + rowb;
                uint32_t off = off128(row, u);
                LDSM_X4(kh[g][0], kh[g][1], kh[g][2], kh[g][3], sKh + off);
                LDSM_X4(kl[g][0], kl[g][1], kl[g][2], kl[g][3], sKl + off);
            }
#pragma unroll
            for (int g = 0; g < 4; g++)
#pragma unroll
                for (int j2 = 0; j2 < 2; j2++)
                    MMA16816(sacc[2 * g + j2], qh[ks][0], qh[ks][1], qh[ks][2], qh[ks][3],
                             kh[g][2 * j2], kh[g][2 * j2 + 1]);
#pragma unroll
            for (int g = 0; g < 4; g++)
#pragma unroll
                for (int j2 = 0; j2 < 2; j2++)
                    MMA16816(sacc[2 * g + j2], qh[ks][0], qh[ks][1], qh[ks][2], qh[ks][3],
                             kl[g][2 * j2], kl[g][2 * j2 + 1]);
#pragma unroll
            for (int g = 0; g < 4; g++)
#pragma unroll
                for (int j2 = 0; j2 < 2; j2++)
                    MMA16816(sacc[2 * g + j2], ql[ks][0], ql[ks][1], ql[ks][2], ql[ks][3],
                             kh[g][2 * j2], kh[g][2 * j2 + 1]);
        }

        float rm0 = -INFINITY, rm1 = -INFINITY;
#pragma unroll
        for (int nt = 0; nt < 8; nt++) {
            int c0 = nt * 8 + cloc;
            float mk0 = smask[c0], mk1 = smask[c0 + 1];
            int jg0 = k0 + c0, jg1 = jg0 + 1;
            sacc[nt][0] = (jg0 > r0g     || mk0 == 0.0f) ? FILLV : sacc[nt][0] * 0.125f;
            sacc[nt][1] = (jg1 > r0g     || mk1 == 0.0f) ? FILLV : sacc[nt][1] * 0.125f;
            sacc[nt][2] = (jg0 > r0g + 8 || mk0 == 0.0f) ? FILLV : sacc[nt][2] * 0.125f;
            sacc[nt][3] = (jg1 > r0g + 8 || mk1 == 0.0f) ? FILLV : sacc[nt][3] * 0.125f;
            rm0 = fmaxf(rm0, fmaxf(sacc[nt][0], sacc[nt][1]));
            rm1 = fmaxf(rm1, fmaxf(sacc[nt][2], sacc[nt][3]));
        }
        rm0 = fmaxf(rm0, __shfl_xor_sync(0xffffffffu, rm0, 1));
        rm0 = fmaxf(rm0, __shfl_xor_sync(0xffffffffu, rm0, 2));
        rm1 = fmaxf(rm1, __shfl_xor_sync(0xffffffffu, rm1, 1));
        rm1 = fmaxf(rm1, __shfl_xor_sync(0xffffffffu, rm1, 2));

        float mn0 = fmaxf(m0, rm0), mn1 = fmaxf(m1, rm1);
        float corr0 = __expf(m0 - mn0), corr1 = __expf(m1 - mn1);
        m0 = mn0; m1 = mn1;

        float rs0 = 0.0f, rs1 = 0.0f;
#pragma unroll
        for (int nt = 0; nt < 8; nt++) {
            sacc[nt][0] = __expf(sacc[nt][0] - mn0);
            sacc[nt][1] = __expf(sacc[nt][1] - mn0);
            sacc[nt][2] = __expf(sacc[nt][2] - mn1);
            sacc[nt][3] = __expf(sacc[nt][3] - mn1);
            rs0 += sacc[nt][0] + sacc[nt][1];
            rs1 += sacc[nt][2] + sacc[nt][3];
        }
        rs0 += __shfl_xor_sync(0xffffffffu, rs0, 1);
        rs0 += __shfl_xor_sync(0xffffffffu, rs0, 2);
        rs1 += __shfl_xor_sync(0xffffffffu, rs1, 1);
        rs1 += __shfl_xor_sync(0xffffffffu, rs1, 2);
        l0 = l0 * corr0 + rs0;
        l1 = l1 * corr1 + rs1;
#pragma unroll
        for (int ns = 0; ns < 8; ns++) {
            oacc[ns][0] *= corr0; oacc[ns][1] *= corr0;
            oacc[ns][2] *= corr1; oacc[ns][3] *= corr1;
        }

#pragma unroll
        for (int ks = 0; ks < 4; ks++) {
            uint32_t ph[4], pl[4];
            split2(sacc[2 * ks][0],     sacc[2 * ks][1],     ph[0], pl[0]);
            split2(sacc[2 * ks][2],     sacc[2 * ks][3],     ph[1], pl[1]);
            split2(sacc[2 * ks + 1][0], sacc[2 * ks + 1][1], ph[2], pl[2]);
            split2(sacc[2 * ks + 1][2], sacc[2 * ks + 1][3], ph[3], pl[3]);

            int rowv = ks * 16 + (ml & 1) * 8 + lr;
#pragma unroll
            for (int np = 0; np < 4; np++) {
                int u = np * 2 + (ml >> 1);
                uint32_t off = off128(rowv, u);
                uint32_t vh[4], vl[4];
                LDSM_X4_T(vh[0], vh[1], vh[2], vh[3], sVh + off);
                LDSM_X4_T(vl[0], vl[1], vl[2], vl[3], sVl + off);
                MMA16816(oacc[2 * np],     ph[0], ph[1], ph[2], ph[3], vh[0], vh[1]);
                MMA16816(oacc[2 * np + 1], ph[0], ph[1], ph[2], ph[3], vh[2], vh[3]);
                MMA16816(oacc[2 * np],     ph[0], ph[1], ph[2], ph[3], vl[0], vl[1]);
                MMA16816(oacc[2 * np + 1], ph[0], ph[1], ph[2], ph[3], vl[2], vl[3]);
                MMA16816(oacc[2 * np],     pl[0], pl[1], pl[2], pl[3], vh[0], vh[1]);
                MMA16816(oacc[2 * np + 1], pl[0], pl[1], pl[2], pl[3], vh[2], vh[3]);
            }
        }

        __syncthreads();
        if (jb + 2 <= jmax) issue_tile(jb + 2);
        else                CP_COMMIT();
    }

    float inv0 = 1.0f / l0, inv1 = 1.0f / l1;
#pragma unroll
    for (int ns = 0; ns < 8; ns++) {
        int col = ns * 8 + cloc;
        uint32_t hi, lo;
        split2(oacc[ns][0] * inv0, oacc[ns][1] * inv0, hi, lo);
        *(uint32_t*)(Ahp + base + (size_t)r0g * HID + col) = hi;
        *(uint32_t*)(Alp + base + (size_t)r0g * HID + col) = lo;
        split2(oacc[ns][2] * inv1, oacc[ns][3] * inv1, hi, lo);
        *(uint32_t*)(Ahp + base + (size_t)(r0g + 8) * HID + col) = hi;
        *(uint32_t*)(Alp + base + (size_t)(r0g + 8) * HID + col) = lo;
    }
}

// ---------------------------------------------------------------------------
extern "C" void kernel_launch(void* const* d_in, const int* in_sizes, int n_in,
                              void* d_out, int out_size)
{
    const float* q    = (const float*)d_in[0];
    const float* k    = (const float*)d_in[1];
    const float* v    = (const float*)d_in[2];
    const float* mask = (const float*)d_in[3];
    const float* Wq   = (const float*)d_in[4];
    const float* bq   = (const float*)d_in[5];
    const float* Wk   = (const float*)d_in[6];
    const float* bk   = (const float*)d_in[7];
    const float* Wv   = (const float*)d_in[8];
    const float* bv   = (const float*)d_in[9];
    const float* Wo   = (const float*)d_in[10];
    const float* bo   = (const float*)d_in[11];
    float* out = (float*)d_out;

    __nv_bfloat16 *xqh, *xql, *xkh, *xkl, *xvh, *xvl;
    __nv_bfloat16 *wqh, *wql, *wkh, *wkl, *wvh, *wvl, *woh, *wol;
    __nv_bfloat16 *Qh, *Ql, *Kh, *Kl, *Vh, *Vl, *Ah, *Al;
    cudaGetSymbolAddress((void**)&xqh, g_xqh); cudaGetSymbolAddress((void**)&xql, g_xql);
    cudaGetSymbolAddress((void**)&xkh, g_xkh); cudaGetSymbolAddress((void**)&xkl, g_xkl);
    cudaGetSymbolAddress((void**)&xvh, g_xvh); cudaGetSymbolAddress((void**)&xvl, g_xvl);
    cudaGetSymbolAddress((void**)&wqh, g_wqh); cudaGetSymbolAddress((void**)&wql, g_wql);
    cudaGetSymbolAddress((void**)&wkh, g_wkh); cudaGetSymbolAddress((void**)&wkl, g_wkl);
    cudaGetSymbolAddress((void**)&wvh, g_wvh); cudaGetSymbolAddress((void**)&wvl, g_wvl);
    cudaGetSymbolAddress((void**)&woh, g_woh); cudaGetSymbolAddress((void**)&wol, g_wol);
    cudaGetSymbolAddress((void**)&Qh,  g_Qh);  cudaGetSymbolAddress((void**)&Ql,  g_Ql);
    cudaGetSymbolAddress((void**)&Kh,  g_Kh);  cudaGetSymbolAddress((void**)&Kl,  g_Kl);
    cudaGetSymbolAddress((void**)&Vh,  g_Vh);  cudaGetSymbolAddress((void**)&Vl,  g_Vl);
    cudaGetSymbolAddress((void**)&Ah,  g_Ah);  cudaGetSymbolAddress((void**)&Al,  g_Al);

    cudaFuncSetAttribute(flash_cp, cudaFuncAttributeMaxDynamicSharedMemorySize,
                         FLASH_SMEM);
    cudaFuncSetAttribute(gemm_bf2<true>,  cudaFuncAttributeMaxDynamicSharedMemorySize,
                         GEMM_SMEM2);
    cudaFuncSetAttribute(gemm_bf2<false>, cudaFuncAttributeMaxDynamicSharedMemorySize,
                         GEMM_SMEM2);

    const int n4x = M_TOT * HID / 4;   // 2097152
    const int n4w = HID * HID / 4;     // 262144

    SplitBatch sbt;
    sbt.src[0] = q;  sbt.dh[0] = xqh; sbt.dl[0] = xql; sbt.n4[0] = n4x;
    sbt.src[1] = k;  sbt.dh[1] = xkh; sbt.dl[1] = xkl; sbt.n4[1] = n4x;
    sbt.src[2] = v;  sbt.dh[2] = xvh; sbt.dl[2] = xvl; sbt.n4[2] = n4x;
    sbt.src[3] = Wq; sbt.dh[3] = wqh; sbt.dl[3] = wql; sbt.n4[3] = n4w;
    sbt.src[4] = Wk; sbt.dh[4] = wkh; sbt.dl[4] = wkl; sbt.n4[4] = n4w;
    sbt.src[5] = Wv; sbt.dh[5] = wvh; sbt.dl[5] = wvl; sbt.n4[5] = n4w;
    sbt.src[6] = Wo; sbt.dh[6] = woh; sbt.dl[6] = wol; sbt.n4[6] = n4w;
    split_all<<<dim3(n4x / 256, 7), 256>>>(sbt);

    GemmBatch gqkv = {};
    gqkv.ah[0] = xqh; gqkv.al[0] = xql; gqkv.wh[0] = wqh; gqkv.wl[0] = wql;
    gqkv.bias[0] = bq; gqkv.ch[0] = Qh; gqkv.cl[0] = Ql;
    gqkv.ah[1] = xkh; gqkv.al[1] = xkl; gqkv.wh[1] = wkh; gqkv.wl[1] = wkl;
    gqkv.bias[1] = bk; gqkv.ch[1] = Kh; gqkv.cl[1] = Kl;
    gqkv.ah[2] = xvh; gqkv.al[2] = xvl; gqkv.wh[2] = wvh; gqkv.wl[2] = wvl;
    gqkv.bias[2] = bv; gqkv.ch[2] = Vh; gqkv.cl[2] = Vl;
    gemm_bf2<true><<<dim3(HID / 128, M_TOT / 128, 3), 256, GEMM_SMEM2>>>(gqkv);

    flash_cp<<<dim3(S_LEN / 128, NH, BATCH), 256, FLASH_SMEM>>>(
        Qh, Ql, Kh, Kl, Vh, Vl, mask, Ah, Al);

    GemmBatch gout = {};
    gout.ah[0] = Ah; gout.al[0] = Al; gout.wh[0] = woh; gout.wl[0] = wol;
    gout.bias[0] = bo; gout.c32[0] = out;
    gemm_bf2<false><<<dim3(HID / 128, M_TOT / 128, 1), 256, GEMM_SMEM2>>>(gout);
}

// round 8
// speedup vs baseline: 2.8596x; 1.0627x over previous
#include <cuda_runtime.h>
#include <cuda_bf16.h>
#include <cstdint>
#include <math.h>

#define S_LEN 2048
#define BATCH 4
#define HID   1024
#define NH    16
#define DH    64
#define M_TOT (BATCH * S_LEN)      // 8192
#define FILLV (-10000000000000.0f)

// Scratch (device globals: no allocations allowed)
__device__ __nv_bfloat16 g_xqh[M_TOT * HID], g_xql[M_TOT * HID];
__device__ __nv_bfloat16 g_xkh[M_TOT * HID], g_xkl[M_TOT * HID];
__device__ __nv_bfloat16 g_xvh[M_TOT * HID], g_xvl[M_TOT * HID];
__device__ __nv_bfloat16 g_wqh[HID * HID], g_wql[HID * HID];
__device__ __nv_bfloat16 g_wkh[HID * HID], g_wkl[HID * HID];
__device__ __nv_bfloat16 g_wvh[HID * HID], g_wvl[HID * HID];
__device__ __nv_bfloat16 g_woh[HID * HID], g_wol[HID * HID];
__device__ __nv_bfloat16 g_Qh[M_TOT * HID], g_Ql[M_TOT * HID];
__device__ __nv_bfloat16 g_Kh[M_TOT * HID], g_Kl[M_TOT * HID];
__device__ __nv_bfloat16 g_Vh[M_TOT * HID], g_Vl[M_TOT * HID];
__device__ __nv_bfloat16 g_Ah[M_TOT * HID], g_Al[M_TOT * HID];

// ===========================================================================
// helpers
// ===========================================================================
__device__ __forceinline__ uint32_t smem_u32(const void* p) {
    uint32_t a;
    asm("{ .reg .u64 t; cvta.to.shared.u64 t, %1; cvt.u32.u64 %0, t; }"
        : "=r"(a) : "l"(p));
    return a;
}

#define LDSM_X4(r0, r1, r2, r3, addr)                                         \
    asm volatile("ldmatrix.sync.aligned.m8n8.x4.shared.b16 {%0,%1,%2,%3}, [%4];" \
                 : "=r"(r0), "=r"(r1), "=r"(r2), "=r"(r3) : "r"(addr))

#define LDSM_X4_T(r0, r1, r2, r3, addr)                                       \
    asm volatile("ldmatrix.sync.aligned.m8n8.x4.trans.shared.b16 {%0,%1,%2,%3}, [%4];" \
                 : "=r"(r0), "=r"(r1), "=r"(r2), "=r"(r3) : "r"(addr))

#define MMA16816(d, a0, a1, a2, a3, b0, b1)                                   \
    asm volatile("mma.sync.aligned.m16n8k16.row.col.f32.bf16.bf16.f32 "       \
                 "{%0,%1,%2,%3}, {%4,%5,%6,%7}, {%8,%9}, {%0,%1,%2,%3};"      \
                 : "+f"((d)[0]), "+f"((d)[1]), "+f"((d)[2]), "+f"((d)[3])     \
                 : "r"(a0), "r"(a1), "r"(a2), "r"(a3), "r"(b0), "r"(b1))

#define CP_ASYNC16(dst, src)                                                  \
    asm volatile("cp.async.cg.shared.global [%0], [%1], 16;"                  \
                 :: "r"(dst), "l"(src) : "memory")
#define CP_COMMIT() asm volatile("cp.async.commit_group;" ::: "memory")
#define CP_WAIT(n)  asm volatile("cp.async.wait_group %0;" :: "n"(n) : "memory")

#define BAR_G(id) asm volatile("bar.sync %0, %1;" :: "r"(id), "r"(128) : "memory")

__device__ __forceinline__ uint32_t pack_bf2(float x, float y) {
    __nv_bfloat16 bx = __float2bfloat16_rn(x);
    __nv_bfloat16 by = __float2bfloat16_rn(y);
    return (uint32_t)__bfloat16_as_ushort(bx)
         | ((uint32_t)__bfloat16_as_ushort(by) << 16);
}

__device__ __forceinline__ void split4(const float4& v, uint2& hi, uint2& lo) {
    __nv_bfloat16 h0 = __float2bfloat16_rn(v.x);
    __nv_bfloat16 h1 = __float2bfloat16_rn(v.y);
    __nv_bfloat16 h2 = __float2bfloat16_rn(v.z);
    __nv_bfloat16 h3 = __float2bfloat16_rn(v.w);
    float l0 = v.x - __bfloat162float(h0);
    float l1 = v.y - __bfloat162float(h1);
    float l2 = v.z - __bfloat162float(h2);
    float l3 = v.w - __bfloat162float(h3);
    hi.x = (uint32_t)__bfloat16_as_ushort(h0)
         | ((uint32_t)__bfloat16_as_ushort(h1) << 16);
    hi.y = (uint32_t)__bfloat16_as_ushort(h2)
         | ((uint32_t)__bfloat16_as_ushort(h3) << 16);
    lo.x = pack_bf2(l0, l1);
    lo.y = pack_bf2(l2, l3);
}

__device__ __forceinline__ void split2(float x, float y, uint32_t& hi, uint32_t& lo) {
    __nv_bfloat16 hx = __float2bfloat16_rn(x);
    __nv_bfloat16 hy = __float2bfloat16_rn(y);
    hi = (uint32_t)__bfloat16_as_ushort(hx)
       | ((uint32_t)__bfloat16_as_ushort(hy) << 16);
    lo = pack_bf2(x - __bfloat162float(hx), y - __bfloat162float(hy));
}

// fast truncation split for P (positive values): hi = upper16 bits, lo = rn(x-hi)
__device__ __forceinline__ void split2t(float x, float y, uint32_t& hi, uint32_t& lo) {
    uint32_t ux = __float_as_uint(x), uy = __float_as_uint(y);
    hi = __byte_perm(ux, uy, 0x7632);   // {x.hi16 -> low, y.hi16 -> high}
    float lx = x - __uint_as_float(ux & 0xffff0000u);
    float ly = y - __uint_as_float(uy & 0xffff0000u);
    asm("cvt.rn.bf16x2.f32 %0, %1, %2;" : "=r"(lo) : "f"(ly), "f"(lx));
}

// 128-byte-row XOR swizzle
__device__ __forceinline__ uint32_t off128(int row, int u) {
    return (uint32_t)(row * 128 + (((u ^ (row & 7))) << 4));
}

// ===========================================================================
// fused split pass
// ===========================================================================
struct SplitBatch {
    const float*   src[7];
    __nv_bfloat16* dh[7];
    __nv_bfloat16* dl[7];
    int            n4[7];
};

__global__ void __launch_bounds__(256)
split_all(SplitBatch s)
{
    const int t = blockIdx.y;
    const int i = blockIdx.x * 256 + threadIdx.x;
    if (i < s.n4[t]) {
        float4 v = ((const float4*)s.src[t])[i];
        uint2 hi, lo;
        split4(v, hi, lo);
        ((uint2*)s.dh[t])[i] = hi;
        ((uint2*)s.dl[t])[i] = lo;
    }
}

// ===========================================================================
// GEMM (round-7 verified): BK=64, 3-stage cp.async, batched over blockIdx.z.
// Adds per-z output scale (Q pre-scaled by 0.125 — exact power of two).
// ===========================================================================
#define GK 1024
#define NCH2 16
#define GSTAGE2 65536
#define GEMM_SMEM2 (3 * GSTAGE2)

struct GemmBatch {
    const __nv_bfloat16* ah[3];
    const __nv_bfloat16* al[3];
    const __nv_bfloat16* wh[3];
    const __nv_bfloat16* wl[3];
    const float*         bias[3];
    __nv_bfloat16*       ch[3];
    __nv_bfloat16*       cl[3];
    float*               c32[3];
    float                sc[3];
};

template<bool BF16OUT>
__global__ void __launch_bounds__(256)
gemm_bf2(GemmBatch gb)
{
    extern __shared__ __align__(128) uint8_t smg[];
    const uint32_t sb = smem_u32(smg);
    const int tid  = threadIdx.x;
    const int lane = tid & 31;
    const int warp = tid >> 5;
    const int wm   = warp >> 2;
    const int wn   = warp & 3;
    const int bm   = blockIdx.y * 128;
    const int bn   = blockIdx.x * 128;
    const int z    = blockIdx.z;
    const int lr   = lane & 7;
    const int ml   = lane >> 3;

    const __nv_bfloat16* srcs[4] = {
        gb.ah[z] + (size_t)bm * GK, gb.al[z] + (size_t)bm * GK,
        gb.wh[z] + (size_t)bn * GK, gb.wl[z] + (size_t)bn * GK };

    const int r0 = tid >> 3, g0 = tid & 7;

    int rowA[4], xorA[4];
#pragma unroll
    for (int mt = 0; mt < 4; mt++) {
        int row = wm * 64 + mt * 16 + (ml & 1) * 8 + lr;
        rowA[mt] = row * 128;
        xorA[mt] = row & 7;
    }
    int rowW[2], xorW[2];
#pragma unroll
    for (int p = 0; p < 2; p++) {
        int row = wn * 32 + p * 16 + (ml >> 1) * 8 + lr;
        rowW[p] = row * 128;
        xorW[p] = row & 7;
    }
    const int gA = ml >> 1;
    const int gW = ml & 1;

    float acc[4][4][4];
#pragma unroll
    for (int mt = 0; mt < 4; mt++)
#pragma unroll
        for (int nt = 0; nt < 4; nt++)
#pragma unroll
            for (int r = 0; r < 4; r++) acc[mt][nt][r] = 0.0f;

    auto issue = [&](int t) {
        int st = t; while (st >= 3) st -= 3;
        const uint32_t stg = sb + (uint32_t)st * GSTAGE2;
        const int kc = t * 64;
#pragma unroll
        for (int m = 0; m < 4; m++) {
            const __nv_bfloat16* s = srcs[m] + kc + g0 * 8;
#pragma unroll
            for (int j = 0; j < 4; j++) {
                int row = r0 + j * 32;
                CP_ASYNC16(stg + m * 16384 + off128(row, g0),
                           s + (size_t)row * GK);
            }
        }
        CP_COMMIT();
    };

    issue(0);
    issue(1);

    for (int c = 0; c < NCH2; c++) {
        CP_WAIT(1);
        __syncthreads();
        if (c + 2 < NCH2) issue(c + 2);
        else              CP_COMMIT();

        int st = c; while (st >= 3) st -= 3;
        const uint32_t stg = sb + (uint32_t)st * GSTAGE2;

#pragma unroll
        for (int ks = 0; ks < 4; ks++) {
            uint32_t ah[4][4], al[4][4], wh[2][4], wl[2][4];
#pragma unroll
            for (int mt = 0; mt < 4; mt++) {
                uint32_t off = (uint32_t)rowA[mt]
                             + (((uint32_t)((ks * 2 + gA) ^ xorA[mt])) << 4);
                LDSM_X4(ah[mt][0], ah[mt][1], ah[mt][2], ah[mt][3], stg + off);
                LDSM_X4(al[mt][0], al[mt][1], al[mt][2], al[mt][3], stg + 16384 + off);
            }
#pragma unroll
            for (int p = 0; p < 2; p++) {
                uint32_t off = (uint32_t)rowW[p]
                             + (((uint32_t)((ks * 2 + gW) ^ xorW[p])) << 4);
                LDSM_X4(wh[p][0], wh[p][1], wh[p][2], wh[p][3], stg + 32768 + off);
                LDSM_X4(wl[p][0], wl[p][1], wl[p][2], wl[p][3], stg + 49152 + off);
            }
#pragma unroll
            for (int mt = 0; mt < 4; mt++)
#pragma unroll
                for (int p = 0; p < 2; p++)
#pragma unroll
                    for (int j2 = 0; j2 < 2; j2++) {
                        int nt = 2 * p + j2;
                        MMA16816(acc[mt][nt], ah[mt][0], ah[mt][1], ah[mt][2], ah[mt][3],
                                 wh[p][2 * j2], wh[p][2 * j2 + 1]);
                        MMA16816(acc[mt][nt], ah[mt][0], ah[mt][1], ah[mt][2], ah[mt][3],
                                 wl[p][2 * j2], wl[p][2 * j2 + 1]);
                        MMA16816(acc[mt][nt], al[mt][0], al[mt][1], al[mt][2], al[mt][3],
                                 wh[p][2 * j2], wh[p][2 * j2 + 1]);
                    }
        }
    }

    const float* bias = gb.bias[z];
    const float  sc   = gb.sc[z];
#pragma unroll
    for (int mt = 0; mt < 4; mt++) {
        int r0g = bm + wm * 64 + mt * 16 + (lane >> 2);
#pragma unroll
        for (int nt = 0; nt < 4; nt++) {
            int cg = bn + wn * 32 + nt * 8 + (lane & 3) * 2;
            float2 bz = *(const float2*)(bias + cg);
            float2 v0 = make_float2((acc[mt][nt][0] + bz.x) * sc,
                                    (acc[mt][nt][1] + bz.y) * sc);
            float2 v1 = make_float2((acc[mt][nt][2] + bz.x) * sc,
                                    (acc[mt][nt][3] + bz.y) * sc);
            if (BF16OUT) {
                uint32_t hi, lo;
                split2(v0.x, v0.y, hi, lo);
                *(uint32_t*)(gb.ch[z] + (size_t)r0g * HID + cg) = hi;
                *(uint32_t*)(gb.cl[z] + (size_t)r0g * HID + cg) = lo;
                split2(v1.x, v1.y, hi, lo);
                *(uint32_t*)(gb.ch[z] + (size_t)(r0g + 8) * HID + cg) = hi;
                *(uint32_t*)(gb.cl[z] + (size_t)(r0g + 8) * HID + cg) = lo;
            } else {
                *(float2*)(gb.c32[z] + (size_t)r0g * HID + cg)       = v0;
                *(float2*)(gb.c32[z] + (size_t)(r0g + 8) * HID + cg) = v1;
            }
        }
    }
}

// ===========================================================================
// Split-KV flash attention. BQ=64, grid (32,16,4), 8 warps in 2 groups:
// group g = w>>2 processes KV tiles t = g, g+2, ... <= qb with private
// 2-stage cp.async buffers + named barriers; merge at the end.
// smem: Qh@0 Ql@8192; group stages @16384 + g*64KB + s*32KB
// (Kh,Kl,Vh,Vl 8KB each); masks @147456 (4 x 256B); exchange m/l/O @148480.
// ===========================================================================
#define XCH_M 148480
#define XCH_L 148736
#define XCH_O 148992
#define FLASH_SMEM 165376

__global__ void __launch_bounds__(256)
flash_sk(const __nv_bfloat16* __restrict__ Qhp, const __nv_bfloat16* __restrict__ Qlp,
         const __nv_bfloat16* __restrict__ Khp, const __nv_bfloat16* __restrict__ Klp,
         const __nv_bfloat16* __restrict__ Vhp, const __nv_bfloat16* __restrict__ Vlp,
         const float* __restrict__ maskg,
         __nv_bfloat16* __restrict__ Ahp, __nv_bfloat16* __restrict__ Alp)
{
    extern __shared__ __align__(128) uint8_t sbuf[];
    const uint32_t sb = smem_u32(sbuf);

    const int tid  = threadIdx.x;
    const int lane = tid & 31;
    const int w    = tid >> 5;
    const int lr   = lane & 7;
    const int ml   = lane >> 3;
    const int qb   = blockIdx.x;            // 0..31
    const int h    = blockIdx.y;
    const int b    = blockIdx.z;
    const int q0   = qb * 64;
    const size_t base = ((size_t)b * S_LEN) * HID + (size_t)h * DH;

    // ---- stage Q (hi@0, lo@8192) ----
#pragma unroll
    for (int j = 0; j < 4; j++) {
        int f = tid + j * 256;
        int term = f >> 9;
        int c = f & 511;
        int row = c >> 3, qq = c & 7;
        CP_ASYNC16(sb + (uint32_t)term * 8192 + off128(row, qq),
                   (term ? Qlp : Qhp) + base + (size_t)(q0 + row) * HID + qq * 8);
    }
    CP_COMMIT();
    CP_WAIT(0);
    __syncthreads();

    uint32_t qh[4][4], ql[4][4];
    {
        int row = (w & 3) * 16 + (ml & 1) * 8 + lr;
#pragma unroll
        for (int ks = 0; ks < 4; ks++) {
            uint32_t off = off128(row, ks * 2 + (ml >> 1));
            LDSM_X4(qh[ks][0], qh[ks][1], qh[ks][2], qh[ks][3], sb + off);
            LDSM_X4(ql[ks][0], ql[ks][1], ql[ks][2], ql[ks][3], sb + 8192 + off);
        }
    }

    const int g      = w >> 2;               // 0 or 1
    const int wg_tid = tid & 127;
    const int barid  = g + 1;

    auto issue_g = [&](int t) {
        if (t <= qb) {
            const int k0t = t * 64;
            const __nv_bfloat16* bs[4] = {
                Khp + base + (size_t)k0t * HID,
                Klp + base + (size_t)k0t * HID,
                Vhp + base + (size_t)k0t * HID,
                Vlp + base + (size_t)k0t * HID };
            const uint32_t stg = sb + 16384u + (uint32_t)g * 65536u
                               + (uint32_t)((t >> 1) & 1) * 32768u;
#pragma unroll
            for (int j = 0; j < 16; j++) {
                int f = wg_tid + j * 128;
                int m = f >> 9, row = (f >> 3) & 63, g0 = f & 7;
                CP_ASYNC16(stg + (uint32_t)m * 8192 + off128(row, g0),
                           bs[m] + (size_t)row * HID + g0 * 8);
            }
            if (wg_tid < 16)
                CP_ASYNC16(sb + 147456u + (uint32_t)(g * 2 + ((t >> 1) & 1)) * 256u
                               + wg_tid * 16,
                           maskg + (size_t)b * S_LEN + k0t + wg_tid * 4);
        }
        CP_COMMIT();
    };

    issue_g(g);
    issue_g(g + 2);

    float oacc[8][4];
#pragma unroll
    for (int ns = 0; ns < 8; ns++)
#pragma unroll
        for (int r = 0; r < 4; r++) oacc[ns][r] = 0.0f;
    float m0 = -INFINITY, m1 = -INFINITY, l0 = 0.0f, l1 = 0.0f;

    const int r0g  = q0 + (w & 3) * 16 + (lane >> 2);
    const int cloc = (lane & 3) * 2;

    for (int t = g; t <= qb; t += 2) {
        const int k0 = t * 64;
        CP_WAIT(1);
        BAR_G(barid);

        const uint32_t stg = sb + 16384u + (uint32_t)g * 65536u
                           + (uint32_t)((t >> 1) & 1) * 32768u;
        const uint32_t sKh = stg, sKl = stg + 8192;
        const uint32_t sVh = stg + 16384, sVl = stg + 24576;
        const float* smask = (const float*)(sbuf + 147456
                           + (g * 2 + ((t >> 1) & 1)) * 256);

        // ---- S = Q K^T (3-term split; Q is pre-scaled by 1/8) ----
        float sacc[8][4];
#pragma unroll
        for (int nt = 0; nt < 8; nt++)
#pragma unroll
            for (int r = 0; r < 4; r++) sacc[nt][r] = 0.0f;

#pragma unroll
        for (int ks = 0; ks < 4; ks++) {
            uint32_t kh[4][4], kl[4][4];
            int rowb = (ml >> 1) * 8 + lr;
            int u    = ks * 2 + (ml & 1);
#pragma unroll
            for (int gg = 0; gg < 4; gg++) {
                int row = gg * 16 + rowb;
                uint32_t off = off128(row, u);
                LDSM_X4(kh[gg][0], kh[gg][1], kh[gg][2], kh[gg][3], sKh + off);
                LDSM_X4(kl[gg][0], kl[gg][1], kl[gg][2], kl[gg][3], sKl + off);
            }
#pragma unroll
            for (int gg = 0; gg < 4; gg++)
#pragma unroll
                for (int j2 = 0; j2 < 2; j2++)
                    MMA16816(sacc[2 * gg + j2], qh[ks][0], qh[ks][1], qh[ks][2], qh[ks][3],
                             kh[gg][2 * j2], kh[gg][2 * j2 + 1]);
#pragma unroll
            for (int gg = 0; gg < 4; gg++)
#pragma unroll
                for (int j2 = 0; j2 < 2; j2++)
                    MMA16816(sacc[2 * gg + j2], qh[ks][0], qh[ks][1], qh[ks][2], qh[ks][3],
                             kl[gg][2 * j2], kl[gg][2 * j2 + 1]);
#pragma unroll
            for (int gg = 0; gg < 4; gg++)
#pragma unroll
                for (int j2 = 0; j2 < 2; j2++)
                    MMA16816(sacc[2 * gg + j2], ql[ks][0], ql[ks][1], ql[ks][2], ql[ks][3],
                             kh[gg][2 * j2], kh[gg][2 * j2 + 1]);
        }

        // ---- mask (+ causal only on diagonal tile) + online softmax ----
        float rm0 = -INFINITY, rm1 = -INFINITY;
        if (t == qb) {
#pragma unroll
            for (int nt = 0; nt < 8; nt++) {
                int c0 = nt * 8 + cloc;
                float mk0 = smask[c0], mk1 = smask[c0 + 1];
                int jg0 = k0 + c0, jg1 = jg0 + 1;
                sacc[nt][0] = (jg0 > r0g     || mk0 == 0.0f) ? FILLV : sacc[nt][0];
                sacc[nt][1] = (jg1 > r0g     || mk1 == 0.0f) ? FILLV : sacc[nt][1];
                sacc[nt][2] = (jg0 > r0g + 8 || mk0 == 0.0f) ? FILLV : sacc[nt][2];
                sacc[nt][3] = (jg1 > r0g + 8 || mk1 == 0.0f) ? FILLV : sacc[nt][3];
                rm0 = fmaxf(rm0, fmaxf(sacc[nt][0], sacc[nt][1]));
                rm1 = fmaxf(rm1, fmaxf(sacc[nt][2], sacc[nt][3]));
            }
        } else {
#pragma unroll
            for (int nt = 0; nt < 8; nt++) {
                int c0 = nt * 8 + cloc;
                float mk0 = smask[c0], mk1 = smask[c0 + 1];
                sacc[nt][0] = (mk0 == 0.0f) ? FILLV : sacc[nt][0];
                sacc[nt][1] = (mk1 == 0.0f) ? FILLV : sacc[nt][1];
                sacc[nt][2] = (mk0 == 0.0f) ? FILLV : sacc[nt][2];
                sacc[nt][3] = (mk1 == 0.0f) ? FILLV : sacc[nt][3];
                rm0 = fmaxf(rm0, fmaxf(sacc[nt][0], sacc[nt][1]));
                rm1 = fmaxf(rm1, fmaxf(sacc[nt][2], sacc[nt][3]));
            }
        }
        rm0 = fmaxf(rm0, __shfl_xor_sync(0xffffffffu, rm0, 1));
        rm0 = fmaxf(rm0, __shfl_xor_sync(0xffffffffu, rm0, 2));
        rm1 = fmaxf(rm1, __shfl_xor_sync(0xffffffffu, rm1, 1));
        rm1 = fmaxf(rm1, __shfl_xor_sync(0xffffffffu, rm1, 2));

        float mn0 = fmaxf(m0, rm0), mn1 = fmaxf(m1, rm1);
        float corr0 = __expf(m0 - mn0), corr1 = __expf(m1 - mn1);
        m0 = mn0; m1 = mn1;

        float rs0 = 0.0f, rs1 = 0.0f;
#pragma unroll
        for (int nt = 0; nt < 8; nt++) {
            sacc[nt][0] = __expf(sacc[nt][0] - mn0);
            sacc[nt][1] = __expf(sacc[nt][1] - mn0);
            sacc[nt][2] = __expf(sacc[nt][2] - mn1);
            sacc[nt][3] = __expf(sacc[nt][3] - mn1);
            rs0 += sacc[nt][0] + sacc[nt][1];
            rs1 += sacc[nt][2] + sacc[nt][3];
        }
        rs0 += __shfl_xor_sync(0xffffffffu, rs0, 1);
        rs0 += __shfl_xor_sync(0xffffffffu, rs0, 2);
        rs1 += __shfl_xor_sync(0xffffffffu, rs1, 1);
        rs1 += __shfl_xor_sync(0xffffffffu, rs1, 2);
        l0 = l0 * corr0 + rs0;
        l1 = l1 * corr1 + rs1;
#pragma unroll
        for (int ns = 0; ns < 8; ns++) {
            oacc[ns][0] *= corr0; oacc[ns][1] *= corr0;
            oacc[ns][2] *= corr1; oacc[ns][3] *= corr1;
        }

        // ---- O += P V (3-term split) ----
#pragma unroll
        for (int ks = 0; ks < 4; ks++) {
            uint32_t ph[4], pl[4];
            split2t(sacc[2 * ks][0],     sacc[2 * ks][1],     ph[0], pl[0]);
            split2t(sacc[2 * ks][2],     sacc[2 * ks][3],     ph[1], pl[1]);
            split2t(sacc[2 * ks + 1][0], sacc[2 * ks + 1][1], ph[2], pl[2]);
            split2t(sacc[2 * ks + 1][2], sacc[2 * ks + 1][3], ph[3], pl[3]);

            int rowv = ks * 16 + (ml & 1) * 8 + lr;
#pragma unroll
            for (int np = 0; np < 4; np++) {
                int u = np * 2 + (ml >> 1);
                uint32_t off = off128(rowv, u);
                uint32_t vh[4], vl[4];
                LDSM_X4_T(vh[0], vh[1], vh[2], vh[3], sVh + off);
                LDSM_X4_T(vl[0], vl[1], vl[2], vl[3], sVl + off);
                MMA16816(oacc[2 * np],     ph[0], ph[1], ph[2], ph[3], vh[0], vh[1]);
                MMA16816(oacc[2 * np + 1], ph[0], ph[1], ph[2], ph[3], vh[2], vh[3]);
                MMA16816(oacc[2 * np],     ph[0], ph[1], ph[2], ph[3], vl[0], vl[1]);
                MMA16816(oacc[2 * np + 1], ph[0], ph[1], ph[2], ph[3], vl[2], vl[3]);
                MMA16816(oacc[2 * np],     pl[0], pl[1], pl[2], pl[3], vh[0], vh[1]);
                MMA16816(oacc[2 * np + 1], pl[0], pl[1], pl[2], pl[3], vh[2], vh[3]);
            }
        }

        BAR_G(barid);
        issue_g(t + 4);
    }

    // ---- merge: group B publishes, group A combines + writes ----
    float* XM = (float*)(sbuf + XCH_M);
    float* XL = (float*)(sbuf + XCH_L);
    float* XO = (float*)(sbuf + XCH_O);
    const int rl = (w & 3) * 16 + (lane >> 2);

    if (g == 1) {
        if ((lane & 3) == 0) {
            XM[rl] = m0; XM[rl + 8] = m1;
            XL[rl] = l0; XL[rl + 8] = l1;
        }
#pragma unroll
        for (int ns = 0; ns < 8; ns++) {
            int col = ns * 8 + cloc;
            *(float2*)&XO[rl * 64 + col]       = make_float2(oacc[ns][0], oacc[ns][1]);
            *(float2*)&XO[(rl + 8) * 64 + col] = make_float2(oacc[ns][2], oacc[ns][3]);
        }
    }
    __syncthreads();
    if (g == 0) {
        float mB0 = XM[rl], mB1 = XM[rl + 8];
        float lB0 = XL[rl], lB1 = XL[rl + 8];
        float mm0 = fmaxf(m0, mB0), mm1 = fmaxf(m1, mB1);
        float a0 = __expf(m0 - mm0), b0f = __expf(mB0 - mm0);
        float a1 = __expf(m1 - mm1), b1f = __expf(mB1 - mm1);
        float li0 = 1.0f / (l0 * a0 + lB0 * b0f);
        float li1 = 1.0f / (l1 * a1 + lB1 * b1f);
#pragma unroll
        for (int ns = 0; ns < 8; ns++) {
            int col = ns * 8 + cloc;
            float2 ob0 = *(const float2*)&XO[rl * 64 + col];
            float2 ob1 = *(const float2*)&XO[(rl + 8) * 64 + col];
            float o00 = (oacc[ns][0] * a0 + ob0.x * b0f) * li0;
            float o01 = (oacc[ns][1] * a0 + ob0.y * b0f) * li0;
            float o10 = (oacc[ns][2] * a1 + ob1.x * b1f) * li1;
            float o11 = (oacc[ns][3] * a1 + ob1.y * b1f) * li1;
            uint32_t hi, lo;
            split2(o00, o01, hi, lo);
            *(uint32_t*)(Ahp + base + (size_t)(q0 + rl) * HID + col) = hi;
            *(uint32_t*)(Alp + base + (size_t)(q0 + rl) * HID + col) = lo;
            split2(o10, o11, hi, lo);
            *(uint32_t*)(Ahp + base + (size_t)(q0 + rl + 8) * HID + col) = hi;
            *(uint32_t*)(Alp + base + (size_t)(q0 + rl + 8) * HID + col) = lo;
        }
    }
}

// ---------------------------------------------------------------------------
extern "C" void kernel_launch(void* const* d_in, const int* in_sizes, int n_in,
                              void* d_out, int out_size)
{
    const float* q    = (const float*)d_in[0];
    const float* k    = (const float*)d_in[1];
    const float* v    = (const float*)d_in[2];
    const float* mask = (const float*)d_in[3];
    const float* Wq   = (const float*)d_in[4];
    const float* bq   = (const float*)d_in[5];
    const float* Wk   = (const float*)d_in[6];
    const float* bk   = (const float*)d_in[7];
    const float* Wv   = (const float*)d_in[8];
    const float* bv   = (const float*)d_in[9];
    const float* Wo   = (const float*)d_in[10];
    const float* bo   = (const float*)d_in[11];
    float* out = (float*)d_out;

    __nv_bfloat16 *xqh, *xql, *xkh, *xkl, *xvh, *xvl;
    __nv_bfloat16 *wqh, *wql, *wkh, *wkl, *wvh, *wvl, *woh, *wol;
    __nv_bfloat16 *Qh, *Ql, *Kh, *Kl, *Vh, *Vl, *Ah, *Al;
    cudaGetSymbolAddress((void**)&xqh, g_xqh); cudaGetSymbolAddress((void**)&xql, g_xql);
    cudaGetSymbolAddress((void**)&xkh, g_xkh); cudaGetSymbolAddress((void**)&xkl, g_xkl);
    cudaGetSymbolAddress((void**)&xvh, g_xvh); cudaGetSymbolAddress((void**)&xvl, g_xvl);
    cudaGetSymbolAddress((void**)&wqh, g_wqh); cudaGetSymbolAddress((void**)&wql, g_wql);
    cudaGetSymbolAddress((void**)&wkh, g_wkh); cudaGetSymbolAddress((void**)&wkl, g_wkl);
    cudaGetSymbolAddress((void**)&wvh, g_wvh); cudaGetSymbolAddress((void**)&wvl, g_wvl);
    cudaGetSymbolAddress((void**)&woh, g_woh); cudaGetSymbolAddress((void**)&wol, g_wol);
    cudaGetSymbolAddress((void**)&Qh,  g_Qh);  cudaGetSymbolAddress((void**)&Ql,  g_Ql);
    cudaGetSymbolAddress((void**)&Kh,  g_Kh);  cudaGetSymbolAddress((void**)&Kl,  g_Kl);
    cudaGetSymbolAddress((void**)&Vh,  g_Vh);  cudaGetSymbolAddress((void**)&Vl,  g_Vl);
    cudaGetSymbolAddress((void**)&Ah,  g_Ah);  cudaGetSymbolAddress((void**)&Al,  g_Al);

    cudaFuncSetAttribute(flash_sk, cudaFuncAttributeMaxDynamicSharedMemorySize,
                         FLASH_SMEM);
    cudaFuncSetAttribute(gemm_bf2<true>,  cudaFuncAttributeMaxDynamicSharedMemorySize,
                         GEMM_SMEM2);
    cudaFuncSetAttribute(gemm_bf2<false>, cudaFuncAttributeMaxDynamicSharedMemorySize,
                         GEMM_SMEM2);

    const int n4x = M_TOT * HID / 4;
    const int n4w = HID * HID / 4;

    SplitBatch sbt;
    sbt.src[0] = q;  sbt.dh[0] = xqh; sbt.dl[0] = xql; sbt.n4[0] = n4x;
    sbt.src[1] = k;  sbt.dh[1] = xkh; sbt.dl[1] = xkl; sbt.n4[1] = n4x;
    sbt.src[2] = v;  sbt.dh[2] = xvh; sbt.dl[2] = xvl; sbt.n4[2] = n4x;
    sbt.src[3] = Wq; sbt.dh[3] = wqh; sbt.dl[3] = wql; sbt.n4[3] = n4w;
    sbt.src[4] = Wk; sbt.dh[4] = wkh; sbt.dl[4] = wkl; sbt.n4[4] = n4w;
    sbt.src[5] = Wv; sbt.dh[5] = wvh; sbt.dl[5] = wvl; sbt.n4[5] = n4w;
    sbt.src[6] = Wo; sbt.dh[6] = woh; sbt.dl[6] = wol; sbt.n4[6] = n4w;
    split_all<<<dim3(n4x / 256, 7), 256>>>(sbt);

    GemmBatch gqkv = {};
    gqkv.ah[0] = xqh; gqkv.al[0] = xql; gqkv.wh[0] = wqh; gqkv.wl[0] = wql;
    gqkv.bias[0] = bq; gqkv.ch[0] = Qh; gqkv.cl[0] = Ql; gqkv.sc[0] = 0.125f;
    gqkv.ah[1] = xkh; gqkv.al[1] = xkl; gqkv.wh[1] = wkh; gqkv.wl[1] = wkl;
    gqkv.bias[1] = bk; gqkv.ch[1] = Kh; gqkv.cl[1] = Kl; gqkv.sc[1] = 1.0f;
    gqkv.ah[2] = xvh; gqkv.al[2] = xvl; gqkv.wh[2] = wvh; gqkv.wl[2] = wvl;
    gqkv.bias[2] = bv; gqkv.ch[2] = Vh; gqkv.cl[2] = Vl; gqkv.sc[2] = 1.0f;
    gemm_bf2<true><<<dim3(HID / 128, M_TOT / 128, 3), 256, GEMM_SMEM2>>>(gqkv);

    flash_sk<<<dim3(S_LEN / 64, NH, BATCH), 256, FLASH_SMEM>>>(
        Qh, Ql, Kh, Kl, Vh, Vl, mask, Ah, Al);

    GemmBatch gout = {};
    gout.ah[0] = Ah; gout.al[0] = Al; gout.wh[0] = woh; gout.wl[0] = wol;
    gout.bias[0] = bo; gout.c32[0] = out; gout.sc[0] = 1.0f;
    gemm_bf2<false><<<dim3(HID / 128, M_TOT / 128, 1), 256, GEMM_SMEM2>>>(gout);
}

// round 9
// speedup vs baseline: 2.8876x; 1.0098x over previous
#include <cuda_runtime.h>
#include <cuda_bf16.h>
#include <cstdint>
#include <math.h>

#define S_LEN 2048
#define BATCH 4
#define HID   1024
#define NH    16
#define DH    64
#define M_TOT (BATCH * S_LEN)      // 8192
#define FILLV (-10000000000000.0f)

// Scratch (device globals: no allocations allowed)
__device__ __nv_bfloat16 g_xqh[M_TOT * HID], g_xql[M_TOT * HID];
__device__ __nv_bfloat16 g_xkh[M_TOT * HID], g_xkl[M_TOT * HID];
__device__ __nv_bfloat16 g_xvh[M_TOT * HID], g_xvl[M_TOT * HID];
__device__ __nv_bfloat16 g_wqh[HID * HID], g_wql[HID * HID];
__device__ __nv_bfloat16 g_wkh[HID * HID], g_wkl[HID * HID];
__device__ __nv_bfloat16 g_wvh[HID * HID], g_wvl[HID * HID];
__device__ __nv_bfloat16 g_woh[HID * HID], g_wol[HID * HID];
__device__ __nv_bfloat16 g_Qh[M_TOT * HID], g_Ql[M_TOT * HID];
__device__ __nv_bfloat16 g_Kh[M_TOT * HID], g_Kl[M_TOT * HID];
__device__ __nv_bfloat16 g_Vh[M_TOT * HID], g_Vl[M_TOT * HID];
__device__ __nv_bfloat16 g_Ah[M_TOT * HID], g_Al[M_TOT * HID];

// ===========================================================================
// helpers
// ===========================================================================
__device__ __forceinline__ uint32_t smem_u32(const void* p) {
    uint32_t a;
    asm("{ .reg .u64 t; cvta.to.shared.u64 t, %1; cvt.u32.u64 %0, t; }"
        : "=r"(a) : "l"(p));
    return a;
}

#define LDSM_X4(r0, r1, r2, r3, addr)                                         \
    asm volatile("ldmatrix.sync.aligned.m8n8.x4.shared.b16 {%0,%1,%2,%3}, [%4];" \
                 : "=r"(r0), "=r"(r1), "=r"(r2), "=r"(r3) : "r"(addr))

#define LDSM_X4_T(r0, r1, r2, r3, addr)                                       \
    asm volatile("ldmatrix.sync.aligned.m8n8.x4.trans.shared.b16 {%0,%1,%2,%3}, [%4];" \
                 : "=r"(r0), "=r"(r1), "=r"(r2), "=r"(r3) : "r"(addr))

#define MMA16816(d, a0, a1, a2, a3, b0, b1)                                   \
    asm volatile("mma.sync.aligned.m16n8k16.row.col.f32.bf16.bf16.f32 "       \
                 "{%0,%1,%2,%3}, {%4,%5,%6,%7}, {%8,%9}, {%0,%1,%2,%3};"      \
                 : "+f"((d)[0]), "+f"((d)[1]), "+f"((d)[2]), "+f"((d)[3])     \
                 : "r"(a0), "r"(a1), "r"(a2), "r"(a3), "r"(b0), "r"(b1))

#define CP_ASYNC16(dst, src)                                                  \
    asm volatile("cp.async.cg.shared.global [%0], [%1], 16;"                  \
                 :: "r"(dst), "l"(src) : "memory")
#define CP_COMMIT() asm volatile("cp.async.commit_group;" ::: "memory")
#define CP_WAIT(n)  asm volatile("cp.async.wait_group %0;" :: "n"(n) : "memory")

#define BAR_G(id) asm volatile("bar.sync %0, %1;" :: "r"(id), "r"(128) : "memory")

__device__ __forceinline__ uint32_t pack_bf2(float x, float y) {
    __nv_bfloat16 bx = __float2bfloat16_rn(x);
    __nv_bfloat16 by = __float2bfloat16_rn(y);
    return (uint32_t)__bfloat16_as_ushort(bx)
         | ((uint32_t)__bfloat16_as_ushort(by) << 16);
}

__device__ __forceinline__ void split4(const float4& v, uint2& hi, uint2& lo) {
    __nv_bfloat16 h0 = __float2bfloat16_rn(v.x);
    __nv_bfloat16 h1 = __float2bfloat16_rn(v.y);
    __nv_bfloat16 h2 = __float2bfloat16_rn(v.z);
    __nv_bfloat16 h3 = __float2bfloat16_rn(v.w);
    float l0 = v.x - __bfloat162float(h0);
    float l1 = v.y - __bfloat162float(h1);
    float l2 = v.z - __bfloat162float(h2);
    float l3 = v.w - __bfloat162float(h3);
    hi.x = (uint32_t)__bfloat16_as_ushort(h0)
         | ((uint32_t)__bfloat16_as_ushort(h1) << 16);
    hi.y = (uint32_t)__bfloat16_as_ushort(h2)
         | ((uint32_t)__bfloat16_as_ushort(h3) << 16);
    lo.x = pack_bf2(l0, l1);
    lo.y = pack_bf2(l2, l3);
}

__device__ __forceinline__ void split2(float x, float y, uint32_t& hi, uint32_t& lo) {
    __nv_bfloat16 hx = __float2bfloat16_rn(x);
    __nv_bfloat16 hy = __float2bfloat16_rn(y);
    hi = (uint32_t)__bfloat16_as_ushort(hx)
       | ((uint32_t)__bfloat16_as_ushort(hy) << 16);
    lo = pack_bf2(x - __bfloat162float(hx), y - __bfloat162float(hy));
}

// fast truncation split for P (positive values)
__device__ __forceinline__ void split2t(float x, float y, uint32_t& hi, uint32_t& lo) {
    uint32_t ux = __float_as_uint(x), uy = __float_as_uint(y);
    hi = __byte_perm(ux, uy, 0x7632);
    float lx = x - __uint_as_float(ux & 0xffff0000u);
    float ly = y - __uint_as_float(uy & 0xffff0000u);
    asm("cvt.rn.bf16x2.f32 %0, %1, %2;" : "=r"(lo) : "f"(ly), "f"(lx));
}

// 128-byte-row XOR swizzle
__device__ __forceinline__ uint32_t off128(int row, int u) {
    return (uint32_t)(row * 128 + (((u ^ (row & 7))) << 4));
}

// ===========================================================================
// fused split pass
// ===========================================================================
struct SplitBatch {
    const float*   src[7];
    __nv_bfloat16* dh[7];
    __nv_bfloat16* dl[7];
    int            n4[7];
};

__global__ void __launch_bounds__(256)
split_all(SplitBatch s)
{
    const int t = blockIdx.y;
    const int i = blockIdx.x * 256 + threadIdx.x;
    if (i < s.n4[t]) {
        float4 v = ((const float4*)s.src[t])[i];
        uint2 hi, lo;
        split4(v, hi, lo);
        ((uint2*)s.dh[t])[i] = hi;
        ((uint2*)s.dl[t])[i] = lo;
    }
}

// ===========================================================================
// GEMM: BK=64, 3-stage cp.async, batched over blockIdx.z.
// Round-9 change: MMA emission is TERM-MAJOR (all hh, then hl, then lh) so
// same-accumulator reuse distance is 16 MMAs instead of 1. Accumulation
// order per acc is unchanged (hh -> hl -> lh) => bit-identical results.
// ===========================================================================
#define GK 1024
#define NCH2 16
#define GSTAGE2 65536
#define GEMM_SMEM2 (3 * GSTAGE2)

struct GemmBatch {
    const __nv_bfloat16* ah[3];
    const __nv_bfloat16* al[3];
    const __nv_bfloat16* wh[3];
    const __nv_bfloat16* wl[3];
    const float*         bias[3];
    __nv_bfloat16*       ch[3];
    __nv_bfloat16*       cl[3];
    float*               c32[3];
    float                sc[3];
};

template<bool BF16OUT>
__global__ void __launch_bounds__(256)
gemm_bf2(GemmBatch gb)
{
    extern __shared__ __align__(128) uint8_t smg[];
    const uint32_t sb = smem_u32(smg);
    const int tid  = threadIdx.x;
    const int lane = tid & 31;
    const int warp = tid >> 5;
    const int wm   = warp >> 2;
    const int wn   = warp & 3;
    const int bm   = blockIdx.y * 128;
    const int bn   = blockIdx.x * 128;
    const int z    = blockIdx.z;
    const int lr   = lane & 7;
    const int ml   = lane >> 3;

    const __nv_bfloat16* srcs[4] = {
        gb.ah[z] + (size_t)bm * GK, gb.al[z] + (size_t)bm * GK,
        gb.wh[z] + (size_t)bn * GK, gb.wl[z] + (size_t)bn * GK };

    const int r0 = tid >> 3, g0 = tid & 7;

    int rowA[4], xorA[4];
#pragma unroll
    for (int mt = 0; mt < 4; mt++) {
        int row = wm * 64 + mt * 16 + (ml & 1) * 8 + lr;
        rowA[mt] = row * 128;
        xorA[mt] = row & 7;
    }
    int rowW[2], xorW[2];
#pragma unroll
    for (int p = 0; p < 2; p++) {
        int row = wn * 32 + p * 16 + (ml >> 1) * 8 + lr;
        rowW[p] = row * 128;
        xorW[p] = row & 7;
    }
    const int gA = ml >> 1;
    const int gW = ml & 1;

    float acc[4][4][4];
#pragma unroll
    for (int mt = 0; mt < 4; mt++)
#pragma unroll
        for (int nt = 0; nt < 4; nt++)
#pragma unroll
            for (int r = 0; r < 4; r++) acc[mt][nt][r] = 0.0f;

    auto issue = [&](int t) {
        int st = t; while (st >= 3) st -= 3;
        const uint32_t stg = sb + (uint32_t)st * GSTAGE2;
        const int kc = t * 64;
#pragma unroll
        for (int m = 0; m < 4; m++) {
            const __nv_bfloat16* s = srcs[m] + kc + g0 * 8;
#pragma unroll
            for (int j = 0; j < 4; j++) {
                int row = r0 + j * 32;
                CP_ASYNC16(stg + m * 16384 + off128(row, g0),
                           s + (size_t)row * GK);
            }
        }
        CP_COMMIT();
    };

    issue(0);
    issue(1);

    for (int c = 0; c < NCH2; c++) {
        CP_WAIT(1);
        __syncthreads();
        if (c + 2 < NCH2) issue(c + 2);
        else              CP_COMMIT();

        int st = c; while (st >= 3) st -= 3;
        const uint32_t stg = sb + (uint32_t)st * GSTAGE2;

#pragma unroll
        for (int ks = 0; ks < 4; ks++) {
            uint32_t ah[4][4], al[4][4], wh[2][4], wl[2][4];
#pragma unroll
            for (int mt = 0; mt < 4; mt++) {
                uint32_t off = (uint32_t)rowA[mt]
                             + (((uint32_t)((ks * 2 + gA) ^ xorA[mt])) << 4);
                LDSM_X4(ah[mt][0], ah[mt][1], ah[mt][2], ah[mt][3], stg + off);
                LDSM_X4(al[mt][0], al[mt][1], al[mt][2], al[mt][3], stg + 16384 + off);
            }
#pragma unroll
            for (int p = 0; p < 2; p++) {
                uint32_t off = (uint32_t)rowW[p]
                             + (((uint32_t)((ks * 2 + gW) ^ xorW[p])) << 4);
                LDSM_X4(wh[p][0], wh[p][1], wh[p][2], wh[p][3], stg + 32768 + off);
                LDSM_X4(wl[p][0], wl[p][1], wl[p][2], wl[p][3], stg + 49152 + off);
            }
            // term-major passes: 16 independent accs between same-acc reuses
#pragma unroll
            for (int mt = 0; mt < 4; mt++)
#pragma unroll
                for (int p = 0; p < 2; p++)
#pragma unroll
                    for (int j2 = 0; j2 < 2; j2++)
                        MMA16816(acc[mt][2 * p + j2],
                                 ah[mt][0], ah[mt][1], ah[mt][2], ah[mt][3],
                                 wh[p][2 * j2], wh[p][2 * j2 + 1]);
#pragma unroll
            for (int mt = 0; mt < 4; mt++)
#pragma unroll
                for (int p = 0; p < 2; p++)
#pragma unroll
                    for (int j2 = 0; j2 < 2; j2++)
                        MMA16816(acc[mt][2 * p + j2],
                                 ah[mt][0], ah[mt][1], ah[mt][2], ah[mt][3],
                                 wl[p][2 * j2], wl[p][2 * j2 + 1]);
#pragma unroll
            for (int mt = 0; mt < 4; mt++)
#pragma unroll
                for (int p = 0; p < 2; p++)
#pragma unroll
                    for (int j2 = 0; j2 < 2; j2++)
                        MMA16816(acc[mt][2 * p + j2],
                                 al[mt][0], al[mt][1], al[mt][2], al[mt][3],
                                 wh[p][2 * j2], wh[p][2 * j2 + 1]);
        }
    }

    const float* bias = gb.bias[z];
    const float  sc   = gb.sc[z];
#pragma unroll
    for (int mt = 0; mt < 4; mt++) {
        int r0g = bm + wm * 64 + mt * 16 + (lane >> 2);
#pragma unroll
        for (int nt = 0; nt < 4; nt++) {
            int cg = bn + wn * 32 + nt * 8 + (lane & 3) * 2;
            float2 bz = *(const float2*)(bias + cg);
            float2 v0 = make_float2((acc[mt][nt][0] + bz.x) * sc,
                                    (acc[mt][nt][1] + bz.y) * sc);
            float2 v1 = make_float2((acc[mt][nt][2] + bz.x) * sc,
                                    (acc[mt][nt][3] + bz.y) * sc);
            if (BF16OUT) {
                uint32_t hi, lo;
                split2(v0.x, v0.y, hi, lo);
                *(uint32_t*)(gb.ch[z] + (size_t)r0g * HID + cg) = hi;
                *(uint32_t*)(gb.cl[z] + (size_t)r0g * HID + cg) = lo;
                split2(v1.x, v1.y, hi, lo);
                *(uint32_t*)(gb.ch[z] + (size_t)(r0g + 8) * HID + cg) = hi;
                *(uint32_t*)(gb.cl[z] + (size_t)(r0g + 8) * HID + cg) = lo;
            } else {
                *(float2*)(gb.c32[z] + (size_t)r0g * HID + cg)       = v0;
                *(float2*)(gb.c32[z] + (size_t)(r0g + 8) * HID + cg) = v1;
            }
        }
    }
}

// ===========================================================================
// Split-KV flash attention (round-8 verified). Round-9: qb reversed so
// longest CTAs launch first (better tail packing on the causal triangle).
// ===========================================================================
#define XCH_M 148480
#define XCH_L 148736
#define XCH_O 148992
#define FLASH_SMEM 165376

__global__ void __launch_bounds__(256)
flash_sk(const __nv_bfloat16* __restrict__ Qhp, const __nv_bfloat16* __restrict__ Qlp,
         const __nv_bfloat16* __restrict__ Khp, const __nv_bfloat16* __restrict__ Klp,
         const __nv_bfloat16* __restrict__ Vhp, const __nv_bfloat16* __restrict__ Vlp,
         const float* __restrict__ maskg,
         __nv_bfloat16* __restrict__ Ahp, __nv_bfloat16* __restrict__ Alp)
{
    extern __shared__ __align__(128) uint8_t sbuf[];
    const uint32_t sb = smem_u32(sbuf);

    const int tid  = threadIdx.x;
    const int lane = tid & 31;
    const int w    = tid >> 5;
    const int lr   = lane & 7;
    const int ml   = lane >> 3;
    const int qb   = (int)gridDim.x - 1 - (int)blockIdx.x;   // long CTAs first
    const int h    = blockIdx.y;
    const int b    = blockIdx.z;
    const int q0   = qb * 64;
    const size_t base = ((size_t)b * S_LEN) * HID + (size_t)h * DH;

    // ---- stage Q (hi@0, lo@8192) ----
#pragma unroll
    for (int j = 0; j < 4; j++) {
        int f = tid + j * 256;
        int term = f >> 9;
        int c = f & 511;
        int row = c >> 3, qq = c & 7;
        CP_ASYNC16(sb + (uint32_t)term * 8192 + off128(row, qq),
                   (term ? Qlp : Qhp) + base + (size_t)(q0 + row) * HID + qq * 8);
    }
    CP_COMMIT();
    CP_WAIT(0);
    __syncthreads();

    uint32_t qh[4][4], ql[4][4];
    {
        int row = (w & 3) * 16 + (ml & 1) * 8 + lr;
#pragma unroll
        for (int ks = 0; ks < 4; ks++) {
            uint32_t off = off128(row, ks * 2 + (ml >> 1));
            LDSM_X4(qh[ks][0], qh[ks][1], qh[ks][2], qh[ks][3], sb + off);
            LDSM_X4(ql[ks][0], ql[ks][1], ql[ks][2], ql[ks][3], sb + 8192 + off);
        }
    }

    const int g      = w >> 2;
    const int wg_tid = tid & 127;
    const int barid  = g + 1;

    auto issue_g = [&](int t) {
        if (t <= qb) {
            const int k0t = t * 64;
            const __nv_bfloat16* bs[4] = {
                Khp + base + (size_t)k0t * HID,
                Klp + base + (size_t)k0t * HID,
                Vhp + base + (size_t)k0t * HID,
                Vlp + base + (size_t)k0t * HID };
            const uint32_t stg = sb + 16384u + (uint32_t)g * 65536u
                               + (uint32_t)((t >> 1) & 1) * 32768u;
#pragma unroll
            for (int j = 0; j < 16; j++) {
                int f = wg_tid + j * 128;
                int m = f >> 9, row = (f >> 3) & 63, g0 = f & 7;
                CP_ASYNC16(stg + (uint32_t)m * 8192 + off128(row, g0),
                           bs[m] + (size_t)row * HID + g0 * 8);
            }
            if (wg_tid < 16)
                CP_ASYNC16(sb + 147456u + (uint32_t)(g * 2 + ((t >> 1) & 1)) * 256u
                               + wg_tid * 16,
                           maskg + (size_t)b * S_LEN + k0t + wg_tid * 4);
        }
        CP_COMMIT();
    };

    issue_g(g);
    issue_g(g + 2);

    float oacc[8][4];
#pragma unroll
    for (int ns = 0; ns < 8; ns++)
#pragma unroll
        for (int r = 0; r < 4; r++) oacc[ns][r] = 0.0f;
    float m0 = -INFINITY, m1 = -INFINITY, l0 = 0.0f, l1 = 0.0f;

    const int r0g  = q0 + (w & 3) * 16 + (lane >> 2);
    const int cloc = (lane & 3) * 2;

    for (int t = g; t <= qb; t += 2) {
        const int k0 = t * 64;
        CP_WAIT(1);
        BAR_G(barid);

        const uint32_t stg = sb + 16384u + (uint32_t)g * 65536u
                           + (uint32_t)((t >> 1) & 1) * 32768u;
        const uint32_t sKh = stg, sKl = stg + 8192;
        const uint32_t sVh = stg + 16384, sVl = stg + 24576;
        const float* smask = (const float*)(sbuf + 147456
                           + (g * 2 + ((t >> 1) & 1)) * 256);

        float sacc[8][4];
#pragma unroll
        for (int nt = 0; nt < 8; nt++)
#pragma unroll
            for (int r = 0; r < 4; r++) sacc[nt][r] = 0.0f;

#pragma unroll
        for (int ks = 0; ks < 4; ks++) {
            uint32_t kh[4][4], kl[4][4];
            int rowb = (ml >> 1) * 8 + lr;
            int u    = ks * 2 + (ml & 1);
#pragma unroll
            for (int gg = 0; gg < 4; gg++) {
                int row = gg * 16 + rowb;
                uint32_t off = off128(row, u);
                LDSM_X4(kh[gg][0], kh[gg][1], kh[gg][2], kh[gg][3], sKh + off);
                LDSM_X4(kl[gg][0], kl[gg][1], kl[gg][2], kl[gg][3], sKl + off);
            }
#pragma unroll
            for (int gg = 0; gg < 4; gg++)
#pragma unroll
                for (int j2 = 0; j2 < 2; j2++)
                    MMA16816(sacc[2 * gg + j2], qh[ks][0], qh[ks][1], qh[ks][2], qh[ks][3],
                             kh[gg][2 * j2], kh[gg][2 * j2 + 1]);
#pragma unroll
            for (int gg = 0; gg < 4; gg++)
#pragma unroll
                for (int j2 = 0; j2 < 2; j2++)
                    MMA16816(sacc[2 * gg + j2], qh[ks][0], qh[ks][1], qh[ks][2], qh[ks][3],
                             kl[gg][2 * j2], kl[gg][2 * j2 + 1]);
#pragma unroll
            for (int gg = 0; gg < 4; gg++)
#pragma unroll
                for (int j2 = 0; j2 < 2; j2++)
                    MMA16816(sacc[2 * gg + j2], ql[ks][0], ql[ks][1], ql[ks][2], ql[ks][3],
                             kh[gg][2 * j2], kh[gg][2 * j2 + 1]);
        }

        float rm0 = -INFINITY, rm1 = -INFINITY;
        if (t == qb) {
#pragma unroll
            for (int nt = 0; nt < 8; nt++) {
                int c0 = nt * 8 + cloc;
                float mk0 = smask[c0], mk1 = smask[c0 + 1];
                int jg0 = k0 + c0, jg1 = jg0 + 1;
                sacc[nt][0] = (jg0 > r0g     || mk0 == 0.0f) ? FILLV : sacc[nt][0];
                sacc[nt][1] = (jg1 > r0g     || mk1 == 0.0f) ? FILLV : sacc[nt][1];
                sacc[nt][2] = (jg0 > r0g + 8 || mk0 == 0.0f) ? FILLV : sacc[nt][2];
                sacc[nt][3] = (jg1 > r0g + 8 || mk1 == 0.0f) ? FILLV : sacc[nt][3];
                rm0 = fmaxf(rm0, fmaxf(sacc[nt][0], sacc[nt][1]));
                rm1 = fmaxf(rm1, fmaxf(sacc[nt][2], sacc[nt][3]));
            }
        } else {
#pragma unroll
            for (int nt = 0; nt < 8; nt++) {
                int c0 = nt * 8 + cloc;
                float mk0 = smask[c0], mk1 = smask[c0 + 1];
                sacc[nt][0] = (mk0 == 0.0f) ? FILLV : sacc[nt][0];
                sacc[nt][1] = (mk1 == 0.0f) ? FILLV : sacc[nt][1];
                sacc[nt][2] = (mk0 == 0.0f) ? FILLV : sacc[nt][2];
                sacc[nt][3] = (mk1 == 0.0f) ? FILLV : sacc[nt][3];
                rm0 = fmaxf(rm0, fmaxf(sacc[nt][0], sacc[nt][1]));
                rm1 = fmaxf(rm1, fmaxf(sacc[nt][2], sacc[nt][3]));
            }
        }
        rm0 = fmaxf(rm0, __shfl_xor_sync(0xffffffffu, rm0, 1));
        rm0 = fmaxf(rm0, __shfl_xor_sync(0xffffffffu, rm0, 2));
        rm1 = fmaxf(rm1, __shfl_xor_sync(0xffffffffu, rm1, 1));
        rm1 = fmaxf(rm1, __shfl_xor_sync(0xffffffffu, rm1, 2));

        float mn0 = fmaxf(m0, rm0), mn1 = fmaxf(m1, rm1);
        float corr0 = __expf(m0 - mn0), corr1 = __expf(m1 - mn1);
        m0 = mn0; m1 = mn1;

        float rs0 = 0.0f, rs1 = 0.0f;
#pragma unroll
        for (int nt = 0; nt < 8; nt++) {
            sacc[nt][0] = __expf(sacc[nt][0] - mn0);
            sacc[nt][1] = __expf(sacc[nt][1] - mn0);
            sacc[nt][2] = __expf(sacc[nt][2] - mn1);
            sacc[nt][3] = __expf(sacc[nt][3] - mn1);
            rs0 += sacc[nt][0] + sacc[nt][1];
            rs1 += sacc[nt][2] + sacc[nt][3];
        }
        rs0 += __shfl_xor_sync(0xffffffffu, rs0, 1);
        rs0 += __shfl_xor_sync(0xffffffffu, rs0, 2);
        rs1 += __shfl_xor_sync(0xffffffffu, rs1, 1);
        rs1 += __shfl_xor_sync(0xffffffffu, rs1, 2);
        l0 = l0 * corr0 + rs0;
        l1 = l1 * corr1 + rs1;
#pragma unroll
        for (int ns = 0; ns < 8; ns++) {
            oacc[ns][0] *= corr0; oacc[ns][1] *= corr0;
            oacc[ns][2] *= corr1; oacc[ns][3] *= corr1;
        }

#pragma unroll
        for (int ks = 0; ks < 4; ks++) {
            uint32_t ph[4], pl[4];
            split2t(sacc[2 * ks][0],     sacc[2 * ks][1],     ph[0], pl[0]);
            split2t(sacc[2 * ks][2],     sacc[2 * ks][3],     ph[1], pl[1]);
            split2t(sacc[2 * ks + 1][0], sacc[2 * ks + 1][1], ph[2], pl[2]);
            split2t(sacc[2 * ks + 1][2], sacc[2 * ks + 1][3], ph[3], pl[3]);

            int rowv = ks * 16 + (ml & 1) * 8 + lr;
#pragma unroll
            for (int np = 0; np < 4; np++) {
                int u = np * 2 + (ml >> 1);
                uint32_t off = off128(rowv, u);
                uint32_t vh[4], vl[4];
                LDSM_X4_T(vh[0], vh[1], vh[2], vh[3], sVh + off);
                LDSM_X4_T(vl[0], vl[1], vl[2], vl[3], sVl + off);
                MMA16816(oacc[2 * np],     ph[0], ph[1], ph[2], ph[3], vh[0], vh[1]);
                MMA16816(oacc[2 * np + 1], ph[0], ph[1], ph[2], ph[3], vh[2], vh[3]);
                MMA16816(oacc[2 * np],     ph[0], ph[1], ph[2], ph[3], vl[0], vl[1]);
                MMA16816(oacc[2 * np + 1], ph[0], ph[1], ph[2], ph[3], vl[2], vl[3]);
                MMA16816(oacc[2 * np],     pl[0], pl[1], pl[2], pl[3], vh[0], vh[1]);
                MMA16816(oacc[2 * np + 1], pl[0], pl[1], pl[2], pl[3], vh[2], vh[3]);
            }
        }

        BAR_G(barid);
        issue_g(t + 4);
    }

    // ---- merge: group B publishes, group A combines + writes ----
    float* XM = (float*)(sbuf + XCH_M);
    float* XL = (float*)(sbuf + XCH_L);
    float* XO = (float*)(sbuf + XCH_O);
    const int rl = (w & 3) * 16 + (lane >> 2);

    if (g == 1) {
        if ((lane & 3) == 0) {
            XM[rl] = m0; XM[rl + 8] = m1;
            XL[rl] = l0; XL[rl + 8] = l1;
        }
#pragma unroll
        for (int ns = 0; ns < 8; ns++) {
            int col = ns * 8 + cloc;
            *(float2*)&XO[rl * 64 + col]       = make_float2(oacc[ns][0], oacc[ns][1]);
            *(float2*)&XO[(rl + 8) * 64 + col] = make_float2(oacc[ns][2], oacc[ns][3]);
        }
    }
    __syncthreads();
    if (g == 0) {
        float mB0 = XM[rl], mB1 = XM[rl + 8];
        float lB0 = XL[rl], lB1 = XL[rl + 8];
        float mm0 = fmaxf(m0, mB0), mm1 = fmaxf(m1, mB1);
        float a0 = __expf(m0 - mm0), b0f = __expf(mB0 - mm0);
        float a1 = __expf(m1 - mm1), b1f = __expf(mB1 - mm1);
        float li0 = 1.0f / (l0 * a0 + lB0 * b0f);
        float li1 = 1.0f / (l1 * a1 + lB1 * b1f);
#pragma unroll
        for (int ns = 0; ns < 8; ns++) {
            int col = ns * 8 + cloc;
            float2 ob0 = *(const float2*)&XO[rl * 64 + col];
            float2 ob1 = *(const float2*)&XO[(rl + 8) * 64 + col];
            float o00 = (oacc[ns][0] * a0 + ob0.x * b0f) * li0;
            float o01 = (oacc[ns][1] * a0 + ob0.y * b0f) * li0;
            float o10 = (oacc[ns][2] * a1 + ob1.x * b1f) * li1;
            float o11 = (oacc[ns][3] * a1 + ob1.y * b1f) * li1;
            uint32_t hi, lo;
            split2(o00, o01, hi, lo);
            *(uint32_t*)(Ahp + base + (size_t)(q0 + rl) * HID + col) = hi;
            *(uint32_t*)(Alp + base + (size_t)(q0 + rl) * HID + col) = lo;
            split2(o10, o11, hi, lo);
            *(uint32_t*)(Ahp + base + (size_t)(q0 + rl + 8) * HID + col) = hi;
            *(uint32_t*)(Alp + base + (size_t)(q0 + rl + 8) * HID + col) = lo;
        }
    }
}

// ---------------------------------------------------------------------------
extern "C" void kernel_launch(void* const* d_in, const int* in_sizes, int n_in,
                              void* d_out, int out_size)
{
    const float* q    = (const float*)d_in[0];
    const float* k    = (const float*)d_in[1];
    const float* v    = (const float*)d_in[2];
    const float* mask = (const float*)d_in[3];
    const float* Wq   = (const float*)d_in[4];
    const float* bq   = (const float*)d_in[5];
    const float* Wk   = (const float*)d_in[6];
    const float* bk   = (const float*)d_in[7];
    const float* Wv   = (const float*)d_in[8];
    const float* bv   = (const float*)d_in[9];
    const float* Wo   = (const float*)d_in[10];
    const float* bo   = (const float*)d_in[11];
    float* out = (float*)d_out;

    __nv_bfloat16 *xqh, *xql, *xkh, *xkl, *xvh, *xvl;
    __nv_bfloat16 *wqh, *wql, *wkh, *wkl, *wvh, *wvl, *woh, *wol;
    __nv_bfloat16 *Qh, *Ql, *Kh, *Kl, *Vh, *Vl, *Ah, *Al;
    cudaGetSymbolAddress((void**)&xqh, g_xqh); cudaGetSymbolAddress((void**)&xql, g_xql);
    cudaGetSymbolAddress((void**)&xkh, g_xkh); cudaGetSymbolAddress((void**)&xkl, g_xkl);
    cudaGetSymbolAddress((void**)&xvh, g_xvh); cudaGetSymbolAddress((void**)&xvl, g_xvl);
    cudaGetSymbolAddress((void**)&wqh, g_wqh); cudaGetSymbolAddress((void**)&wql, g_wql);
    cudaGetSymbolAddress((void**)&wkh, g_wkh); cudaGetSymbolAddress((void**)&wkl, g_wkl);
    cudaGetSymbolAddress((void**)&wvh, g_wvh); cudaGetSymbolAddress((void**)&wvl, g_wvl);
    cudaGetSymbolAddress((void**)&woh, g_woh); cudaGetSymbolAddress((void**)&wol, g_wol);
    cudaGetSymbolAddress((void**)&Qh,  g_Qh);  cudaGetSymbolAddress((void**)&Ql,  g_Ql);
    cudaGetSymbolAddress((void**)&Kh,  g_Kh);  cudaGetSymbolAddress((void**)&Kl,  g_Kl);
    cudaGetSymbolAddress((void**)&Vh,  g_Vh);  cudaGetSymbolAddress((void**)&Vl,  g_Vl);
    cudaGetSymbolAddress((void**)&Ah,  g_Ah);  cudaGetSymbolAddress((void**)&Al,  g_Al);

    cudaFuncSetAttribute(flash_sk, cudaFuncAttributeMaxDynamicSharedMemorySize,
                         FLASH_SMEM);
    cudaFuncSetAttribute(gemm_bf2<true>,  cudaFuncAttributeMaxDynamicSharedMemorySize,
                         GEMM_SMEM2);
    cudaFuncSetAttribute(gemm_bf2<false>, cudaFuncAttributeMaxDynamicSharedMemorySize,
                         GEMM_SMEM2);

    const int n4x = M_TOT * HID / 4;
    const int n4w = HID * HID / 4;

    SplitBatch sbt;
    sbt.src[0] = q;  sbt.dh[0] = xqh; sbt.dl[0] = xql; sbt.n4[0] = n4x;
    sbt.src[1] = k;  sbt.dh[1] = xkh; sbt.dl[1] = xkl; sbt.n4[1] = n4x;
    sbt.src[2] = v;  sbt.dh[2] = xvh; sbt.dl[2] = xvl; sbt.n4[2] = n4x;
    sbt.src[3] = Wq; sbt.dh[3] = wqh; sbt.dl[3] = wql; sbt.n4[3] = n4w;
    sbt.src[4] = Wk; sbt.dh[4] = wkh; sbt.dl[4] = wkl; sbt.n4[4] = n4w;
    sbt.src[5] = Wv; sbt.dh[5] = wvh; sbt.dl[5] = wvl; sbt.n4[5] = n4w;
    sbt.src[6] = Wo; sbt.dh[6] = woh; sbt.dl[6] = wol; sbt.n4[6] = n4w;
    split_all<<<dim3(n4x / 256, 7), 256>>>(sbt);

    GemmBatch gqkv = {};
    gqkv.ah[0] = xqh; gqkv.al[0] = xql; gqkv.wh[0] = wqh; gqkv.wl[0] = wql;
    gqkv.bias[0] = bq; gqkv.ch[0] = Qh; gqkv.cl[0] = Ql; gqkv.sc[0] = 0.125f;
    gqkv.ah[1] = xkh; gqkv.al[1] = xkl; gqkv.wh[1] = wkh; gqkv.wl[1] = wkl;
    gqkv.bias[1] = bk; gqkv.ch[1] = Kh; gqkv.cl[1] = Kl; gqkv.sc[1] = 1.0f;
    gqkv.ah[2] = xvh; gqkv.al[2] = xvl; gqkv.wh[2] = wvh; gqkv.wl[2] = wvl;
    gqkv.bias[2] = bv; gqkv.ch[2] = Vh; gqkv.cl[2] = Vl; gqkv.sc[2] = 1.0f;
    gemm_bf2<true><<<dim3(HID / 128, M_TOT / 128, 3), 256, GEMM_SMEM2>>>(gqkv);

    flash_sk<<<dim3(S_LEN / 64, NH, BATCH), 256, FLASH_SMEM>>>(
        Qh, Ql, Kh, Kl, Vh, Vl, mask, Ah, Al);

    GemmBatch gout = {};
    gout.ah[0] = Ah; gout.al[0] = Al; gout.wh[0] = woh; gout.wl[0] = wol;
    gout.bias[0] = bo; gout.c32[0] = out; gout.sc[0] = 1.0f;
    gemm_bf2<false><<<dim3(HID / 128, M_TOT / 128, 1), 256, GEMM_SMEM2>>>(gout);
}

// round 10
// speedup vs baseline: 2.8894x; 1.0006x over previous
#include <cuda_runtime.h>
#include <cuda_bf16.h>
#include <cstdint>
#include <math.h>

#define S_LEN 2048
#define BATCH 4
#define HID   1024
#define NH    16
#define DH    64
#define M_TOT (BATCH * S_LEN)      // 8192
#define FILLV (-10000000000000.0f)

// Scratch (device globals: no allocations allowed)
__device__ __nv_bfloat16 g_xqh[M_TOT * HID], g_xql[M_TOT * HID];
__device__ __nv_bfloat16 g_xkh[M_TOT * HID], g_xkl[M_TOT * HID];
__device__ __nv_bfloat16 g_xvh[M_TOT * HID], g_xvl[M_TOT * HID];
__device__ __nv_bfloat16 g_wqh[HID * HID], g_wql[HID * HID];
__device__ __nv_bfloat16 g_wkh[HID * HID], g_wkl[HID * HID];
__device__ __nv_bfloat16 g_wvh[HID * HID], g_wvl[HID * HID];
__device__ __nv_bfloat16 g_woh[HID * HID], g_wol[HID * HID];
__device__ __nv_bfloat16 g_Qh[M_TOT * HID], g_Ql[M_TOT * HID];
__device__ __nv_bfloat16 g_Kh[M_TOT * HID], g_Kl[M_TOT * HID];
__device__ __nv_bfloat16 g_Vh[M_TOT * HID], g_Vl[M_TOT * HID];
__device__ __nv_bfloat16 g_Ah[M_TOT * HID], g_Al[M_TOT * HID];

// ===========================================================================
// helpers
// ===========================================================================
__device__ __forceinline__ uint32_t smem_u32(const void* p) {
    uint32_t a;
    asm("{ .reg .u64 t; cvta.to.shared.u64 t, %1; cvt.u32.u64 %0, t; }"
        : "=r"(a) : "l"(p));
    return a;
}

#define LDSM_X4(r0, r1, r2, r3, addr)                                         \
    asm volatile("ldmatrix.sync.aligned.m8n8.x4.shared.b16 {%0,%1,%2,%3}, [%4];" \
                 : "=r"(r0), "=r"(r1), "=r"(r2), "=r"(r3) : "r"(addr))

#define LDSM_X4_T(r0, r1, r2, r3, addr)                                       \
    asm volatile("ldmatrix.sync.aligned.m8n8.x4.trans.shared.b16 {%0,%1,%2,%3}, [%4];" \
                 : "=r"(r0), "=r"(r1), "=r"(r2), "=r"(r3) : "r"(addr))

#define MMA16816(d, a0, a1, a2, a3, b0, b1)                                   \
    asm volatile("mma.sync.aligned.m16n8k16.row.col.f32.bf16.bf16.f32 "       \
                 "{%0,%1,%2,%3}, {%4,%5,%6,%7}, {%8,%9}, {%0,%1,%2,%3};"      \
                 : "+f"((d)[0]), "+f"((d)[1]), "+f"((d)[2]), "+f"((d)[3])     \
                 : "r"(a0), "r"(a1), "r"(a2), "r"(a3), "r"(b0), "r"(b1))

#define CP_ASYNC16(dst, src)                                                  \
    asm volatile("cp.async.cg.shared.global [%0], [%1], 16;"                  \
                 :: "r"(dst), "l"(src) : "memory")
#define CP_COMMIT() asm volatile("cp.async.commit_group;" ::: "memory")
#define CP_WAIT(n)  asm volatile("cp.async.wait_group %0;" :: "n"(n) : "memory")

#define BAR_G(id) asm volatile("bar.sync %0, %1;" :: "r"(id), "r"(128) : "memory")

__device__ __forceinline__ uint32_t pack_bf2(float x, float y) {
    __nv_bfloat16 bx = __float2bfloat16_rn(x);
    __nv_bfloat16 by = __float2bfloat16_rn(y);
    return (uint32_t)__bfloat16_as_ushort(bx)
         | ((uint32_t)__bfloat16_as_ushort(by) << 16);
}

__device__ __forceinline__ void split4(const float4& v, uint2& hi, uint2& lo) {
    __nv_bfloat16 h0 = __float2bfloat16_rn(v.x);
    __nv_bfloat16 h1 = __float2bfloat16_rn(v.y);
    __nv_bfloat16 h2 = __float2bfloat16_rn(v.z);
    __nv_bfloat16 h3 = __float2bfloat16_rn(v.w);
    float l0 = v.x - __bfloat162float(h0);
    float l1 = v.y - __bfloat162float(h1);
    float l2 = v.z - __bfloat162float(h2);
    float l3 = v.w - __bfloat162float(h3);
    hi.x = (uint32_t)__bfloat16_as_ushort(h0)
         | ((uint32_t)__bfloat16_as_ushort(h1) << 16);
    hi.y = (uint32_t)__bfloat16_as_ushort(h2)
         | ((uint32_t)__bfloat16_as_ushort(h3) << 16);
    lo.x = pack_bf2(l0, l1);
    lo.y = pack_bf2(l2, l3);
}

__device__ __forceinline__ void split2(float x, float y, uint32_t& hi, uint32_t& lo) {
    __nv_bfloat16 hx = __float2bfloat16_rn(x);
    __nv_bfloat16 hy = __float2bfloat16_rn(y);
    hi = (uint32_t)__bfloat16_as_ushort(hx)
       | ((uint32_t)__bfloat16_as_ushort(hy) << 16);
    lo = pack_bf2(x - __bfloat162float(hx), y - __bfloat162float(hy));
}

// fast truncation split for P (positive values)
__device__ __forceinline__ void split2t(float x, float y, uint32_t& hi, uint32_t& lo) {
    uint32_t ux = __float_as_uint(x), uy = __float_as_uint(y);
    hi = __byte_perm(ux, uy, 0x7632);
    float lx = x - __uint_as_float(ux & 0xffff0000u);
    float ly = y - __uint_as_float(uy & 0xffff0000u);
    asm("cvt.rn.bf16x2.f32 %0, %1, %2;" : "=r"(lo) : "f"(ly), "f"(lx));
}

// 128-byte-row XOR swizzle
__device__ __forceinline__ uint32_t off128(int row, int u) {
    return (uint32_t)(row * 128 + (((u ^ (row & 7))) << 4));
}

// ===========================================================================
// fused split pass
// ===========================================================================
struct SplitBatch {
    const float*   src[7];
    __nv_bfloat16* dh[7];
    __nv_bfloat16* dl[7];
    int            n4[7];
};

__global__ void __launch_bounds__(256)
split_all(SplitBatch s)
{
    const int t = blockIdx.y;
    const int i = blockIdx.x * 256 + threadIdx.x;
    if (i < s.n4[t]) {
        float4 v = ((const float4*)s.src[t])[i];
        uint2 hi, lo;
        split4(v, hi, lo);
        ((uint2*)s.dh[t])[i] = hi;
        ((uint2*)s.dl[t])[i] = lo;
    }
}

// ===========================================================================
// GEMM: BK=64, 3-stage cp.async, batched over blockIdx.z.
// Round-10: 512 threads / 16 warps (4x4 grid, 32x32 warp tile) -> 4 warps
// per SMSP so LDSM bursts and barrier drains hide behind other warps' MMAs.
// Per-accumulator arithmetic order unchanged => bit-identical results.
// ===========================================================================
#define GK 1024
#define NCH2 16
#define GSTAGE2 65536
#define GEMM_SMEM2 (3 * GSTAGE2)

struct GemmBatch {
    const __nv_bfloat16* ah[3];
    const __nv_bfloat16* al[3];
    const __nv_bfloat16* wh[3];
    const __nv_bfloat16* wl[3];
    const float*         bias[3];
    __nv_bfloat16*       ch[3];
    __nv_bfloat16*       cl[3];
    float*               c32[3];
    float                sc[3];
};

template<bool BF16OUT>
__global__ void __launch_bounds__(512)
gemm_bf2(GemmBatch gb)
{
    extern __shared__ __align__(128) uint8_t smg[];
    const uint32_t sb = smem_u32(smg);
    const int tid  = threadIdx.x;
    const int lane = tid & 31;
    const int warp = tid >> 5;          // 0..15
    const int wm   = warp >> 2;         // 0..3
    const int wn   = warp & 3;          // 0..3
    const int bm   = blockIdx.y * 128;
    const int bn   = blockIdx.x * 128;
    const int z    = blockIdx.z;
    const int lr   = lane & 7;
    const int ml   = lane >> 3;

    const __nv_bfloat16* srcs[4] = {
        gb.ah[z] + (size_t)bm * GK, gb.al[z] + (size_t)bm * GK,
        gb.wh[z] + (size_t)bn * GK, gb.wl[z] + (size_t)bn * GK };

    // cp.async slots: 512 threads, 1024 granules/matrix = 128 rows x 8
    const int r0 = tid >> 3, g0 = tid & 7;   // r0 0..63

    // frag row bases + xor bits (warp tile 32x32: mt=0..1, p=0..1)
    int rowA[2], xorA[2];
#pragma unroll
    for (int mt = 0; mt < 2; mt++) {
        int row = wm * 32 + mt * 16 + (ml & 1) * 8 + lr;
        rowA[mt] = row * 128;
        xorA[mt] = row & 7;
    }
    int rowW[2], xorW[2];
#pragma unroll
    for (int p = 0; p < 2; p++) {
        int row = wn * 32 + p * 16 + (ml >> 1) * 8 + lr;
        rowW[p] = row * 128;
        xorW[p] = row & 7;
    }
    const int gA = ml >> 1;
    const int gW = ml & 1;

    float acc[2][4][4];
#pragma unroll
    for (int mt = 0; mt < 2; mt++)
#pragma unroll
        for (int nt = 0; nt < 4; nt++)
#pragma unroll
            for (int r = 0; r < 4; r++) acc[mt][nt][r] = 0.0f;

    auto issue = [&](int t) {
        int st = t; while (st >= 3) st -= 3;
        const uint32_t stg = sb + (uint32_t)st * GSTAGE2;
        const int kc = t * 64;
#pragma unroll
        for (int m = 0; m < 4; m++) {
            const __nv_bfloat16* s = srcs[m] + kc + g0 * 8;
            CP_ASYNC16(stg + m * 16384 + off128(r0, g0),
                       s + (size_t)r0 * GK);
            CP_ASYNC16(stg + m * 16384 + off128(r0 + 64, g0),
                       s + (size_t)(r0 + 64) * GK);
        }
        CP_COMMIT();
    };

    issue(0);
    issue(1);

    for (int c = 0; c < NCH2; c++) {
        CP_WAIT(1);
        __syncthreads();
        if (c + 2 < NCH2) issue(c + 2);
        else              CP_COMMIT();

        int st = c; while (st >= 3) st -= 3;
        const uint32_t stg = sb + (uint32_t)st * GSTAGE2;

#pragma unroll
        for (int ks = 0; ks < 4; ks++) {
            uint32_t ah[2][4], al[2][4], wh[2][4], wl[2][4];
#pragma unroll
            for (int mt = 0; mt < 2; mt++) {
                uint32_t off = (uint32_t)rowA[mt]
                             + (((uint32_t)((ks * 2 + gA) ^ xorA[mt])) << 4);
                LDSM_X4(ah[mt][0], ah[mt][1], ah[mt][2], ah[mt][3], stg + off);
                LDSM_X4(al[mt][0], al[mt][1], al[mt][2], al[mt][3], stg + 16384 + off);
            }
#pragma unroll
            for (int p = 0; p < 2; p++) {
                uint32_t off = (uint32_t)rowW[p]
                             + (((uint32_t)((ks * 2 + gW) ^ xorW[p])) << 4);
                LDSM_X4(wh[p][0], wh[p][1], wh[p][2], wh[p][3], stg + 32768 + off);
                LDSM_X4(wl[p][0], wl[p][1], wl[p][2], wl[p][3], stg + 49152 + off);
            }
            // term-major passes (per-acc order hh -> hl -> lh preserved)
#pragma unroll
            for (int mt = 0; mt < 2; mt++)
#pragma unroll
                for (int p = 0; p < 2; p++)
#pragma unroll
                    for (int j2 = 0; j2 < 2; j2++)
                        MMA16816(acc[mt][2 * p + j2],
                                 ah[mt][0], ah[mt][1], ah[mt][2], ah[mt][3],
                                 wh[p][2 * j2], wh[p][2 * j2 + 1]);
#pragma unroll
            for (int mt = 0; mt < 2; mt++)
#pragma unroll
                for (int p = 0; p < 2; p++)
#pragma unroll
                    for (int j2 = 0; j2 < 2; j2++)
                        MMA16816(acc[mt][2 * p + j2],
                                 ah[mt][0], ah[mt][1], ah[mt][2], ah[mt][3],
                                 wl[p][2 * j2], wl[p][2 * j2 + 1]);
#pragma unroll
            for (int mt = 0; mt < 2; mt++)
#pragma unroll
                for (int p = 0; p < 2; p++)
#pragma unroll
                    for (int j2 = 0; j2 < 2; j2++)
                        MMA16816(acc[mt][2 * p + j2],
                                 al[mt][0], al[mt][1], al[mt][2], al[mt][3],
                                 wh[p][2 * j2], wh[p][2 * j2 + 1]);
        }
    }

    const float* bias = gb.bias[z];
    const float  sc   = gb.sc[z];
#pragma unroll
    for (int mt = 0; mt < 2; mt++) {
        int r0g = bm + wm * 32 + mt * 16 + (lane >> 2);
#pragma unroll
        for (int nt = 0; nt < 4; nt++) {
            int cg = bn + wn * 32 + nt * 8 + (lane & 3) * 2;
            float2 bz = *(const float2*)(bias + cg);
            float2 v0 = make_float2((acc[mt][nt][0] + bz.x) * sc,
                                    (acc[mt][nt][1] + bz.y) * sc);
            float2 v1 = make_float2((acc[mt][nt][2] + bz.x) * sc,
                                    (acc[mt][nt][3] + bz.y) * sc);
            if (BF16OUT) {
                uint32_t hi, lo;
                split2(v0.x, v0.y, hi, lo);
                *(uint32_t*)(gb.ch[z] + (size_t)r0g * HID + cg) = hi;
                *(uint32_t*)(gb.cl[z] + (size_t)r0g * HID + cg) = lo;
                split2(v1.x, v1.y, hi, lo);
                *(uint32_t*)(gb.ch[z] + (size_t)(r0g + 8) * HID + cg) = hi;
                *(uint32_t*)(gb.cl[z] + (size_t)(r0g + 8) * HID + cg) = lo;
            } else {
                *(float2*)(gb.c32[z] + (size_t)r0g * HID + cg)       = v0;
                *(float2*)(gb.c32[z] + (size_t)(r0g + 8) * HID + cg) = v1;
            }
        }
    }
}

// ===========================================================================
// Split-KV flash attention (round-9 verified, unchanged).
// ===========================================================================
#define XCH_M 148480
#define XCH_L 148736
#define XCH_O 148992
#define FLASH_SMEM 165376

__global__ void __launch_bounds__(256)
flash_sk(const __nv_bfloat16* __restrict__ Qhp, const __nv_bfloat16* __restrict__ Qlp,
         const __nv_bfloat16* __restrict__ Khp, const __nv_bfloat16* __restrict__ Klp,
         const __nv_bfloat16* __restrict__ Vhp, const __nv_bfloat16* __restrict__ Vlp,
         const float* __restrict__ maskg,
         __nv_bfloat16* __restrict__ Ahp, __nv_bfloat16* __restrict__ Alp)
{
    extern __shared__ __align__(128) uint8_t sbuf[];
    const uint32_t sb = smem_u32(sbuf);

    const int tid  = threadIdx.x;
    const int lane = tid & 31;
    const int w    = tid >> 5;
    const int lr   = lane & 7;
    const int ml   = lane >> 3;
    const int qb   = (int)gridDim.x - 1 - (int)blockIdx.x;
    const int h    = blockIdx.y;
    const int b    = blockIdx.z;
    const int q0   = qb * 64;
    const size_t base = ((size_t)b * S_LEN) * HID + (size_t)h * DH;

#pragma unroll
    for (int j = 0; j < 4; j++) {
        int f = tid + j * 256;
        int term = f >> 9;
        int c = f & 511;
        int row = c >> 3, qq = c & 7;
        CP_ASYNC16(sb + (uint32_t)term * 8192 + off128(row, qq),
                   (term ? Qlp : Qhp) + base + (size_t)(q0 + row) * HID + qq * 8);
    }
    CP_COMMIT();
    CP_WAIT(0);
    __syncthreads();

    uint32_t qh[4][4], ql[4][4];
    {
        int row = (w & 3) * 16 + (ml & 1) * 8 + lr;
#pragma unroll
        for (int ks = 0; ks < 4; ks++) {
            uint32_t off = off128(row, ks * 2 + (ml >> 1));
            LDSM_X4(qh[ks][0], qh[ks][1], qh[ks][2], qh[ks][3], sb + off);
            LDSM_X4(ql[ks][0], ql[ks][1], ql[ks][2], ql[ks][3], sb + 8192 + off);
        }
    }

    const int g      = w >> 2;
    const int wg_tid = tid & 127;
    const int barid  = g + 1;

    auto issue_g = [&](int t) {
        if (t <= qb) {
            const int k0t = t * 64;
            const __nv_bfloat16* bs[4] = {
                Khp + base + (size_t)k0t * HID,
                Klp + base + (size_t)k0t * HID,
                Vhp + base + (size_t)k0t * HID,
                Vlp + base + (size_t)k0t * HID };
            const uint32_t stg = sb + 16384u + (uint32_t)g * 65536u
                               + (uint32_t)((t >> 1) & 1) * 32768u;
#pragma unroll
            for (int j = 0; j < 16; j++) {
                int f = wg_tid + j * 128;
                int m = f >> 9, row = (f >> 3) & 63, g0 = f & 7;
                CP_ASYNC16(stg + (uint32_t)m * 8192 + off128(row, g0),
                           bs[m] + (size_t)row * HID + g0 * 8);
            }
            if (wg_tid < 16)
                CP_ASYNC16(sb + 147456u + (uint32_t)(g * 2 + ((t >> 1) & 1)) * 256u
                               + wg_tid * 16,
                           maskg + (size_t)b * S_LEN + k0t + wg_tid * 4);
        }
        CP_COMMIT();
    };

    issue_g(g);
    issue_g(g + 2);

    float oacc[8][4];
#pragma unroll
    for (int ns = 0; ns < 8; ns++)
#pragma unroll
        for (int r = 0; r < 4; r++) oacc[ns][r] = 0.0f;
    float m0 = -INFINITY, m1 = -INFINITY, l0 = 0.0f, l1 = 0.0f;

    const int r0g  = q0 + (w & 3) * 16 + (lane >> 2);
    const int cloc = (lane & 3) * 2;

    for (int t = g; t <= qb; t += 2) {
        const int k0 = t * 64;
        CP_WAIT(1);
        BAR_G(barid);

        const uint32_t stg = sb + 16384u + (uint32_t)g * 65536u
                           + (uint32_t)((t >> 1) & 1) * 32768u;
        const uint32_t sKh = stg, sKl = stg + 8192;
        const uint32_t sVh = stg + 16384, sVl = stg + 24576;
        const float* smask = (const float*)(sbuf + 147456
                           + (g * 2 + ((t >> 1) & 1)) * 256);

        float sacc[8][4];
#pragma unroll
        for (int nt = 0; nt < 8; nt++)
#pragma unroll
            for (int r = 0; r < 4; r++) sacc[nt][r] = 0.0f;

#pragma unroll
        for (int ks = 0; ks < 4; ks++) {
            uint32_t kh[4][4], kl[4][4];
            int rowb = (ml >> 1) * 8 + lr;
            int u    = ks * 2 + (ml & 1);
#pragma unroll
            for (int gg = 0; gg < 4; gg++) {
                int row = gg * 16 + rowb;
                uint32_t off = off128(row, u);
                LDSM_X4(kh[gg][0], kh[gg][1], kh[gg][2], kh[gg][3], sKh + off);
                LDSM_X4(kl[gg][0], kl[gg][1], kl[gg][2], kl[gg][3], sKl + off);
            }
#pragma unroll
            for (int gg = 0; gg < 4; gg++)
#pragma unroll
                for (int j2 = 0; j2 < 2; j2++)
                    MMA16816(sacc[2 * gg + j2], qh[ks][0], qh[ks][1], qh[ks][2], qh[ks][3],
                             kh[gg][2 * j2], kh[gg][2 * j2 + 1]);
#pragma unroll
            for (int gg = 0; gg < 4; gg++)
#pragma unroll
                for (int j2 = 0; j2 < 2; j2++)
                    MMA16816(sacc[2 * gg + j2], qh[ks][0], qh[ks][1], qh[ks][2], qh[ks][3],
                             kl[gg][2 * j2], kl[gg][2 * j2 + 1]);
#pragma unroll
            for (int gg = 0; gg < 4; gg++)
#pragma unroll
                for (int j2 = 0; j2 < 2; j2++)
                    MMA16816(sacc[2 * gg + j2], ql[ks][0], ql[ks][1], ql[ks][2], ql[ks][3],
                             kh[gg][2 * j2], kh[gg][2 * j2 + 1]);
        }

        float rm0 = -INFINITY, rm1 = -INFINITY;
        if (t == qb) {
#pragma unroll
            for (int nt = 0; nt < 8; nt++) {
                int c0 = nt * 8 + cloc;
                float mk0 = smask[c0], mk1 = smask[c0 + 1];
                int jg0 = k0 + c0, jg1 = jg0 + 1;
                sacc[nt][0] = (jg0 > r0g     || mk0 == 0.0f) ? FILLV : sacc[nt][0];
                sacc[nt][1] = (jg1 > r0g     || mk1 == 0.0f) ? FILLV : sacc[nt][1];
                sacc[nt][2] = (jg0 > r0g + 8 || mk0 == 0.0f) ? FILLV : sacc[nt][2];
                sacc[nt][3] = (jg1 > r0g + 8 || mk1 == 0.0f) ? FILLV : sacc[nt][3];
                rm0 = fmaxf(rm0, fmaxf(sacc[nt][0], sacc[nt][1]));
                rm1 = fmaxf(rm1, fmaxf(sacc[nt][2], sacc[nt][3]));
            }
        } else {
#pragma unroll
            for (int nt = 0; nt < 8; nt++) {
                int c0 = nt * 8 + cloc;
                float mk0 = smask[c0], mk1 = smask[c0 + 1];
                sacc[nt][0] = (mk0 == 0.0f) ? FILLV : sacc[nt][0];
                sacc[nt][1] = (mk1 == 0.0f) ? FILLV : sacc[nt][1];
                sacc[nt][2] = (mk0 == 0.0f) ? FILLV : sacc[nt][2];
                sacc[nt][3] = (mk1 == 0.0f) ? FILLV : sacc[nt][3];
                rm0 = fmaxf(rm0, fmaxf(sacc[nt][0], sacc[nt][1]));
                rm1 = fmaxf(rm1, fmaxf(sacc[nt][2], sacc[nt][3]));
            }
        }
        rm0 = fmaxf(rm0, __shfl_xor_sync(0xffffffffu, rm0, 1));
        rm0 = fmaxf(rm0, __shfl_xor_sync(0xffffffffu, rm0, 2));
        rm1 = fmaxf(rm1, __shfl_xor_sync(0xffffffffu, rm1, 1));
        rm1 = fmaxf(rm1, __shfl_xor_sync(0xffffffffu, rm1, 2));

        float mn0 = fmaxf(m0, rm0), mn1 = fmaxf(m1, rm1);
        float corr0 = __expf(m0 - mn0), corr1 = __expf(m1 - mn1);
        m0 = mn0; m1 = mn1;

        float rs0 = 0.0f, rs1 = 0.0f;
#pragma unroll
        for (int nt = 0; nt < 8; nt++) {
            sacc[nt][0] = __expf(sacc[nt][0] - mn0);
            sacc[nt][1] = __expf(sacc[nt][1] - mn0);
            sacc[nt][2] = __expf(sacc[nt][2] - mn1);
            sacc[nt][3] = __expf(sacc[nt][3] - mn1);
            rs0 += sacc[nt][0] + sacc[nt][1];
            rs1 += sacc[nt][2] + sacc[nt][3];
        }
        rs0 += __shfl_xor_sync(0xffffffffu, rs0, 1);
        rs0 += __shfl_xor_sync(0xffffffffu, rs0, 2);
        rs1 += __shfl_xor_sync(0xffffffffu, rs1, 1);
        rs1 += __shfl_xor_sync(0xffffffffu, rs1, 2);
        l0 = l0 * corr0 + rs0;
        l1 = l1 * corr1 + rs1;
#pragma unroll
        for (int ns = 0; ns < 8; ns++) {
            oacc[ns][0] *= corr0; oacc[ns][1] *= corr0;
            oacc[ns][2] *= corr1; oacc[ns][3] *= corr1;
        }

#pragma unroll
        for (int ks = 0; ks < 4; ks++) {
            uint32_t ph[4], pl[4];
            split2t(sacc[2 * ks][0],     sacc[2 * ks][1],     ph[0], pl[0]);
            split2t(sacc[2 * ks][2],     sacc[2 * ks][3],     ph[1], pl[1]);
            split2t(sacc[2 * ks + 1][0], sacc[2 * ks + 1][1], ph[2], pl[2]);
            split2t(sacc[2 * ks + 1][2], sacc[2 * ks + 1][3], ph[3], pl[3]);

            int rowv = ks * 16 + (ml & 1) * 8 + lr;
#pragma unroll
            for (int np = 0; np < 4; np++) {
                int u = np * 2 + (ml >> 1);
                uint32_t off = off128(rowv, u);
                uint32_t vh[4], vl[4];
                LDSM_X4_T(vh[0], vh[1], vh[2], vh[3], sVh + off);
                LDSM_X4_T(vl[0], vl[1], vl[2], vl[3], sVl + off);
                MMA16816(oacc[2 * np],     ph[0], ph[1], ph[2], ph[3], vh[0], vh[1]);
                MMA16816(oacc[2 * np + 1], ph[0], ph[1], ph[2], ph[3], vh[2], vh[3]);
                MMA16816(oacc[2 * np],     ph[0], ph[1], ph[2], ph[3], vl[0], vl[1]);
                MMA16816(oacc[2 * np + 1], ph[0], ph[1], ph[2], ph[3], vl[2], vl[3]);
                MMA16816(oacc[2 * np],     pl[0], pl[1], pl[2], pl[3], vh[0], vh[1]);
                MMA16816(oacc[2 * np + 1], pl[0], pl[1], pl[2], pl[3], vh[2], vh[3]);
            }
        }

        BAR_G(barid);
        issue_g(t + 4);
    }

    // ---- merge ----
    float* XM = (float*)(sbuf + XCH_M);
    float* XL = (float*)(sbuf + XCH_L);
    float* XO = (float*)(sbuf + XCH_O);
    const int rl = (w & 3) * 16 + (lane >> 2);

    if (g == 1) {
        if ((lane & 3) == 0) {
            XM[rl] = m0; XM[rl + 8] = m1;
            XL[rl] = l0; XL[rl + 8] = l1;
        }
#pragma unroll
        for (int ns = 0; ns < 8; ns++) {
            int col = ns * 8 + cloc;
            *(float2*)&XO[rl * 64 + col]       = make_float2(oacc[ns][0], oacc[ns][1]);
            *(float2*)&XO[(rl + 8) * 64 + col] = make_float2(oacc[ns][2], oacc[ns][3]);
        }
    }
    __syncthreads();
    if (g == 0) {
        float mB0 = XM[rl], mB1 = XM[rl + 8];
        float lB0 = XL[rl], lB1 = XL[rl + 8];
        float mm0 = fmaxf(m0, mB0), mm1 = fmaxf(m1, mB1);
        float a0 = __expf(m0 - mm0), b0f = __expf(mB0 - mm0);
        float a1 = __expf(m1 - mm1), b1f = __expf(mB1 - mm1);
        float li0 = 1.0f / (l0 * a0 + lB0 * b0f);
        float li1 = 1.0f / (l1 * a1 + lB1 * b1f);
#pragma unroll
        for (int ns = 0; ns < 8; ns++) {
            int col = ns * 8 + cloc;
            float2 ob0 = *(const float2*)&XO[rl * 64 + col];
            float2 ob1 = *(const float2*)&XO[(rl + 8) * 64 + col];
            float o00 = (oacc[ns][0] * a0 + ob0.x * b0f) * li0;
            float o01 = (oacc[ns][1] * a0 + ob0.y * b0f) * li0;
            float o10 = (oacc[ns][2] * a1 + ob1.x * b1f) * li1;
            float o11 = (oacc[ns][3] * a1 + ob1.y * b1f) * li1;
            uint32_t hi, lo;
            split2(o00, o01, hi, lo);
            *(uint32_t*)(Ahp + base + (size_t)(q0 + rl) * HID + col) = hi;
            *(uint32_t*)(Alp + base + (size_t)(q0 + rl) * HID + col) = lo;
            split2(o10, o11, hi, lo);
            *(uint32_t*)(Ahp + base + (size_t)(q0 + rl + 8) * HID + col) = hi;
            *(uint32_t*)(Alp + base + (size_t)(q0 + rl + 8) * HID + col) = lo;
        }
    }
}

// ---------------------------------------------------------------------------
extern "C" void kernel_launch(void* const* d_in, const int* in_sizes, int n_in,
                              void* d_out, int out_size)
{
    const float* q    = (const float*)d_in[0];
    const float* k    = (const float*)d_in[1];
    const float* v    = (const float*)d_in[2];
    const float* mask = (const float*)d_in[3];
    const float* Wq   = (const float*)d_in[4];
    const float* bq   = (const float*)d_in[5];
    const float* Wk   = (const float*)d_in[6];
    const float* bk   = (const float*)d_in[7];
    const float* Wv   = (const float*)d_in[8];
    const float* bv   = (const float*)d_in[9];
    const float* Wo   = (const float*)d_in[10];
    const float* bo   = (const float*)d_in[11];
    float* out = (float*)d_out;

    __nv_bfloat16 *xqh, *xql, *xkh, *xkl, *xvh, *xvl;
    __nv_bfloat16 *wqh, *wql, *wkh, *wkl, *wvh, *wvl, *woh, *wol;
    __nv_bfloat16 *Qh, *Ql, *Kh, *Kl, *Vh, *Vl, *Ah, *Al;
    cudaGetSymbolAddress((void**)&xqh, g_xqh); cudaGetSymbolAddress((void**)&xql, g_xql);
    cudaGetSymbolAddress((void**)&xkh, g_xkh); cudaGetSymbolAddress((void**)&xkl, g_xkl);
    cudaGetSymbolAddress((void**)&xvh, g_xvh); cudaGetSymbolAddress((void**)&xvl, g_xvl);
    cudaGetSymbolAddress((void**)&wqh, g_wqh); cudaGetSymbolAddress((void**)&wql, g_wql);
    cudaGetSymbolAddress((void**)&wkh, g_wkh); cudaGetSymbolAddress((void**)&wkl, g_wkl);
    cudaGetSymbolAddress((void**)&wvh, g_wvh); cudaGetSymbolAddress((void**)&wvl, g_wvl);
    cudaGetSymbolAddress((void**)&woh, g_woh); cudaGetSymbolAddress((void**)&wol, g_wol);
    cudaGetSymbolAddress((void**)&Qh,  g_Qh);  cudaGetSymbolAddress((void**)&Ql,  g_Ql);
    cudaGetSymbolAddress((void**)&Kh,  g_Kh);  cudaGetSymbolAddress((void**)&Kl,  g_Kl);
    cudaGetSymbolAddress((void**)&Vh,  g_Vh);  cudaGetSymbolAddress((void**)&Vl,  g_Vl);
    cudaGetSymbolAddress((void**)&Ah,  g_Ah);  cudaGetSymbolAddress((void**)&Al,  g_Al);

    cudaFuncSetAttribute(flash_sk, cudaFuncAttributeMaxDynamicSharedMemorySize,
                         FLASH_SMEM);
    cudaFuncSetAttribute(gemm_bf2<true>,  cudaFuncAttributeMaxDynamicSharedMemorySize,
                         GEMM_SMEM2);
    cudaFuncSetAttribute(gemm_bf2<false>, cudaFuncAttributeMaxDynamicSharedMemorySize,
                         GEMM_SMEM2);

    const int n4x = M_TOT * HID / 4;
    const int n4w = HID * HID / 4;

    SplitBatch sbt;
    sbt.src[0] = q;  sbt.dh[0] = xqh; sbt.dl[0] = xql; sbt.n4[0] = n4x;
    sbt.src[1] = k;  sbt.dh[1] = xkh; sbt.dl[1] = xkl; sbt.n4[1] = n4x;
    sbt.src[2] = v;  sbt.dh[2] = xvh; sbt.dl[2] = xvl; sbt.n4[2] = n4x;
    sbt.src[3] = Wq; sbt.dh[3] = wqh; sbt.dl[3] = wql; sbt.n4[3] = n4w;
    sbt.src[4] = Wk; sbt.dh[4] = wkh; sbt.dl[4] = wkl; sbt.n4[4] = n4w;
    sbt.src[5] = Wv; sbt.dh[5] = wvh; sbt.dl[5] = wvl; sbt.n4[5] = n4w;
    sbt.src[6] = Wo; sbt.dh[6] = woh; sbt.dl[6] = wol; sbt.n4[6] = n4w;
    split_all<<<dim3(n4x / 256, 7), 256>>>(sbt);

    GemmBatch gqkv = {};
    gqkv.ah[0] = xqh; gqkv.al[0] = xql; gqkv.wh[0] = wqh; gqkv.wl[0] = wql;
    gqkv.bias[0] = bq; gqkv.ch[0] = Qh; gqkv.cl[0] = Ql; gqkv.sc[0] = 0.125f;
    gqkv.ah[1] = xkh; gqkv.al[1] = xkl; gqkv.wh[1] = wkh; gqkv.wl[1] = wkl;
    gqkv.bias[1] = bk; gqkv.ch[1] = Kh; gqkv.cl[1] = Kl; gqkv.sc[1] = 1.0f;
    gqkv.ah[2] = xvh; gqkv.al[2] = xvl; gqkv.wh[2] = wvh; gqkv.wl[2] = wvl;
    gqkv.bias[2] = bv; gqkv.ch[2] = Vh; gqkv.cl[2] = Vl; gqkv.sc[2] = 1.0f;
    gemm_bf2<true><<<dim3(HID / 128, M_TOT / 128, 3), 512, GEMM_SMEM2>>>(gqkv);

    flash_sk<<<dim3(S_LEN / 64, NH, BATCH), 256, FLASH_SMEM>>>(
        Qh, Ql, Kh, Kl, Vh, Vl, mask, Ah, Al);

    GemmBatch gout = {};
    gout.ah[0] = Ah; gout.al[0] = Al; gout.wh[0] = woh; gout.wl[0] = wol;
    gout.bias[0] = bo; gout.c32[0] = out; gout.sc[0] = 1.0f;
    gemm_bf2<false><<<dim3(HID / 128, M_TOT / 128, 1), 512, GEMM_SMEM2>>>(gout);
}

// round 11
// speedup vs baseline: 3.2754x; 1.1336x over previous
#include <cuda_runtime.h>
#include <cuda_bf16.h>
#include <cuda_fp16.h>
#include <cstdint>
#include <math.h>

#define S_LEN 2048
#define BATCH 4
#define HID   1024
#define NH    16
#define DH    64
#define M_TOT (BATCH * S_LEN)      // 8192
#define FILLV (-10000000000000.0f)

#define BETA_C 0.984375f           // 1 - 2^-6
#define INVB   64.0f               // 1/beta

// Scratch (device globals: no allocations allowed)
// fp16 fold pairs for GEMM inputs
__device__ __half g_xqh[M_TOT * HID], g_xqu[M_TOT * HID];
__device__ __half g_xkh[M_TOT * HID], g_xku[M_TOT * HID];
__device__ __half g_xvh[M_TOT * HID], g_xvu[M_TOT * HID];
__device__ __half g_wqh[HID * HID], g_wqv[HID * HID];
__device__ __half g_wkh[HID * HID], g_wkv[HID * HID];
__device__ __half g_wvh[HID * HID], g_wvv[HID * HID];
__device__ __half g_woh[HID * HID], g_wov[HID * HID];
// bf16 split pairs for flash (unchanged format)
__device__ __nv_bfloat16 g_Qh[M_TOT * HID], g_Ql[M_TOT * HID];
__device__ __nv_bfloat16 g_Kh[M_TOT * HID], g_Kl[M_TOT * HID];
__device__ __nv_bfloat16 g_Vh[M_TOT * HID], g_Vl[M_TOT * HID];
// flash output: fp16 fold pair for the out-GEMM
__device__ __half g_Ah16[M_TOT * HID], g_Au16[M_TOT * HID];

// ===========================================================================
// helpers
// ===========================================================================
__device__ __forceinline__ uint32_t smem_u32(const void* p) {
    uint32_t a;
    asm("{ .reg .u64 t; cvta.to.shared.u64 t, %1; cvt.u32.u64 %0, t; }"
        : "=r"(a) : "l"(p));
    return a;
}

#define LDSM_X4(r0, r1, r2, r3, addr)                                         \
    asm volatile("ldmatrix.sync.aligned.m8n8.x4.shared.b16 {%0,%1,%2,%3}, [%4];" \
                 : "=r"(r0), "=r"(r1), "=r"(r2), "=r"(r3) : "r"(addr))

#define LDSM_X4_T(r0, r1, r2, r3, addr)                                       \
    asm volatile("ldmatrix.sync.aligned.m8n8.x4.trans.shared.b16 {%0,%1,%2,%3}, [%4];" \
                 : "=r"(r0), "=r"(r1), "=r"(r2), "=r"(r3) : "r"(addr))

// bf16 mma (flash)
#define MMA16816(d, a0, a1, a2, a3, b0, b1)                                   \
    asm volatile("mma.sync.aligned.m16n8k16.row.col.f32.bf16.bf16.f32 "       \
                 "{%0,%1,%2,%3}, {%4,%5,%6,%7}, {%8,%9}, {%0,%1,%2,%3};"      \
                 : "+f"((d)[0]), "+f"((d)[1]), "+f"((d)[2]), "+f"((d)[3])     \
                 : "r"(a0), "r"(a1), "r"(a2), "r"(a3), "r"(b0), "r"(b1))

// fp16 mma (GEMMs)
#define MMA16816H(d, a0, a1, a2, a3, b0, b1)                                  \
    asm volatile("mma.sync.aligned.m16n8k16.row.col.f32.f16.f16.f32 "         \
                 "{%0,%1,%2,%3}, {%4,%5,%6,%7}, {%8,%9}, {%0,%1,%2,%3};"      \
                 : "+f"((d)[0]), "+f"((d)[1]), "+f"((d)[2]), "+f"((d)[3])     \
                 : "r"(a0), "r"(a1), "r"(a2), "r"(a3), "r"(b0), "r"(b1))

#define CP_ASYNC16(dst, src)                                                  \
    asm volatile("cp.async.cg.shared.global [%0], [%1], 16;"                  \
                 :: "r"(dst), "l"(src) : "memory")
#define CP_COMMIT() asm volatile("cp.async.commit_group;" ::: "memory")
#define CP_WAIT(n)  asm volatile("cp.async.wait_group %0;" :: "n"(n) : "memory")

#define BAR_G(id) asm volatile("bar.sync %0, %1;" :: "r"(id), "r"(128) : "memory")

__device__ __forceinline__ uint32_t pack_bf2(float x, float y) {
    __nv_bfloat16 bx = __float2bfloat16_rn(x);
    __nv_bfloat16 by = __float2bfloat16_rn(y);
    return (uint32_t)__bfloat16_as_ushort(bx)
         | ((uint32_t)__bfloat16_as_ushort(by) << 16);
}

// bf16 round-split (QKV gemm epilogue -> flash inputs)
__device__ __forceinline__ void split2(float x, float y, uint32_t& hi, uint32_t& lo) {
    __nv_bfloat16 hx = __float2bfloat16_rn(x);
    __nv_bfloat16 hy = __float2bfloat16_rn(y);
    hi = (uint32_t)__bfloat16_as_ushort(hx)
       | ((uint32_t)__bfloat16_as_ushort(hy) << 16);
    lo = pack_bf2(x - __bfloat162float(hx), y - __bfloat162float(hy));
}

// fast truncation split for P (positive values) in flash
__device__ __forceinline__ void split2t(float x, float y, uint32_t& hi, uint32_t& lo) {
    uint32_t ux = __float_as_uint(x), uy = __float_as_uint(y);
    hi = __byte_perm(ux, uy, 0x7632);
    float lx = x - __uint_as_float(ux & 0xffff0000u);
    float ly = y - __uint_as_float(uy & 0xffff0000u);
    asm("cvt.rn.bf16x2.f32 %0, %1, %2;" : "=r"(lo) : "f"(ly), "f"(lx));
}

// fp16 A-side fold pair: h = rn16(x), u = rn16(x - (1-beta)*h)
__device__ __forceinline__ void split2h(float x, float y, uint32_t& h, uint32_t& u) {
    __half hx = __float2half_rn(x);
    __half hy = __float2half_rn(y);
    h = (uint32_t)__half_as_ushort(hx) | ((uint32_t)__half_as_ushort(hy) << 16);
    __half ux = __float2half_rn(x - BETA_C * __half2float(hx));
    __half uy = __float2half_rn(y - BETA_C * __half2float(hy));
    u = (uint32_t)__half_as_ushort(ux) | ((uint32_t)__half_as_ushort(uy) << 16);
}

// fp16 W-side fold pair: h = rn16(w), v = rn16((w - (1-beta)*h) * 64)
__device__ __forceinline__ void split2hw(float x, float y, uint32_t& h, uint32_t& v) {
    __half hx = __float2half_rn(x);
    __half hy = __float2half_rn(y);
    h = (uint32_t)__half_as_ushort(hx) | ((uint32_t)__half_as_ushort(hy) << 16);
    __half vx = __float2half_rn((x - BETA_C * __half2float(hx)) * INVB);
    __half vy = __float2half_rn((y - BETA_C * __half2float(hy)) * INVB);
    v = (uint32_t)__half_as_ushort(vx) | ((uint32_t)__half_as_ushort(vy) << 16);
}

// 128-byte-row XOR swizzle
__device__ __forceinline__ uint32_t off128(int row, int u) {
    return (uint32_t)(row * 128 + (((u ^ (row & 7))) << 4));
}

// ===========================================================================
// fused split pass: tensors 0..2 = A-side (inputs), 3..6 = W-side (weights)
// ===========================================================================
struct SplitBatch {
    const float* src[7];
    __half*      dh[7];
    __half*      du[7];
    int          n4[7];
};

__global__ void __launch_bounds__(256)
split_all(SplitBatch s)
{
    const int t = blockIdx.y;
    const int i = blockIdx.x * 256 + threadIdx.x;
    if (i < s.n4[t]) {
        float4 v = ((const float4*)s.src[t])[i];
        uint2 h, u;
        if (t < 3) {
            split2h(v.x, v.y, h.x, u.x);
            split2h(v.z, v.w, h.y, u.y);
        } else {
            split2hw(v.x, v.y, h.x, u.x);
            split2hw(v.z, v.w, h.y, u.y);
        }
        ((uint2*)s.dh[t])[i] = h;
        ((uint2*)s.du[t])[i] = u;
    }
}

// ===========================================================================
// GEMM v4: fp16 residual-fold, 2 MMAs per k-step per acc (P and S accs).
// D = (1-beta)*P + S.  BK=64, 3-stage cp.async, 512 threads / 16 warps,
// batched over blockIdx.z. Stage: Ah@0 Ua@16K Wh@32K Vw@48K.
// ===========================================================================
#define GK 1024
#define NCH2 16
#define GSTAGE2 65536
#define GEMM_SMEM2 (3 * GSTAGE2)

struct GemmBatch {
    const __half*  ah[3];
    const __half*  au[3];
    const __half*  wh[3];
    const __half*  wv[3];
    const float*   bias[3];
    __nv_bfloat16* ch[3];
    __nv_bfloat16* cl[3];
    float*         c32[3];
    float          sc[3];
};

template<bool BF16OUT>
__global__ void __launch_bounds__(512)
gemm_h2(GemmBatch gb)
{
    extern __shared__ __align__(128) uint8_t smg[];
    const uint32_t sb = smem_u32(smg);
    const int tid  = threadIdx.x;
    const int lane = tid & 31;
    const int warp = tid >> 5;          // 0..15
    const int wm   = warp >> 2;
    const int wn   = warp & 3;
    const int bm   = blockIdx.y * 128;
    const int bn   = blockIdx.x * 128;
    const int z    = blockIdx.z;
    const int lr   = lane & 7;
    const int ml   = lane >> 3;

    const __half* srcs[4] = {
        gb.ah[z] + (size_t)bm * GK, gb.au[z] + (size_t)bm * GK,
        gb.wh[z] + (size_t)bn * GK, gb.wv[z] + (size_t)bn * GK };

    const int r0 = tid >> 3, g0 = tid & 7;

    int rowA[2], xorA[2];
#pragma unroll
    for (int mt = 0; mt < 2; mt++) {
        int row = wm * 32 + mt * 16 + (ml & 1) * 8 + lr;
        rowA[mt] = row * 128;
        xorA[mt] = row & 7;
    }
    int rowW[2], xorW[2];
#pragma unroll
    for (int p = 0; p < 2; p++) {
        int row = wn * 32 + p * 16 + (ml >> 1) * 8 + lr;
        rowW[p] = row * 128;
        xorW[p] = row & 7;
    }
    const int gA = ml >> 1;
    const int gW = ml & 1;

    float accP[2][4][4], accS[2][4][4];
#pragma unroll
    for (int mt = 0; mt < 2; mt++)
#pragma unroll
        for (int nt = 0; nt < 4; nt++)
#pragma unroll
            for (int r = 0; r < 4; r++) { accP[mt][nt][r] = 0.0f; accS[mt][nt][r] = 0.0f; }

    auto issue = [&](int t) {
        int st = t; while (st >= 3) st -= 3;
        const uint32_t stg = sb + (uint32_t)st * GSTAGE2;
        const int kc = t * 64;
#pragma unroll
        for (int m = 0; m < 4; m++) {
            const __half* s = srcs[m] + kc + g0 * 8;
            CP_ASYNC16(stg + m * 16384 + off128(r0, g0),
                       s + (size_t)r0 * GK);
            CP_ASYNC16(stg + m * 16384 + off128(r0 + 64, g0),
                       s + (size_t)(r0 + 64) * GK);
        }
        CP_COMMIT();
    };

    issue(0);
    issue(1);

    for (int c = 0; c < NCH2; c++) {
        CP_WAIT(1);
        __syncthreads();
        if (c + 2 < NCH2) issue(c + 2);
        else              CP_COMMIT();

        int st = c; while (st >= 3) st -= 3;
        const uint32_t stg = sb + (uint32_t)st * GSTAGE2;

#pragma unroll
        for (int ks = 0; ks < 4; ks++) {
            uint32_t ah[2][4], ua[2][4], wh[2][4], vw[2][4];
#pragma unroll
            for (int mt = 0; mt < 2; mt++) {
                uint32_t off = (uint32_t)rowA[mt]
                             + (((uint32_t)((ks * 2 + gA) ^ xorA[mt])) << 4);
                LDSM_X4(ah[mt][0], ah[mt][1], ah[mt][2], ah[mt][3], stg + off);
                LDSM_X4(ua[mt][0], ua[mt][1], ua[mt][2], ua[mt][3], stg + 16384 + off);
            }
#pragma unroll
            for (int p = 0; p < 2; p++) {
                uint32_t off = (uint32_t)rowW[p]
                             + (((uint32_t)((ks * 2 + gW) ^ xorW[p])) << 4);
                LDSM_X4(wh[p][0], wh[p][1], wh[p][2], wh[p][3], stg + 32768 + off);
                LDSM_X4(vw[p][0], vw[p][1], vw[p][2], vw[p][3], stg + 49152 + off);
            }
#pragma unroll
            for (int mt = 0; mt < 2; mt++)
#pragma unroll
                for (int p = 0; p < 2; p++)
#pragma unroll
                    for (int j2 = 0; j2 < 2; j2++)
                        MMA16816H(accP[mt][2 * p + j2],
                                  ah[mt][0], ah[mt][1], ah[mt][2], ah[mt][3],
                                  wh[p][2 * j2], wh[p][2 * j2 + 1]);
#pragma unroll
            for (int mt = 0; mt < 2; mt++)
#pragma unroll
                for (int p = 0; p < 2; p++)
#pragma unroll
                    for (int j2 = 0; j2 < 2; j2++)
                        MMA16816H(accS[mt][2 * p + j2],
                                  ua[mt][0], ua[mt][1], ua[mt][2], ua[mt][3],
                                  vw[p][2 * j2], vw[p][2 * j2 + 1]);
        }
    }

    const float* bias = gb.bias[z];
    const float  sc   = gb.sc[z];
#pragma unroll
    for (int mt = 0; mt < 2; mt++) {
        int r0g = bm + wm * 32 + mt * 16 + (lane >> 2);
#pragma unroll
        for (int nt = 0; nt < 4; nt++) {
            int cg = bn + wn * 32 + nt * 8 + (lane & 3) * 2;
            float2 bz = *(const float2*)(bias + cg);
            float d0 = fmaf(BETA_C, accP[mt][nt][0], accS[mt][nt][0]);
            float d1 = fmaf(BETA_C, accP[mt][nt][1], accS[mt][nt][1]);
            float d2 = fmaf(BETA_C, accP[mt][nt][2], accS[mt][nt][2]);
            float d3 = fmaf(BETA_C, accP[mt][nt][3], accS[mt][nt][3]);
            float2 v0 = make_float2((d0 + bz.x) * sc, (d1 + bz.y) * sc);
            float2 v1 = make_float2((d2 + bz.x) * sc, (d3 + bz.y) * sc);
            if (BF16OUT) {
                uint32_t hi, lo;
                split2(v0.x, v0.y, hi, lo);
                *(uint32_t*)(gb.ch[z] + (size_t)r0g * HID + cg) = hi;
                *(uint32_t*)(gb.cl[z] + (size_t)r0g * HID + cg) = lo;
                split2(v1.x, v1.y, hi, lo);
                *(uint32_t*)(gb.ch[z] + (size_t)(r0g + 8) * HID + cg) = hi;
                *(uint32_t*)(gb.cl[z] + (size_t)(r0g + 8) * HID + cg) = lo;
            } else {
                *(float2*)(gb.c32[z] + (size_t)r0g * HID + cg)       = v0;
                *(float2*)(gb.c32[z] + (size_t)(r0g + 8) * HID + cg) = v1;
            }
        }
    }
}

// ===========================================================================
// Split-KV flash attention (round-10 verified, unchanged math).
// Epilogue now writes fp16 fold pair (Ah16, Au16) for the out-GEMM.
// ===========================================================================
#define XCH_M 148480
#define XCH_L 148736
#define XCH_O 148992
#define FLASH_SMEM 165376

__global__ void __launch_bounds__(256)
flash_sk(const __nv_bfloat16* __restrict__ Qhp, const __nv_bfloat16* __restrict__ Qlp,
         const __nv_bfloat16* __restrict__ Khp, const __nv_bfloat16* __restrict__ Klp,
         const __nv_bfloat16* __restrict__ Vhp, const __nv_bfloat16* __restrict__ Vlp,
         const float* __restrict__ maskg,
         __half* __restrict__ Ahp, __half* __restrict__ Aup)
{
    extern __shared__ __align__(128) uint8_t sbuf[];
    const uint32_t sb = smem_u32(sbuf);

    const int tid  = threadIdx.x;
    const int lane = tid & 31;
    const int w    = tid >> 5;
    const int lr   = lane & 7;
    const int ml   = lane >> 3;
    const int qb   = (int)gridDim.x - 1 - (int)blockIdx.x;
    const int h    = blockIdx.y;
    const int b    = blockIdx.z;
    const int q0   = qb * 64;
    const size_t base = ((size_t)b * S_LEN) * HID + (size_t)h * DH;

#pragma unroll
    for (int j = 0; j < 4; j++) {
        int f = tid + j * 256;
        int term = f >> 9;
        int c = f & 511;
        int row = c >> 3, qq = c & 7;
        CP_ASYNC16(sb + (uint32_t)term * 8192 + off128(row, qq),
                   (term ? Qlp : Qhp) + base + (size_t)(q0 + row) * HID + qq * 8);
    }
    CP_COMMIT();
    CP_WAIT(0);
    __syncthreads();

    uint32_t qh[4][4], ql[4][4];
    {
        int row = (w & 3) * 16 + (ml & 1) * 8 + lr;
#pragma unroll
        for (int ks = 0; ks < 4; ks++) {
            uint32_t off = off128(row, ks * 2 + (ml >> 1));
            LDSM_X4(qh[ks][0], qh[ks][1], qh[ks][2], qh[ks][3], sb + off);
            LDSM_X4(ql[ks][0], ql[ks][1], ql[ks][2], ql[ks][3], sb + 8192 + off);
        }
    }

    const int g      = w >> 2;
    const int wg_tid = tid & 127;
    const int barid  = g + 1;

    auto issue_g = [&](int t) {
        if (t <= qb) {
            const int k0t = t * 64;
            const __nv_bfloat16* bs[4] = {
                Khp + base + (size_t)k0t * HID,
                Klp + base + (size_t)k0t * HID,
                Vhp + base + (size_t)k0t * HID,
                Vlp + base + (size_t)k0t * HID };
            const uint32_t stg = sb + 16384u + (uint32_t)g * 65536u
                               + (uint32_t)((t >> 1) & 1) * 32768u;
#pragma unroll
            for (int j = 0; j < 16; j++) {
                int f = wg_tid + j * 128;
                int m = f >> 9, row = (f >> 3) & 63, g0 = f & 7;
                CP_ASYNC16(stg + (uint32_t)m * 8192 + off128(row, g0),
                           bs[m] + (size_t)row * HID + g0 * 8);
            }
            if (wg_tid < 16)
                CP_ASYNC16(sb + 147456u + (uint32_t)(g * 2 + ((t >> 1) & 1)) * 256u
                               + wg_tid * 16,
                           maskg + (size_t)b * S_LEN + k0t + wg_tid * 4);
        }
        CP_COMMIT();
    };

    issue_g(g);
    issue_g(g + 2);

    float oacc[8][4];
#pragma unroll
    for (int ns = 0; ns < 8; ns++)
#pragma unroll
        for (int r = 0; r < 4; r++) oacc[ns][r] = 0.0f;
    float m0 = -INFINITY, m1 = -INFINITY, l0 = 0.0f, l1 = 0.0f;

    const int r0g  = q0 + (w & 3) * 16 + (lane >> 2);
    const int cloc = (lane & 3) * 2;

    for (int t = g; t <= qb; t += 2) {
        const int k0 = t * 64;
        CP_WAIT(1);
        BAR_G(barid);

        const uint32_t stg = sb + 16384u + (uint32_t)g * 65536u
                           + (uint32_t)((t >> 1) & 1) * 32768u;
        const uint32_t sKh = stg, sKl = stg + 8192;
        const uint32_t sVh = stg + 16384, sVl = stg + 24576;
        const float* smask = (const float*)(sbuf + 147456
                           + (g * 2 + ((t >> 1) & 1)) * 256);

        float sacc[8][4];
#pragma unroll
        for (int nt = 0; nt < 8; nt++)
#pragma unroll
            for (int r = 0; r < 4; r++) sacc[nt][r] = 0.0f;

#pragma unroll
        for (int ks = 0; ks < 4; ks++) {
            uint32_t kh[4][4], kl[4][4];
            int rowb = (ml >> 1) * 8 + lr;
            int u    = ks * 2 + (ml & 1);
#pragma unroll
            for (int gg = 0; gg < 4; gg++) {
                int row = gg * 16 + rowb;
                uint32_t off = off128(row, u);
                LDSM_X4(kh[gg][0], kh[gg][1], kh[gg][2], kh[gg][3], sKh + off);
                LDSM_X4(kl[gg][0], kl[gg][1], kl[gg][2], kl[gg][3], sKl + off);
            }
#pragma unroll
            for (int gg = 0; gg < 4; gg++)
#pragma unroll
                for (int j2 = 0; j2 < 2; j2++)
                    MMA16816(sacc[2 * gg + j2], qh[ks][0], qh[ks][1], qh[ks][2], qh[ks][3],
                             kh[gg][2 * j2], kh[gg][2 * j2 + 1]);
#pragma unroll
            for (int gg = 0; gg < 4; gg++)
#pragma unroll
                for (int j2 = 0; j2 < 2; j2++)
                    MMA16816(sacc[2 * gg + j2], qh[ks][0], qh[ks][1], qh[ks][2], qh[ks][3],
                             kl[gg][2 * j2], kl[gg][2 * j2 + 1]);
#pragma unroll
            for (int gg = 0; gg < 4; gg++)
#pragma unroll
                for (int j2 = 0; j2 < 2; j2++)
                    MMA16816(sacc[2 * gg + j2], ql[ks][0], ql[ks][1], ql[ks][2], ql[ks][3],
                             kh[gg][2 * j2], kh[gg][2 * j2 + 1]);
        }

        float rm0 = -INFINITY, rm1 = -INFINITY;
        if (t == qb) {
#pragma unroll
            for (int nt = 0; nt < 8; nt++) {
                int c0 = nt * 8 + cloc;
                float mk0 = smask[c0], mk1 = smask[c0 + 1];
                int jg0 = k0 + c0, jg1 = jg0 + 1;
                sacc[nt][0] = (jg0 > r0g     || mk0 == 0.0f) ? FILLV : sacc[nt][0];
                sacc[nt][1] = (jg1 > r0g     || mk1 == 0.0f) ? FILLV : sacc[nt][1];
                sacc[nt][2] = (jg0 > r0g + 8 || mk0 == 0.0f) ? FILLV : sacc[nt][2];
                sacc[nt][3] = (jg1 > r0g + 8 || mk1 == 0.0f) ? FILLV : sacc[nt][3];
                rm0 = fmaxf(rm0, fmaxf(sacc[nt][0], sacc[nt][1]));
                rm1 = fmaxf(rm1, fmaxf(sacc[nt][2], sacc[nt][3]));
            }
        } else {
#pragma unroll
            for (int nt = 0; nt < 8; nt++) {
                int c0 = nt * 8 + cloc;
                float mk0 = smask[c0], mk1 = smask[c0 + 1];
                sacc[nt][0] = (mk0 == 0.0f) ? FILLV : sacc[nt][0];
                sacc[nt][1] = (mk1 == 0.0f) ? FILLV : sacc[nt][1];
                sacc[nt][2] = (mk0 == 0.0f) ? FILLV : sacc[nt][2];
                sacc[nt][3] = (mk1 == 0.0f) ? FILLV : sacc[nt][3];
                rm0 = fmaxf(rm0, fmaxf(sacc[nt][0], sacc[nt][1]));
                rm1 = fmaxf(rm1, fmaxf(sacc[nt][2], sacc[nt][3]));
            }
        }
        rm0 = fmaxf(rm0, __shfl_xor_sync(0xffffffffu, rm0, 1));
        rm0 = fmaxf(rm0, __shfl_xor_sync(0xffffffffu, rm0, 2));
        rm1 = fmaxf(rm1, __shfl_xor_sync(0xffffffffu, rm1, 1));
        rm1 = fmaxf(rm1, __shfl_xor_sync(0xffffffffu, rm1, 2));

        float mn0 = fmaxf(m0, rm0), mn1 = fmaxf(m1, rm1);
        float corr0 = __expf(m0 - mn0), corr1 = __expf(m1 - mn1);
        m0 = mn0; m1 = mn1;

        float rs0 = 0.0f, rs1 = 0.0f;
#pragma unroll
        for (int nt = 0; nt < 8; nt++) {
            sacc[nt][0] = __expf(sacc[nt][0] - mn0);
            sacc[nt][1] = __expf(sacc[nt][1] - mn0);
            sacc[nt][2] = __expf(sacc[nt][2] - mn1);
            sacc[nt][3] = __expf(sacc[nt][3] - mn1);
            rs0 += sacc[nt][0] + sacc[nt][1];
            rs1 += sacc[nt][2] + sacc[nt][3];
        }
        rs0 += __shfl_xor_sync(0xffffffffu, rs0, 1);
        rs0 += __shfl_xor_sync(0xffffffffu, rs0, 2);
        rs1 += __shfl_xor_sync(0xffffffffu, rs1, 1);
        rs1 += __shfl_xor_sync(0xffffffffu, rs1, 2);
        l0 = l0 * corr0 + rs0;
        l1 = l1 * corr1 + rs1;
#pragma unroll
        for (int ns = 0; ns < 8; ns++) {
            oacc[ns][0] *= corr0; oacc[ns][1] *= corr0;
            oacc[ns][2] *= corr1; oacc[ns][3] *= corr1;
        }

#pragma unroll
        for (int ks = 0; ks < 4; ks++) {
            uint32_t ph[4], pl[4];
            split2t(sacc[2 * ks][0],     sacc[2 * ks][1],     ph[0], pl[0]);
            split2t(sacc[2 * ks][2],     sacc[2 * ks][3],     ph[1], pl[1]);
            split2t(sacc[2 * ks + 1][0], sacc[2 * ks + 1][1], ph[2], pl[2]);
            split2t(sacc[2 * ks + 1][2], sacc[2 * ks + 1][3], ph[3], pl[3]);

            int rowv = ks * 16 + (ml & 1) * 8 + lr;
#pragma unroll
            for (int np = 0; np < 4; np++) {
                int u = np * 2 + (ml >> 1);
                uint32_t off = off128(rowv, u);
                uint32_t vh[4], vl[4];
                LDSM_X4_T(vh[0], vh[1], vh[2], vh[3], sVh + off);
                LDSM_X4_T(vl[0], vl[1], vl[2], vl[3], sVl + off);
                MMA16816(oacc[2 * np],     ph[0], ph[1], ph[2], ph[3], vh[0], vh[1]);
                MMA16816(oacc[2 * np + 1], ph[0], ph[1], ph[2], ph[3], vh[2], vh[3]);
                MMA16816(oacc[2 * np],     ph[0], ph[1], ph[2], ph[3], vl[0], vl[1]);
                MMA16816(oacc[2 * np + 1], ph[0], ph[1], ph[2], ph[3], vl[2], vl[3]);
                MMA16816(oacc[2 * np],     pl[0], pl[1], pl[2], pl[3], vh[0], vh[1]);
                MMA16816(oacc[2 * np + 1], pl[0], pl[1], pl[2], pl[3], vh[2], vh[3]);
            }
        }

        BAR_G(barid);
        issue_g(t + 4);
    }

    // ---- merge: group B publishes, group A combines + writes fp16 fold ----
    float* XM = (float*)(sbuf + XCH_M);
    float* XL = (float*)(sbuf + XCH_L);
    float* XO = (float*)(sbuf + XCH_O);
    const int rl = (w & 3) * 16 + (lane >> 2);

    if (g == 1) {
        if ((lane & 3) == 0) {
            XM[rl] = m0; XM[rl + 8] = m1;
            XL[rl] = l0; XL[rl + 8] = l1;
        }
#pragma unroll
        for (int ns = 0; ns < 8; ns++) {
            int col = ns * 8 + cloc;
            *(float2*)&XO[rl * 64 + col]       = make_float2(oacc[ns][0], oacc[ns][1]);
            *(float2*)&XO[(rl + 8) * 64 + col] = make_float2(oacc[ns][2], oacc[ns][3]);
        }
    }
    __syncthreads();
    if (g == 0) {
        float mB0 = XM[rl], mB1 = XM[rl + 8];
        float lB0 = XL[rl], lB1 = XL[rl + 8];
        float mm0 = fmaxf(m0, mB0), mm1 = fmaxf(m1, mB1);
        float a0 = __expf(m0 - mm0), b0f = __expf(mB0 - mm0);
        float a1 = __expf(m1 - mm1), b1f = __expf(mB1 - mm1);
        float li0 = 1.0f / (l0 * a0 + lB0 * b0f);
        float li1 = 1.0f / (l1 * a1 + lB1 * b1f);
#pragma unroll
        for (int ns = 0; ns < 8; ns++) {
            int col = ns * 8 + cloc;
            float2 ob0 = *(const float2*)&XO[rl * 64 + col];
            float2 ob1 = *(const float2*)&XO[(rl + 8) * 64 + col];
            float o00 = (oacc[ns][0] * a0 + ob0.x * b0f) * li0;
            float o01 = (oacc[ns][1] * a0 + ob0.y * b0f) * li0;
            float o10 = (oacc[ns][2] * a1 + ob1.x * b1f) * li1;
            float o11 = (oacc[ns][3] * a1 + ob1.y * b1f) * li1;
            uint32_t hh, uu;
            split2h(o00, o01, hh, uu);
            *(uint32_t*)(Ahp + base + (size_t)(q0 + rl) * HID + col) = hh;
            *(uint32_t*)(Aup + base + (size_t)(q0 + rl) * HID + col) = uu;
            split2h(o10, o11, hh, uu);
            *(uint32_t*)(Ahp + base + (size_t)(q0 + rl + 8) * HID + col) = hh;
            *(uint32_t*)(Aup + base + (size_t)(q0 + rl + 8) * HID + col) = uu;
        }
    }
}

// ---------------------------------------------------------------------------
extern "C" void kernel_launch(void* const* d_in, const int* in_sizes, int n_in,
                              void* d_out, int out_size)
{
    const float* q    = (const float*)d_in[0];
    const float* k    = (const float*)d_in[1];
    const float* v    = (const float*)d_in[2];
    const float* mask = (const float*)d_in[3];
    const float* Wq   = (const float*)d_in[4];
    const float* bq   = (const float*)d_in[5];
    const float* Wk   = (const float*)d_in[6];
    const float* bk   = (const float*)d_in[7];
    const float* Wv   = (const float*)d_in[8];
    const float* bv   = (const float*)d_in[9];
    const float* Wo   = (const float*)d_in[10];
    const float* bo   = (const float*)d_in[11];
    float* out = (float*)d_out;

    __half *xqh, *xqu, *xkh, *xku, *xvh, *xvu;
    __half *wqh, *wqv, *wkh, *wkv, *wvh, *wvv, *woh, *wov;
    __half *Ah16, *Au16;
    __nv_bfloat16 *Qh, *Ql, *Kh, *Kl, *Vh, *Vl;
    cudaGetSymbolAddress((void**)&xqh, g_xqh); cudaGetSymbolAddress((void**)&xqu, g_xqu);
    cudaGetSymbolAddress((void**)&xkh, g_xkh); cudaGetSymbolAddress((void**)&xku, g_xku);
    cudaGetSymbolAddress((void**)&xvh, g_xvh); cudaGetSymbolAddress((void**)&xvu, g_xvu);
    cudaGetSymbolAddress((void**)&wqh, g_wqh); cudaGetSymbolAddress((void**)&wqv, g_wqv);
    cudaGetSymbolAddress((void**)&wkh, g_wkh); cudaGetSymbolAddress((void**)&wkv, g_wkv);
    cudaGetSymbolAddress((void**)&wvh, g_wvh); cudaGetSymbolAddress((void**)&wvv, g_wvv);
    cudaGetSymbolAddress((void**)&woh, g_woh); cudaGetSymbolAddress((void**)&wov, g_wov);
    cudaGetSymbolAddress((void**)&Qh,  g_Qh);  cudaGetSymbolAddress((void**)&Ql,  g_Ql);
    cudaGetSymbolAddress((void**)&Kh,  g_Kh);  cudaGetSymbolAddress((void**)&Kl,  g_Kl);
    cudaGetSymbolAddress((void**)&Vh,  g_Vh);  cudaGetSymbolAddress((void**)&Vl,  g_Vl);
    cudaGetSymbolAddress((void**)&Ah16, g_Ah16); cudaGetSymbolAddress((void**)&Au16, g_Au16);

    cudaFuncSetAttribute(flash_sk, cudaFuncAttributeMaxDynamicSharedMemorySize,
                         FLASH_SMEM);
    cudaFuncSetAttribute(gemm_h2<true>,  cudaFuncAttributeMaxDynamicSharedMemorySize,
                         GEMM_SMEM2);
    cudaFuncSetAttribute(gemm_h2<false>, cudaFuncAttributeMaxDynamicSharedMemorySize,
                         GEMM_SMEM2);

    const int n4x = M_TOT * HID / 4;
    const int n4w = HID * HID / 4;

    SplitBatch sbt;
    sbt.src[0] = q;  sbt.dh[0] = xqh; sbt.du[0] = xqu; sbt.n4[0] = n4x;
    sbt.src[1] = k;  sbt.dh[1] = xkh; sbt.du[1] = xku; sbt.n4[1] = n4x;
    sbt.src[2] = v;  sbt.dh[2] = xvh; sbt.du[2] = xvu; sbt.n4[2] = n4x;
    sbt.src[3] = Wq; sbt.dh[3] = wqh; sbt.du[3] = wqv; sbt.n4[3] = n4w;
    sbt.src[4] = Wk; sbt.dh[4] = wkh; sbt.du[4] = wkv; sbt.n4[4] = n4w;
    sbt.src[5] = Wv; sbt.dh[5] = wvh; sbt.du[5] = wvv; sbt.n4[5] = n4w;
    sbt.src[6] = Wo; sbt.dh[6] = woh; sbt.du[6] = wov; sbt.n4[6] = n4w;
    split_all<<<dim3(n4x / 256, 7), 256>>>(sbt);

    GemmBatch gqkv = {};
    gqkv.ah[0] = xqh; gqkv.au[0] = xqu; gqkv.wh[0] = wqh; gqkv.wv[0] = wqv;
    gqkv.bias[0] = bq; gqkv.ch[0] = Qh; gqkv.cl[0] = Ql; gqkv.sc[0] = 0.125f;
    gqkv.ah[1] = xkh; gqkv.au[1] = xku; gqkv.wh[1] = wkh; gqkv.wv[1] = wkv;
    gqkv.bias[1] = bk; gqkv.ch[1] = Kh; gqkv.cl[1] = Kl; gqkv.sc[1] = 1.0f;
    gqkv.ah[2] = xvh; gqkv.au[2] = xvu; gqkv.wh[2] = wvh; gqkv.wv[2] = wvv;
    gqkv.bias[2] = bv; gqkv.ch[2] = Vh; gqkv.cl[2] = Vl; gqkv.sc[2] = 1.0f;
    gemm_h2<true><<<dim3(HID / 128, M_TOT / 128, 3), 512, GEMM_SMEM2>>>(gqkv);

    flash_sk<<<dim3(S_LEN / 64, NH, BATCH), 256, FLASH_SMEM>>>(
        Qh, Ql, Kh, Kl, Vh, Vl, mask, Ah16, Au16);

    GemmBatch gout = {};
    gout.ah[0] = Ah16; gout.au[0] = Au16; gout.wh[0] = woh; gout.wv[0] = wov;
    gout.bias[0] = bo; gout.c32[0] = out; gout.sc[0] = 1.0f;
    gemm_h2<false><<<dim3(HID / 128, M_TOT / 128, 1), 512, GEMM_SMEM2>>>(gout);
}

// round 12
// speedup vs baseline: 3.3672x; 1.0280x over previous
#include <cuda_runtime.h>
#include <cuda_bf16.h>
#include <cuda_fp16.h>
#include <cstdint>
#include <math.h>

#define S_LEN 2048
#define BATCH 4
#define HID   1024
#define NH    16
#define DH    64
#define M_TOT (BATCH * S_LEN)      // 8192
#define FILLV (-10000000000000.0f)

#define BETA_C 0.984375f           // 1 - 2^-6
#define INVB   64.0f               // 1/beta

// Scratch (device globals: no allocations allowed)
// fp16 fold pairs for GEMM inputs
__device__ __half g_xqh[M_TOT * HID], g_xqu[M_TOT * HID];
__device__ __half g_xkh[M_TOT * HID], g_xku[M_TOT * HID];
__device__ __half g_xvh[M_TOT * HID], g_xvu[M_TOT * HID];
__device__ __half g_wqh[HID * HID], g_wqv[HID * HID];
__device__ __half g_wkh[HID * HID], g_wkv[HID * HID];
__device__ __half g_wvh[HID * HID], g_wvv[HID * HID];
__device__ __half g_woh[HID * HID], g_wov[HID * HID];
// fp16 fold pairs for flash: Q A-side, K/V B-side
__device__ __half g_Q16h[M_TOT * HID], g_Q16u[M_TOT * HID];
__device__ __half g_K16h[M_TOT * HID], g_K16v[M_TOT * HID];
__device__ __half g_V16h[M_TOT * HID], g_V16v[M_TOT * HID];
// flash output: fp16 A-side pair for the out-GEMM
__device__ __half g_A16h[M_TOT * HID], g_A16u[M_TOT * HID];

// ===========================================================================
// helpers
// ===========================================================================
__device__ __forceinline__ uint32_t smem_u32(const void* p) {
    uint32_t a;
    asm("{ .reg .u64 t; cvta.to.shared.u64 t, %1; cvt.u32.u64 %0, t; }"
        : "=r"(a) : "l"(p));
    return a;
}

#define LDSM_X4(r0, r1, r2, r3, addr)                                         \
    asm volatile("ldmatrix.sync.aligned.m8n8.x4.shared.b16 {%0,%1,%2,%3}, [%4];" \
                 : "=r"(r0), "=r"(r1), "=r"(r2), "=r"(r3) : "r"(addr))

#define LDSM_X4_T(r0, r1, r2, r3, addr)                                       \
    asm volatile("ldmatrix.sync.aligned.m8n8.x4.trans.shared.b16 {%0,%1,%2,%3}, [%4];" \
                 : "=r"(r0), "=r"(r1), "=r"(r2), "=r"(r3) : "r"(addr))

// fp16 mma
#define MMA16816H(d, a0, a1, a2, a3, b0, b1)                                  \
    asm volatile("mma.sync.aligned.m16n8k16.row.col.f32.f16.f16.f32 "         \
                 "{%0,%1,%2,%3}, {%4,%5,%6,%7}, {%8,%9}, {%0,%1,%2,%3};"      \
                 : "+f"((d)[0]), "+f"((d)[1]), "+f"((d)[2]), "+f"((d)[3])     \
                 : "r"(a0), "r"(a1), "r"(a2), "r"(a3), "r"(b0), "r"(b1))

#define CP_ASYNC16(dst, src)                                                  \
    asm volatile("cp.async.cg.shared.global [%0], [%1], 16;"                  \
                 :: "r"(dst), "l"(src) : "memory")
#define CP_COMMIT() asm volatile("cp.async.commit_group;" ::: "memory")
#define CP_WAIT(n)  asm volatile("cp.async.wait_group %0;" :: "n"(n) : "memory")

#define BAR_G(id) asm volatile("bar.sync %0, %1;" :: "r"(id), "r"(128) : "memory")

// fp16 A-side fold pair: h = rn16(x), u = rn16(x - (1-beta)*h)
__device__ __forceinline__ void split2h(float x, float y, uint32_t& h, uint32_t& u) {
    __half hx = __float2half_rn(x);
    __half hy = __float2half_rn(y);
    h = (uint32_t)__half_as_ushort(hx) | ((uint32_t)__half_as_ushort(hy) << 16);
    __half ux = __float2half_rn(fmaf(-BETA_C, __half2float(hx), x));
    __half uy = __float2half_rn(fmaf(-BETA_C, __half2float(hy), y));
    u = (uint32_t)__half_as_ushort(ux) | ((uint32_t)__half_as_ushort(uy) << 16);
}

// fp16 B-side fold pair: h = rn16(w), v = rn16((w - (1-beta)*h) * 64)
__device__ __forceinline__ void split2hw(float x, float y, uint32_t& h, uint32_t& v) {
    __half hx = __float2half_rn(x);
    __half hy = __float2half_rn(y);
    h = (uint32_t)__half_as_ushort(hx) | ((uint32_t)__half_as_ushort(hy) << 16);
    __half vx = __float2half_rn(fmaf(-BETA_C, __half2float(hx), x) * INVB);
    __half vy = __float2half_rn(fmaf(-BETA_C, __half2float(hy), y) * INVB);
    v = (uint32_t)__half_as_ushort(vx) | ((uint32_t)__half_as_ushort(vy) << 16);
}

// 128-byte-row XOR swizzle
__device__ __forceinline__ uint32_t off128(int row, int u) {
    return (uint32_t)(row * 128 + (((u ^ (row & 7))) << 4));
}

// ===========================================================================
// fused split pass: tensors 0..2 = A-side (inputs), 3..6 = W-side (weights)
// ===========================================================================
struct SplitBatch {
    const float* src[7];
    __half*      dh[7];
    __half*      du[7];
    int          n4[7];
};

__global__ void __launch_bounds__(256)
split_all(SplitBatch s)
{
    const int t = blockIdx.y;
    const int i = blockIdx.x * 256 + threadIdx.x;
    if (i < s.n4[t]) {
        float4 v = ((const float4*)s.src[t])[i];
        uint2 h, u;
        if (t < 3) {
            split2h(v.x, v.y, h.x, u.x);
            split2h(v.z, v.w, h.y, u.y);
        } else {
            split2hw(v.x, v.y, h.x, u.x);
            split2hw(v.z, v.w, h.y, u.y);
        }
        ((uint2*)s.dh[t])[i] = h;
        ((uint2*)s.du[t])[i] = u;
    }
}

// ===========================================================================
// GEMM v5: fp16 residual-fold, 8 warps / 64x32 warp tiles (LDSM:MMA = 12:32).
// D = (1-beta)*P + S. BK=64, 3-stage cp.async, batched over blockIdx.z.
// Epilogue modes: 0 = fp32, 1 = A-side fold pair, 2 = B-side fold pair.
// ===========================================================================
#define GK 1024
#define NCH2 16
#define GSTAGE2 65536
#define GEMM_SMEM2 (3 * GSTAGE2)

struct GemmBatch {
    const __half* ah[3];
    const __half* au[3];
    const __half* wh[3];
    const __half* wv[3];
    const float*  bias[3];
    __half*       ch[3];
    __half*       cu[3];
    float*        c32[3];
    float         sc[3];
    int           mode[3];
};

__global__ void __launch_bounds__(256)
gemm_h3(GemmBatch gb)
{
    extern __shared__ __align__(128) uint8_t smg[];
    const uint32_t sb = smem_u32(smg);
    const int tid  = threadIdx.x;
    const int lane = tid & 31;
    const int warp = tid >> 5;          // 0..7
    const int wm   = warp >> 2;         // 0..1
    const int wn   = warp & 3;          // 0..3
    const int bm   = blockIdx.y * 128;
    const int bn   = blockIdx.x * 128;
    const int z    = blockIdx.z;
    const int lr   = lane & 7;
    const int ml   = lane >> 3;

    const __half* srcs[4] = {
        gb.ah[z] + (size_t)bm * GK, gb.au[z] + (size_t)bm * GK,
        gb.wh[z] + (size_t)bn * GK, gb.wv[z] + (size_t)bn * GK };

    const int r0 = tid >> 3, g0 = tid & 7;   // 32 rows per j-step

    int rowA[4], xorA[4];
#pragma unroll
    for (int mt = 0; mt < 4; mt++) {
        int row = wm * 64 + mt * 16 + (ml & 1) * 8 + lr;
        rowA[mt] = row * 128;
        xorA[mt] = row & 7;
    }
    int rowW[2], xorW[2];
#pragma unroll
    for (int p = 0; p < 2; p++) {
        int row = wn * 32 + p * 16 + (ml >> 1) * 8 + lr;
        rowW[p] = row * 128;
        xorW[p] = row & 7;
    }
    const int gA = ml >> 1;
    const int gW = ml & 1;

    float accP[4][4][4], accS[4][4][4];
#pragma unroll
    for (int mt = 0; mt < 4; mt++)
#pragma unroll
        for (int nt = 0; nt < 4; nt++)
#pragma unroll
            for (int r = 0; r < 4; r++) { accP[mt][nt][r] = 0.0f; accS[mt][nt][r] = 0.0f; }

    auto issue = [&](int t) {
        int st = t; while (st >= 3) st -= 3;
        const uint32_t stg = sb + (uint32_t)st * GSTAGE2;
        const int kc = t * 64;
#pragma unroll
        for (int m = 0; m < 4; m++) {
            const __half* s = srcs[m] + kc + g0 * 8;
#pragma unroll
            for (int j = 0; j < 4; j++) {
                int row = r0 + j * 32;
                CP_ASYNC16(stg + m * 16384 + off128(row, g0),
                           s + (size_t)row * GK);
            }
        }
        CP_COMMIT();
    };

    issue(0);
    issue(1);

    for (int c = 0; c < NCH2; c++) {
        CP_WAIT(1);
        __syncthreads();
        if (c + 2 < NCH2) issue(c + 2);
        else              CP_COMMIT();

        int st = c; while (st >= 3) st -= 3;
        const uint32_t stg = sb + (uint32_t)st * GSTAGE2;

#pragma unroll
        for (int ks = 0; ks < 4; ks++) {
            uint32_t ah[4][4], ua[4][4], wh[2][4], vw[2][4];
#pragma unroll
            for (int mt = 0; mt < 4; mt++) {
                uint32_t off = (uint32_t)rowA[mt]
                             + (((uint32_t)((ks * 2 + gA) ^ xorA[mt])) << 4);
                LDSM_X4(ah[mt][0], ah[mt][1], ah[mt][2], ah[mt][3], stg + off);
                LDSM_X4(ua[mt][0], ua[mt][1], ua[mt][2], ua[mt][3], stg + 16384 + off);
            }
#pragma unroll
            for (int p = 0; p < 2; p++) {
                uint32_t off = (uint32_t)rowW[p]
                             + (((uint32_t)((ks * 2 + gW) ^ xorW[p])) << 4);
                LDSM_X4(wh[p][0], wh[p][1], wh[p][2], wh[p][3], stg + 32768 + off);
                LDSM_X4(vw[p][0], vw[p][1], vw[p][2], vw[p][3], stg + 49152 + off);
            }
#pragma unroll
            for (int mt = 0; mt < 4; mt++)
#pragma unroll
                for (int p = 0; p < 2; p++)
#pragma unroll
                    for (int j2 = 0; j2 < 2; j2++)
                        MMA16816H(accP[mt][2 * p + j2],
                                  ah[mt][0], ah[mt][1], ah[mt][2], ah[mt][3],
                                  wh[p][2 * j2], wh[p][2 * j2 + 1]);
#pragma unroll
            for (int mt = 0; mt < 4; mt++)
#pragma unroll
                for (int p = 0; p < 2; p++)
#pragma unroll
                    for (int j2 = 0; j2 < 2; j2++)
                        MMA16816H(accS[mt][2 * p + j2],
                                  ua[mt][0], ua[mt][1], ua[mt][2], ua[mt][3],
                                  vw[p][2 * j2], vw[p][2 * j2 + 1]);
        }
    }

    const float* bias = gb.bias[z];
    const float  sc   = gb.sc[z];
    const int    mode = gb.mode[z];
#pragma unroll
    for (int mt = 0; mt < 4; mt++) {
        int r0g = bm + wm * 64 + mt * 16 + (lane >> 2);
#pragma unroll
        for (int nt = 0; nt < 4; nt++) {
            int cg = bn + wn * 32 + nt * 8 + (lane & 3) * 2;
            float2 bz = *(const float2*)(bias + cg);
            float d0 = fmaf(BETA_C, accP[mt][nt][0], accS[mt][nt][0]);
            float d1 = fmaf(BETA_C, accP[mt][nt][1], accS[mt][nt][1]);
            float d2 = fmaf(BETA_C, accP[mt][nt][2], accS[mt][nt][2]);
            float d3 = fmaf(BETA_C, accP[mt][nt][3], accS[mt][nt][3]);
            float2 v0 = make_float2((d0 + bz.x) * sc, (d1 + bz.y) * sc);
            float2 v1 = make_float2((d2 + bz.x) * sc, (d3 + bz.y) * sc);
            if (mode == 0) {
                *(float2*)(gb.c32[z] + (size_t)r0g * HID + cg)       = v0;
                *(float2*)(gb.c32[z] + (size_t)(r0g + 8) * HID + cg) = v1;
            } else {
                uint32_t h, u;
                if (mode == 1) split2h(v0.x, v0.y, h, u);
                else           split2hw(v0.x, v0.y, h, u);
                *(uint32_t*)(gb.ch[z] + (size_t)r0g * HID + cg) = h;
                *(uint32_t*)(gb.cu[z] + (size_t)r0g * HID + cg) = u;
                if (mode == 1) split2h(v1.x, v1.y, h, u);
                else           split2hw(v1.x, v1.y, h, u);
                *(uint32_t*)(gb.ch[z] + (size_t)(r0g + 8) * HID + cg) = h;
                *(uint32_t*)(gb.cu[z] + (size_t)(r0g + 8) * HID + cg) = u;
            }
        }
    }
}

// ===========================================================================
// Split-KV flash attention, fp16 residual-fold for S and PV.
// Structure identical to round-11 (verified); MMAs 192 -> 128 per tile.
// ===========================================================================
#define XCH_M 148480
#define XCH_L 148736
#define XCH_O 148992
#define FLASH_SMEM 165376

__global__ void __launch_bounds__(256)
flash_sk(const __half* __restrict__ Qhp, const __half* __restrict__ Qup,
         const __half* __restrict__ Khp, const __half* __restrict__ Kvp,
         const __half* __restrict__ Vhp, const __half* __restrict__ Vvp,
         const float* __restrict__ maskg,
         __half* __restrict__ Ahp, __half* __restrict__ Aup)
{
    extern __shared__ __align__(128) uint8_t sbuf[];
    const uint32_t sb = smem_u32(sbuf);

    const int tid  = threadIdx.x;
    const int lane = tid & 31;
    const int w    = tid >> 5;
    const int lr   = lane & 7;
    const int ml   = lane >> 3;
    const int qb   = (int)gridDim.x - 1 - (int)blockIdx.x;
    const int h    = blockIdx.y;
    const int b    = blockIdx.z;
    const int q0   = qb * 64;
    const size_t base = ((size_t)b * S_LEN) * HID + (size_t)h * DH;

    // ---- stage Q (h@0, u@8192) ----
#pragma unroll
    for (int j = 0; j < 4; j++) {
        int f = tid + j * 256;
        int term = f >> 9;
        int c = f & 511;
        int row = c >> 3, qq = c & 7;
        CP_ASYNC16(sb + (uint32_t)term * 8192 + off128(row, qq),
                   (term ? Qup : Qhp) + base + (size_t)(q0 + row) * HID + qq * 8);
    }
    CP_COMMIT();
    CP_WAIT(0);
    __syncthreads();

    uint32_t qh[4][4], qu[4][4];
    {
        int row = (w & 3) * 16 + (ml & 1) * 8 + lr;
#pragma unroll
        for (int ks = 0; ks < 4; ks++) {
            uint32_t off = off128(row, ks * 2 + (ml >> 1));
            LDSM_X4(qh[ks][0], qh[ks][1], qh[ks][2], qh[ks][3], sb + off);
            LDSM_X4(qu[ks][0], qu[ks][1], qu[ks][2], qu[ks][3], sb + 8192 + off);
        }
    }

    const int g      = w >> 2;
    const int wg_tid = tid & 127;
    const int barid  = g + 1;

    auto issue_g = [&](int t) {
        if (t <= qb) {
            const int k0t = t * 64;
            const __half* bs[4] = {
                Khp + base + (size_t)k0t * HID,
                Kvp + base + (size_t)k0t * HID,
                Vhp + base + (size_t)k0t * HID,
                Vvp + base + (size_t)k0t * HID };
            const uint32_t stg = sb + 16384u + (uint32_t)g * 65536u
                               + (uint32_t)((t >> 1) & 1) * 32768u;
#pragma unroll
            for (int j = 0; j < 16; j++) {
                int f = wg_tid + j * 128;
                int m = f >> 9, row = (f >> 3) & 63, g0 = f & 7;
                CP_ASYNC16(stg + (uint32_t)m * 8192 + off128(row, g0),
                           bs[m] + (size_t)row * HID + g0 * 8);
            }
            if (wg_tid < 16)
                CP_ASYNC16(sb + 147456u + (uint32_t)(g * 2 + ((t >> 1) & 1)) * 256u
                               + wg_tid * 16,
                           maskg + (size_t)b * S_LEN + k0t + wg_tid * 4);
        }
        CP_COMMIT();
    };

    issue_g(g);
    issue_g(g + 2);

    float oP[8][4], oS[8][4];
#pragma unroll
    for (int ns = 0; ns < 8; ns++)
#pragma unroll
        for (int r = 0; r < 4; r++) { oP[ns][r] = 0.0f; oS[ns][r] = 0.0f; }
    float m0 = -INFINITY, m1 = -INFINITY, l0 = 0.0f, l1 = 0.0f;

    const int r0g  = q0 + (w & 3) * 16 + (lane >> 2);
    const int cloc = (lane & 3) * 2;

    for (int t = g; t <= qb; t += 2) {
        const int k0 = t * 64;
        CP_WAIT(1);
        BAR_G(barid);

        const uint32_t stg = sb + 16384u + (uint32_t)g * 65536u
                           + (uint32_t)((t >> 1) & 1) * 32768u;
        const uint32_t sKh = stg, sKv = stg + 8192;
        const uint32_t sVh = stg + 16384, sVv = stg + 24576;
        const float* smask = (const float*)(sbuf + 147456
                           + (g * 2 + ((t >> 1) & 1)) * 256);

        // ---- S = Q K^T (fold: 2 fp16 MMAs per step) ----
        float sP[8][4], sS[8][4];
#pragma unroll
        for (int nt = 0; nt < 8; nt++)
#pragma unroll
            for (int r = 0; r < 4; r++) { sP[nt][r] = 0.0f; sS[nt][r] = 0.0f; }

#pragma unroll
        for (int ks = 0; ks < 4; ks++) {
            uint32_t kh[4][4], kv[4][4];
            int rowb = (ml >> 1) * 8 + lr;
            int u    = ks * 2 + (ml & 1);
#pragma unroll
            for (int gg = 0; gg < 4; gg++) {
                int row = gg * 16 + rowb;
                uint32_t off = off128(row, u);
                LDSM_X4(kh[gg][0], kh[gg][1], kh[gg][2], kh[gg][3], sKh + off);
                LDSM_X4(kv[gg][0], kv[gg][1], kv[gg][2], kv[gg][3], sKv + off);
            }
#pragma unroll
            for (int gg = 0; gg < 4; gg++)
#pragma unroll
                for (int j2 = 0; j2 < 2; j2++)
                    MMA16816H(sP[2 * gg + j2], qh[ks][0], qh[ks][1], qh[ks][2], qh[ks][3],
                              kh[gg][2 * j2], kh[gg][2 * j2 + 1]);
#pragma unroll
            for (int gg = 0; gg < 4; gg++)
#pragma unroll
                for (int j2 = 0; j2 < 2; j2++)
                    MMA16816H(sS[2 * gg + j2], qu[ks][0], qu[ks][1], qu[ks][2], qu[ks][3],
                              kv[gg][2 * j2], kv[gg][2 * j2 + 1]);
        }

        // combine fold terms
        float sacc[8][4];
#pragma unroll
        for (int nt = 0; nt < 8; nt++)
#pragma unroll
            for (int r = 0; r < 4; r++)
                sacc[nt][r] = fmaf(BETA_C, sP[nt][r], sS[nt][r]);

        // ---- mask (+ causal only on diagonal tile) + online softmax ----
        float rm0 = -INFINITY, rm1 = -INFINITY;
        if (t == qb) {
#pragma unroll
            for (int nt = 0; nt < 8; nt++) {
                int c0 = nt * 8 + cloc;
                float mk0 = smask[c0], mk1 = smask[c0 + 1];
                int jg0 = k0 + c0, jg1 = jg0 + 1;
                sacc[nt][0] = (jg0 > r0g     || mk0 == 0.0f) ? FILLV : sacc[nt][0];
                sacc[nt][1] = (jg1 > r0g     || mk1 == 0.0f) ? FILLV : sacc[nt][1];
                sacc[nt][2] = (jg0 > r0g + 8 || mk0 == 0.0f) ? FILLV : sacc[nt][2];
                sacc[nt][3] = (jg1 > r0g + 8 || mk1 == 0.0f) ? FILLV : sacc[nt][3];
                rm0 = fmaxf(rm0, fmaxf(sacc[nt][0], sacc[nt][1]));
                rm1 = fmaxf(rm1, fmaxf(sacc[nt][2], sacc[nt][3]));
            }
        } else {
#pragma unroll
            for (int nt = 0; nt < 8; nt++) {
                int c0 = nt * 8 + cloc;
                float mk0 = smask[c0], mk1 = smask[c0 + 1];
                sacc[nt][0] = (mk0 == 0.0f) ? FILLV : sacc[nt][0];
                sacc[nt][1] = (mk1 == 0.0f) ? FILLV : sacc[nt][1];
                sacc[nt][2] = (mk0 == 0.0f) ? FILLV : sacc[nt][2];
                sacc[nt][3] = (mk1 == 0.0f) ? FILLV : sacc[nt][3];
                rm0 = fmaxf(rm0, fmaxf(sacc[nt][0], sacc[nt][1]));
                rm1 = fmaxf(rm1, fmaxf(sacc[nt][2], sacc[nt][3]));
            }
        }
        rm0 = fmaxf(rm0, __shfl_xor_sync(0xffffffffu, rm0, 1));
        rm0 = fmaxf(rm0, __shfl_xor_sync(0xffffffffu, rm0, 2));
        rm1 = fmaxf(rm1, __shfl_xor_sync(0xffffffffu, rm1, 1));
        rm1 = fmaxf(rm1, __shfl_xor_sync(0xffffffffu, rm1, 2));

        float mn0 = fmaxf(m0, rm0), mn1 = fmaxf(m1, rm1);
        float corr0 = __expf(m0 - mn0), corr1 = __expf(m1 - mn1);
        m0 = mn0; m1 = mn1;

        float rs0 = 0.0f, rs1 = 0.0f;
#pragma unroll
        for (int nt = 0; nt < 8; nt++) {
            sacc[nt][0] = __expf(sacc[nt][0] - mn0);
            sacc[nt][1] = __expf(sacc[nt][1] - mn0);
            sacc[nt][2] = __expf(sacc[nt][2] - mn1);
            sacc[nt][3] = __expf(sacc[nt][3] - mn1);
            rs0 += sacc[nt][0] + sacc[nt][1];
            rs1 += sacc[nt][2] + sacc[nt][3];
        }
        rs0 += __shfl_xor_sync(0xffffffffu, rs0, 1);
        rs0 += __shfl_xor_sync(0xffffffffu, rs0, 2);
        rs1 += __shfl_xor_sync(0xffffffffu, rs1, 1);
        rs1 += __shfl_xor_sync(0xffffffffu, rs1, 2);
        l0 = l0 * corr0 + rs0;
        l1 = l1 * corr1 + rs1;
#pragma unroll
        for (int ns = 0; ns < 8; ns++) {
            oP[ns][0] *= corr0; oP[ns][1] *= corr0;
            oP[ns][2] *= corr1; oP[ns][3] *= corr1;
            oS[ns][0] *= corr0; oS[ns][1] *= corr0;
            oS[ns][2] *= corr1; oS[ns][3] *= corr1;
        }

        // ---- O += P V (fold: 2 fp16 MMAs per step) ----
#pragma unroll
        for (int ks = 0; ks < 4; ks++) {
            uint32_t ph[4], pu[4];
            split2h(sacc[2 * ks][0],     sacc[2 * ks][1],     ph[0], pu[0]);
            split2h(sacc[2 * ks][2],     sacc[2 * ks][3],     ph[1], pu[1]);
            split2h(sacc[2 * ks + 1][0], sacc[2 * ks + 1][1], ph[2], pu[2]);
            split2h(sacc[2 * ks + 1][2], sacc[2 * ks + 1][3], ph[3], pu[3]);

            int rowv = ks * 16 + (ml & 1) * 8 + lr;
#pragma unroll
            for (int np = 0; np < 4; np++) {
                int u = np * 2 + (ml >> 1);
                uint32_t off = off128(rowv, u);
                uint32_t vh[4], vv[4];
                LDSM_X4_T(vh[0], vh[1], vh[2], vh[3], sVh + off);
                LDSM_X4_T(vv[0], vv[1], vv[2], vv[3], sVv + off);
                MMA16816H(oP[2 * np],     ph[0], ph[1], ph[2], ph[3], vh[0], vh[1]);
                MMA16816H(oP[2 * np + 1], ph[0], ph[1], ph[2], ph[3], vh[2], vh[3]);
                MMA16816H(oS[2 * np],     pu[0], pu[1], pu[2], pu[3], vv[0], vv[1]);
                MMA16816H(oS[2 * np + 1], pu[0], pu[1], pu[2], pu[3], vv[2], vv[3]);
            }
        }

        BAR_G(barid);
        issue_g(t + 4);
    }

    // combine fold terms for O
    float oacc[8][4];
#pragma unroll
    for (int ns = 0; ns < 8; ns++)
#pragma unroll
        for (int r = 0; r < 4; r++)
            oacc[ns][r] = fmaf(BETA_C, oP[ns][r], oS[ns][r]);

    // ---- merge: group B publishes, group A combines + writes fp16 fold ----
    float* XM = (float*)(sbuf + XCH_M);
    float* XL = (float*)(sbuf + XCH_L);
    float* XO = (float*)(sbuf + XCH_O);
    const int rl = (w & 3) * 16 + (lane >> 2);

    if (g == 1) {
        if ((lane & 3) == 0) {
            XM[rl] = m0; XM[rl + 8] = m1;
            XL[rl] = l0; XL[rl + 8] = l1;
        }
#pragma unroll
        for (int ns = 0; ns < 8; ns++) {
            int col = ns * 8 + cloc;
            *(float2*)&XO[rl * 64 + col]       = make_float2(oacc[ns][0], oacc[ns][1]);
            *(float2*)&XO[(rl + 8) * 64 + col] = make_float2(oacc[ns][2], oacc[ns][3]);
        }
    }
    __syncthreads();
    if (g == 0) {
        float mB0 = XM[rl], mB1 = XM[rl + 8];
        float lB0 = XL[rl], lB1 = XL[rl + 8];
        float mm0 = fmaxf(m0, mB0), mm1 = fmaxf(m1, mB1);
        float a0 = __expf(m0 - mm0), b0f = __expf(mB0 - mm0);
        float a1 = __expf(m1 - mm1), b1f = __expf(mB1 - mm1);
        float li0 = 1.0f / (l0 * a0 + lB0 * b0f);
        float li1 = 1.0f / (l1 * a1 + lB1 * b1f);
#pragma unroll
        for (int ns = 0; ns < 8; ns++) {
            int col = ns * 8 + cloc;
            float2 ob0 = *(const float2*)&XO[rl * 64 + col];
            float2 ob1 = *(const float2*)&XO[(rl + 8) * 64 + col];
            float o00 = (oacc[ns][0] * a0 + ob0.x * b0f) * li0;
            float o01 = (oacc[ns][1] * a0 + ob0.y * b0f) * li0;
            float o10 = (oacc[ns][2] * a1 + ob1.x * b1f) * li1;
            float o11 = (oacc[ns][3] * a1 + ob1.y * b1f) * li1;
            uint32_t hh, uu;
            split2h(o00, o01, hh, uu);
            *(uint32_t*)(Ahp + base + (size_t)(q0 + rl) * HID + col) = hh;
            *(uint32_t*)(Aup + base + (size_t)(q0 + rl) * HID + col) = uu;
            split2h(o10, o11, hh, uu);
            *(uint32_t*)(Ahp + base + (size_t)(q0 + rl + 8) * HID + col) = hh;
            *(uint32_t*)(Aup + base + (size_t)(q0 + rl + 8) * HID + col) = uu;
        }
    }
}

// ---------------------------------------------------------------------------
extern "C" void kernel_launch(void* const* d_in, const int* in_sizes, int n_in,
                              void* d_out, int out_size)
{
    const float* q    = (const float*)d_in[0];
    const float* k    = (const float*)d_in[1];
    const float* v    = (const float*)d_in[2];
    const float* mask = (const float*)d_in[3];
    const float* Wq   = (const float*)d_in[4];
    const float* bq   = (const float*)d_in[5];
    const float* Wk   = (const float*)d_in[6];
    const float* bk   = (const float*)d_in[7];
    const float* Wv   = (const float*)d_in[8];
    const float* bv   = (const float*)d_in[9];
    const float* Wo   = (const float*)d_in[10];
    const float* bo   = (const float*)d_in[11];
    float* out = (float*)d_out;

    __half *xqh, *xqu, *xkh, *xku, *xvh, *xvu;
    __half *wqh, *wqv, *wkh, *wkv, *wvh, *wvv, *woh, *wov;
    __half *Q16h, *Q16u, *K16h, *K16v, *V16h, *V16v, *A16h, *A16u;
    cudaGetSymbolAddress((void**)&xqh, g_xqh); cudaGetSymbolAddress((void**)&xqu, g_xqu);
    cudaGetSymbolAddress((void**)&xkh, g_xkh); cudaGetSymbolAddress((void**)&xku, g_xku);
    cudaGetSymbolAddress((void**)&xvh, g_xvh); cudaGetSymbolAddress((void**)&xvu, g_xvu);
    cudaGetSymbolAddress((void**)&wqh, g_wqh); cudaGetSymbolAddress((void**)&wqv, g_wqv);
    cudaGetSymbolAddress((void**)&wkh, g_wkh); cudaGetSymbolAddress((void**)&wkv, g_wkv);
    cudaGetSymbolAddress((void**)&wvh, g_wvh); cudaGetSymbolAddress((void**)&wvv, g_wvv);
    cudaGetSymbolAddress((void**)&woh, g_woh); cudaGetSymbolAddress((void**)&wov, g_wov);
    cudaGetSymbolAddress((void**)&Q16h, g_Q16h); cudaGetSymbolAddress((void**)&Q16u, g_Q16u);
    cudaGetSymbolAddress((void**)&K16h, g_K16h); cudaGetSymbolAddress((void**)&K16v, g_K16v);
    cudaGetSymbolAddress((void**)&V16h, g_V16h); cudaGetSymbolAddress((void**)&V16v, g_V16v);
    cudaGetSymbolAddress((void**)&A16h, g_A16h); cudaGetSymbolAddress((void**)&A16u, g_A16u);

    cudaFuncSetAttribute(flash_sk, cudaFuncAttributeMaxDynamicSharedMemorySize,
                         FLASH_SMEM);
    cudaFuncSetAttribute(gemm_h3, cudaFuncAttributeMaxDynamicSharedMemorySize,
                         GEMM_SMEM2);

    const int n4x = M_TOT * HID / 4;
    const int n4w = HID * HID / 4;

    SplitBatch sbt;
    sbt.src[0] = q;  sbt.dh[0] = xqh; sbt.du[0] = xqu; sbt.n4[0] = n4x;
    sbt.src[1] = k;  sbt.dh[1] = xkh; sbt.du[1] = xku; sbt.n4[1] = n4x;
    sbt.src[2] = v;  sbt.dh[2] = xvh; sbt.du[2] = xvu; sbt.n4[2] = n4x;
    sbt.src[3] = Wq; sbt.dh[3] = wqh; sbt.du[3] = wqv; sbt.n4[3] = n4w;
    sbt.src[4] = Wk; sbt.dh[4] = wkh; sbt.du[4] = wkv; sbt.n4[4] = n4w;
    sbt.src[5] = Wv; sbt.dh[5] = wvh; sbt.du[5] = wvv; sbt.n4[5] = n4w;
    sbt.src[6] = Wo; sbt.dh[6] = woh; sbt.du[6] = wov; sbt.n4[6] = n4w;
    split_all<<<dim3(n4x / 256, 7), 256>>>(sbt);

    GemmBatch gqkv = {};
    gqkv.ah[0] = xqh; gqkv.au[0] = xqu; gqkv.wh[0] = wqh; gqkv.wv[0] = wqv;
    gqkv.bias[0] = bq; gqkv.ch[0] = Q16h; gqkv.cu[0] = Q16u;
    gqkv.sc[0] = 0.125f; gqkv.mode[0] = 1;    // Q: A-side pair
    gqkv.ah[1] = xkh; gqkv.au[1] = xku; gqkv.wh[1] = wkh; gqkv.wv[1] = wkv;
    gqkv.bias[1] = bk; gqkv.ch[1] = K16h; gqkv.cu[1] = K16v;
    gqkv.sc[1] = 1.0f; gqkv.mode[1] = 2;      // K: B-side pair
    gqkv.ah[2] = xvh; gqkv.au[2] = xvu; gqkv.wh[2] = wvh; gqkv.wv[2] = wvv;
    gqkv.bias[2] = bv; gqkv.ch[2] = V16h; gqkv.cu[2] = V16v;
    gqkv.sc[2] = 1.0f; gqkv.mode[2] = 2;      // V: B-side pair
    gemm_h3<<<dim3(HID / 128, M_TOT / 128, 3), 256, GEMM_SMEM2>>>(gqkv);

    flash_sk<<<dim3(S_LEN / 64, NH, BATCH), 256, FLASH_SMEM>>>(
        Q16h, Q16u, K16h, K16v, V16h, V16v, mask, A16h, A16u);

    GemmBatch gout = {};
    gout.ah[0] = A16h; gout.au[0] = A16u; gout.wh[0] = woh; gout.wv[0] = wov;
    gout.bias[0] = bo; gout.c32[0] = out; gout.sc[0] = 1.0f; gout.mode[0] = 0;
    gemm_h3<<<dim3(HID / 128, M_TOT / 128, 1), 256, GEMM_SMEM2>>>(gout);
}

// round 13
// speedup vs baseline: 3.5142x; 1.0437x over previous
#include <cuda_runtime.h>
#include <cuda_bf16.h>
#include <cuda_fp16.h>
#include <cstdint>
#include <math.h>

#define S_LEN 2048
#define BATCH 4
#define HID   1024
#define NH    16
#define DH    64
#define M_TOT (BATCH * S_LEN)      // 8192
#define FILLV (-10000000000000.0f)

#define BETA_C 0.984375f           // 1 - 2^-6
#define INVB   64.0f               // 1/beta

// Scratch (device globals: no allocations allowed)
__device__ __half g_xqh[M_TOT * HID], g_xqu[M_TOT * HID];
__device__ __half g_xkh[M_TOT * HID], g_xku[M_TOT * HID];
__device__ __half g_xvh[M_TOT * HID], g_xvu[M_TOT * HID];
__device__ __half g_wqh[HID * HID], g_wqv[HID * HID];
__device__ __half g_wkh[HID * HID], g_wkv[HID * HID];
__device__ __half g_wvh[HID * HID], g_wvv[HID * HID];
__device__ __half g_woh[HID * HID], g_wov[HID * HID];
__device__ __half g_Q16h[M_TOT * HID], g_Q16u[M_TOT * HID];
__device__ __half g_K16h[M_TOT * HID], g_K16v[M_TOT * HID];
__device__ __half g_V16h[M_TOT * HID], g_V16v[M_TOT * HID];
__device__ __half g_A16h[M_TOT * HID], g_A16u[M_TOT * HID];

// ===========================================================================
// helpers
// ===========================================================================
__device__ __forceinline__ uint32_t smem_u32(const void* p) {
    uint32_t a;
    asm("{ .reg .u64 t; cvta.to.shared.u64 t, %1; cvt.u32.u64 %0, t; }"
        : "=r"(a) : "l"(p));
    return a;
}

#define LDSM_X4(r0, r1, r2, r3, addr)                                         \
    asm volatile("ldmatrix.sync.aligned.m8n8.x4.shared.b16 {%0,%1,%2,%3}, [%4];" \
                 : "=r"(r0), "=r"(r1), "=r"(r2), "=r"(r3) : "r"(addr))

#define LDSM_X4_T(r0, r1, r2, r3, addr)                                       \
    asm volatile("ldmatrix.sync.aligned.m8n8.x4.trans.shared.b16 {%0,%1,%2,%3}, [%4];" \
                 : "=r"(r0), "=r"(r1), "=r"(r2), "=r"(r3) : "r"(addr))

#define MMA16816H(d, a0, a1, a2, a3, b0, b1)                                  \
    asm volatile("mma.sync.aligned.m16n8k16.row.col.f32.f16.f16.f32 "         \
                 "{%0,%1,%2,%3}, {%4,%5,%6,%7}, {%8,%9}, {%0,%1,%2,%3};"      \
                 : "+f"((d)[0]), "+f"((d)[1]), "+f"((d)[2]), "+f"((d)[3])     \
                 : "r"(a0), "r"(a1), "r"(a2), "r"(a3), "r"(b0), "r"(b1))

#define CP_ASYNC16(dst, src)                                                  \
    asm volatile("cp.async.cg.shared.global [%0], [%1], 16;"                  \
                 :: "r"(dst), "l"(src) : "memory")
#define CP_COMMIT() asm volatile("cp.async.commit_group;" ::: "memory")
#define CP_WAIT(n)  asm volatile("cp.async.wait_group %0;" :: "n"(n) : "memory")

#define BAR_G(id) asm volatile("bar.sync %0, %1;" :: "r"(id), "r"(128) : "memory")

// fp16 A-side fold pair: h = rn16(x), u = rn16(x - (1-beta)*h)
__device__ __forceinline__ void split2h(float x, float y, uint32_t& h, uint32_t& u) {
    __half hx = __float2half_rn(x);
    __half hy = __float2half_rn(y);
    h = (uint32_t)__half_as_ushort(hx) | ((uint32_t)__half_as_ushort(hy) << 16);
    __half ux = __float2half_rn(fmaf(-BETA_C, __half2float(hx), x));
    __half uy = __float2half_rn(fmaf(-BETA_C, __half2float(hy), y));
    u = (uint32_t)__half_as_ushort(ux) | ((uint32_t)__half_as_ushort(uy) << 16);
}

// fp16 B-side fold pair: h = rn16(w), v = rn16((w - (1-beta)*h) * 64)
__device__ __forceinline__ void split2hw(float x, float y, uint32_t& h, uint32_t& v) {
    __half hx = __float2half_rn(x);
    __half hy = __float2half_rn(y);
    h = (uint32_t)__half_as_ushort(hx) | ((uint32_t)__half_as_ushort(hy) << 16);
    __half vx = __float2half_rn(fmaf(-BETA_C, __half2float(hx), x) * INVB);
    __half vy = __float2half_rn(fmaf(-BETA_C, __half2float(hy), y) * INVB);
    v = (uint32_t)__half_as_ushort(vx) | ((uint32_t)__half_as_ushort(vy) << 16);
}

// 128-byte-row XOR swizzle
__device__ __forceinline__ uint32_t off128(int row, int u) {
    return (uint32_t)(row * 128 + (((u ^ (row & 7))) << 4));
}

// ===========================================================================
// fused split pass: tensors 0..2 = A-side (inputs), 3..6 = W-side (weights)
// ===========================================================================
struct SplitBatch {
    const float* src[7];
    __half*      dh[7];
    __half*      du[7];
    int          n4[7];
};

__global__ void __launch_bounds__(256)
split_all(SplitBatch s)
{
    const int t = blockIdx.y;
    const int i = blockIdx.x * 256 + threadIdx.x;
    if (i < s.n4[t]) {
        float4 v = ((const float4*)s.src[t])[i];
        uint2 h, u;
        if (t < 3) {
            split2h(v.x, v.y, h.x, u.x);
            split2h(v.z, v.w, h.y, u.y);
        } else {
            split2hw(v.x, v.y, h.x, u.x);
            split2hw(v.z, v.w, h.y, u.y);
        }
        ((uint2*)s.dh[t])[i] = h;
        ((uint2*)s.du[t])[i] = u;
    }
}

// ===========================================================================
// GEMM v6: fp16 residual-fold, CTA tile 128x64, BK=64, 2-stage cp.async,
// 48KB/stage -> 96KB smem -> 2 CTAs/SM (peer CTA hides per-chunk overhead).
// 8 warps in 4x2, warp tile 32x32. D = (1-beta)*P + S.
// Stage layout: Ah@0(16K) Au@16K Wh@32K(8K) Wv@40K.
// Epilogue modes: 0 = fp32, 1 = A-side fold pair, 2 = B-side fold pair.
// ===========================================================================
#define GK 1024
#define NCH2 16
#define GSTAGE3 49152
#define GEMM_SMEM3 (2 * GSTAGE3)    // 98304

struct GemmBatch {
    const __half* ah[3];
    const __half* au[3];
    const __half* wh[3];
    const __half* wv[3];
    const float*  bias[3];
    __half*       ch[3];
    __half*       cu[3];
    float*        c32[3];
    float         sc[3];
    int           mode[3];
};

__global__ void __launch_bounds__(256, 2)
gemm_h4(GemmBatch gb)
{
    extern __shared__ __align__(128) uint8_t smg[];
    const uint32_t sb = smem_u32(smg);
    const int tid  = threadIdx.x;
    const int lane = tid & 31;
    const int warp = tid >> 5;          // 0..7
    const int wm   = warp >> 1;         // 0..3
    const int wn   = warp & 1;          // 0..1
    const int bm   = blockIdx.y * 128;
    const int bn   = blockIdx.x * 64;
    const int z    = blockIdx.z;
    const int lr   = lane & 7;
    const int ml   = lane >> 3;

    const __half* srcs[4] = {
        gb.ah[z] + (size_t)bm * GK, gb.au[z] + (size_t)bm * GK,
        gb.wh[z] + (size_t)bn * GK, gb.wv[z] + (size_t)bn * GK };

    const int r0 = tid >> 3, g0 = tid & 7;   // 32 rows per j-step

    int rowA[2], xorA[2];
#pragma unroll
    for (int mt = 0; mt < 2; mt++) {
        int row = wm * 32 + mt * 16 + (ml & 1) * 8 + lr;
        rowA[mt] = row * 128;
        xorA[mt] = row & 7;
    }
    int rowW[2], xorW[2];
#pragma unroll
    for (int p = 0; p < 2; p++) {
        int row = wn * 32 + p * 16 + (ml >> 1) * 8 + lr;
        rowW[p] = row * 128;
        xorW[p] = row & 7;
    }
    const int gA = ml >> 1;
    const int gW = ml & 1;

    float accP[2][4][4], accS[2][4][4];
#pragma unroll
    for (int mt = 0; mt < 2; mt++)
#pragma unroll
        for (int nt = 0; nt < 4; nt++)
#pragma unroll
            for (int r = 0; r < 4; r++) { accP[mt][nt][r] = 0.0f; accS[mt][nt][r] = 0.0f; }

    auto issue = [&](int t) {
        const uint32_t stg = sb + (uint32_t)(t & 1) * GSTAGE3;
        const int kc = t * 64;
        // A terms: 128 rows x 8 granules = 1024 -> 4 per thread
#pragma unroll
        for (int m = 0; m < 2; m++) {
            const __half* s = srcs[m] + kc + g0 * 8;
#pragma unroll
            for (int j = 0; j < 4; j++) {
                int row = r0 + j * 32;
                CP_ASYNC16(stg + m * 16384 + off128(row, g0),
                           s + (size_t)row * GK);
            }
        }
        // W terms: 64 rows x 8 granules = 512 -> 2 per thread
#pragma unroll
        for (int m = 0; m < 2; m++) {
            const __half* s = srcs[2 + m] + kc + g0 * 8;
#pragma unroll
            for (int j = 0; j < 2; j++) {
                int row = r0 + j * 32;
                CP_ASYNC16(stg + 32768 + m * 8192 + off128(row, g0),
                           s + (size_t)row * GK);
            }
        }
        CP_COMMIT();
    };

    issue(0);
    issue(1);

    for (int c = 0; c < NCH2; c++) {
        CP_WAIT(1);
        __syncthreads();

        const uint32_t stg = sb + (uint32_t)(c & 1) * GSTAGE3;

#pragma unroll
        for (int ks = 0; ks < 4; ks++) {
            uint32_t ah[2][4], ua[2][4], wh[2][4], vw[2][4];
#pragma unroll
            for (int mt = 0; mt < 2; mt++) {
                uint32_t off = (uint32_t)rowA[mt]
                             + (((uint32_t)((ks * 2 + gA) ^ xorA[mt])) << 4);
                LDSM_X4(ah[mt][0], ah[mt][1], ah[mt][2], ah[mt][3], stg + off);
                LDSM_X4(ua[mt][0], ua[mt][1], ua[mt][2], ua[mt][3], stg + 16384 + off);
            }
#pragma unroll
            for (int p = 0; p < 2; p++) {
                uint32_t off = (uint32_t)rowW[p]
                             + (((uint32_t)((ks * 2 + gW) ^ xorW[p])) << 4);
                LDSM_X4(wh[p][0], wh[p][1], wh[p][2], wh[p][3], stg + 32768 + off);
                LDSM_X4(vw[p][0], vw[p][1], vw[p][2], vw[p][3], stg + 40960 + off);
            }
#pragma unroll
            for (int mt = 0; mt < 2; mt++)
#pragma unroll
                for (int p = 0; p < 2; p++)
#pragma unroll
                    for (int j2 = 0; j2 < 2; j2++)
                        MMA16816H(accP[mt][2 * p + j2],
                                  ah[mt][0], ah[mt][1], ah[mt][2], ah[mt][3],
                                  wh[p][2 * j2], wh[p][2 * j2 + 1]);
#pragma unroll
            for (int mt = 0; mt < 2; mt++)
#pragma unroll
                for (int p = 0; p < 2; p++)
#pragma unroll
                    for (int j2 = 0; j2 < 2; j2++)
                        MMA16816H(accS[mt][2 * p + j2],
                                  ua[mt][0], ua[mt][1], ua[mt][2], ua[mt][3],
                                  vw[p][2 * j2], vw[p][2 * j2 + 1]);
        }

        __syncthreads();                 // all reads done before refilling stage
        if (c + 2 < NCH2) issue(c + 2);
        else              CP_COMMIT();   // keep group count uniform
    }

    const float* bias = gb.bias[z];
    const float  sc   = gb.sc[z];
    const int    mode = gb.mode[z];
#pragma unroll
    for (int mt = 0; mt < 2; mt++) {
        int r0g = bm + wm * 32 + mt * 16 + (lane >> 2);
#pragma unroll
        for (int nt = 0; nt < 4; nt++) {
            int cg = bn + wn * 32 + nt * 8 + (lane & 3) * 2;
            float2 bz = *(const float2*)(bias + cg);
            float d0 = fmaf(BETA_C, accP[mt][nt][0], accS[mt][nt][0]);
            float d1 = fmaf(BETA_C, accP[mt][nt][1], accS[mt][nt][1]);
            float d2 = fmaf(BETA_C, accP[mt][nt][2], accS[mt][nt][2]);
            float d3 = fmaf(BETA_C, accP[mt][nt][3], accS[mt][nt][3]);
            float2 v0 = make_float2((d0 + bz.x) * sc, (d1 + bz.y) * sc);
            float2 v1 = make_float2((d2 + bz.x) * sc, (d3 + bz.y) * sc);
            if (mode == 0) {
                *(float2*)(gb.c32[z] + (size_t)r0g * HID + cg)       = v0;
                *(float2*)(gb.c32[z] + (size_t)(r0g + 8) * HID + cg) = v1;
            } else {
                uint32_t h, u;
                if (mode == 1) split2h(v0.x, v0.y, h, u);
                else           split2hw(v0.x, v0.y, h, u);
                *(uint32_t*)(gb.ch[z] + (size_t)r0g * HID + cg) = h;
                *(uint32_t*)(gb.cu[z] + (size_t)r0g * HID + cg) = u;
                if (mode == 1) split2h(v1.x, v1.y, h, u);
                else           split2hw(v1.x, v1.y, h, u);
                *(uint32_t*)(gb.ch[z] + (size_t)(r0g + 8) * HID + cg) = h;
                *(uint32_t*)(gb.cu[z] + (size_t)(r0g + 8) * HID + cg) = u;
            }
        }
    }
}

// ===========================================================================
// Split-KV flash attention, fp16 residual-fold (round-12 verified, unchanged).
// ===========================================================================
#define XCH_M 148480
#define XCH_L 148736
#define XCH_O 148992
#define FLASH_SMEM 165376

__global__ void __launch_bounds__(256)
flash_sk(const __half* __restrict__ Qhp, const __half* __restrict__ Qup,
         const __half* __restrict__ Khp, const __half* __restrict__ Kvp,
         const __half* __restrict__ Vhp, const __half* __restrict__ Vvp,
         const float* __restrict__ maskg,
         __half* __restrict__ Ahp, __half* __restrict__ Aup)
{
    extern __shared__ __align__(128) uint8_t sbuf[];
    const uint32_t sb = smem_u32(sbuf);

    const int tid  = threadIdx.x;
    const int lane = tid & 31;
    const int w    = tid >> 5;
    const int lr   = lane & 7;
    const int ml   = lane >> 3;
    const int qb   = (int)gridDim.x - 1 - (int)blockIdx.x;
    const int h    = blockIdx.y;
    const int b    = blockIdx.z;
    const int q0   = qb * 64;
    const size_t base = ((size_t)b * S_LEN) * HID + (size_t)h * DH;

#pragma unroll
    for (int j = 0; j < 4; j++) {
        int f = tid + j * 256;
        int term = f >> 9;
        int c = f & 511;
        int row = c >> 3, qq = c & 7;
        CP_ASYNC16(sb + (uint32_t)term * 8192 + off128(row, qq),
                   (term ? Qup : Qhp) + base + (size_t)(q0 + row) * HID + qq * 8);
    }
    CP_COMMIT();
    CP_WAIT(0);
    __syncthreads();

    uint32_t qh[4][4], qu[4][4];
    {
        int row = (w & 3) * 16 + (ml & 1) * 8 + lr;
#pragma unroll
        for (int ks = 0; ks < 4; ks++) {
            uint32_t off = off128(row, ks * 2 + (ml >> 1));
            LDSM_X4(qh[ks][0], qh[ks][1], qh[ks][2], qh[ks][3], sb + off);
            LDSM_X4(qu[ks][0], qu[ks][1], qu[ks][2], qu[ks][3], sb + 8192 + off);
        }
    }

    const int g      = w >> 2;
    const int wg_tid = tid & 127;
    const int barid  = g + 1;

    auto issue_g = [&](int t) {
        if (t <= qb) {
            const int k0t = t * 64;
            const __half* bs[4] = {
                Khp + base + (size_t)k0t * HID,
                Kvp + base + (size_t)k0t * HID,
                Vhp + base + (size_t)k0t * HID,
                Vvp + base + (size_t)k0t * HID };
            const uint32_t stg = sb + 16384u + (uint32_t)g * 65536u
                               + (uint32_t)((t >> 1) & 1) * 32768u;
#pragma unroll
            for (int j = 0; j < 16; j++) {
                int f = wg_tid + j * 128;
                int m = f >> 9, row = (f >> 3) & 63, g0 = f & 7;
                CP_ASYNC16(stg + (uint32_t)m * 8192 + off128(row, g0),
                           bs[m] + (size_t)row * HID + g0 * 8);
            }
            if (wg_tid < 16)
                CP_ASYNC16(sb + 147456u + (uint32_t)(g * 2 + ((t >> 1) & 1)) * 256u
                               + wg_tid * 16,
                           maskg + (size_t)b * S_LEN + k0t + wg_tid * 4);
        }
        CP_COMMIT();
    };

    issue_g(g);
    issue_g(g + 2);

    float oP[8][4], oS[8][4];
#pragma unroll
    for (int ns = 0; ns < 8; ns++)
#pragma unroll
        for (int r = 0; r < 4; r++) { oP[ns][r] = 0.0f; oS[ns][r] = 0.0f; }
    float m0 = -INFINITY, m1 = -INFINITY, l0 = 0.0f, l1 = 0.0f;

    const int r0g  = q0 + (w & 3) * 16 + (lane >> 2);
    const int cloc = (lane & 3) * 2;

    for (int t = g; t <= qb; t += 2) {
        const int k0 = t * 64;
        CP_WAIT(1);
        BAR_G(barid);

        const uint32_t stg = sb + 16384u + (uint32_t)g * 65536u
                           + (uint32_t)((t >> 1) & 1) * 32768u;
        const uint32_t sKh = stg, sKv = stg + 8192;
        const uint32_t sVh = stg + 16384, sVv = stg + 24576;
        const float* smask = (const float*)(sbuf + 147456
                           + (g * 2 + ((t >> 1) & 1)) * 256);

        float sP[8][4], sS[8][4];
#pragma unroll
        for (int nt = 0; nt < 8; nt++)
#pragma unroll
            for (int r = 0; r < 4; r++) { sP[nt][r] = 0.0f; sS[nt][r] = 0.0f; }

#pragma unroll
        for (int ks = 0; ks < 4; ks++) {
            uint32_t kh[4][4], kv[4][4];
            int rowb = (ml >> 1) * 8 + lr;
            int u    = ks * 2 + (ml & 1);
#pragma unroll
            for (int gg = 0; gg < 4; gg++) {
                int row = gg * 16 + rowb;
                uint32_t off = off128(row, u);
                LDSM_X4(kh[gg][0], kh[gg][1], kh[gg][2], kh[gg][3], sKh + off);
                LDSM_X4(kv[gg][0], kv[gg][1], kv[gg][2], kv[gg][3], sKv + off);
            }
#pragma unroll
            for (int gg = 0; gg < 4; gg++)
#pragma unroll
                for (int j2 = 0; j2 < 2; j2++)
                    MMA16816H(sP[2 * gg + j2], qh[ks][0], qh[ks][1], qh[ks][2], qh[ks][3],
                              kh[gg][2 * j2], kh[gg][2 * j2 + 1]);
#pragma unroll
            for (int gg = 0; gg < 4; gg++)
#pragma unroll
                for (int j2 = 0; j2 < 2; j2++)
                    MMA16816H(sS[2 * gg + j2], qu[ks][0], qu[ks][1], qu[ks][2], qu[ks][3],
                              kv[gg][2 * j2], kv[gg][2 * j2 + 1]);
        }

        float sacc[8][4];
#pragma unroll
        for (int nt = 0; nt < 8; nt++)
#pragma unroll
            for (int r = 0; r < 4; r++)
                sacc[nt][r] = fmaf(BETA_C, sP[nt][r], sS[nt][r]);

        float rm0 = -INFINITY, rm1 = -INFINITY;
        if (t == qb) {
#pragma unroll
            for (int nt = 0; nt < 8; nt++) {
                int c0 = nt * 8 + cloc;
                float mk0 = smask[c0], mk1 = smask[c0 + 1];
                int jg0 = k0 + c0, jg1 = jg0 + 1;
                sacc[nt][0] = (jg0 > r0g     || mk0 == 0.0f) ? FILLV : sacc[nt][0];
                sacc[nt][1] = (jg1 > r0g     || mk1 == 0.0f) ? FILLV : sacc[nt][1];
                sacc[nt][2] = (jg0 > r0g + 8 || mk0 == 0.0f) ? FILLV : sacc[nt][2];
                sacc[nt][3] = (jg1 > r0g + 8 || mk1 == 0.0f) ? FILLV : sacc[nt][3];
                rm0 = fmaxf(rm0, fmaxf(sacc[nt][0], sacc[nt][1]));
                rm1 = fmaxf(rm1, fmaxf(sacc[nt][2], sacc[nt][3]));
            }
        } else {
#pragma unroll
            for (int nt = 0; nt < 8; nt++) {
                int c0 = nt * 8 + cloc;
                float mk0 = smask[c0], mk1 = smask[c0 + 1];
                sacc[nt][0] = (mk0 == 0.0f) ? FILLV : sacc[nt][0];
                sacc[nt][1] = (mk1 == 0.0f) ? FILLV : sacc[nt][1];
                sacc[nt][2] = (mk0 == 0.0f) ? FILLV : sacc[nt][2];
                sacc[nt][3] = (mk1 == 0.0f) ? FILLV : sacc[nt][3];
                rm0 = fmaxf(rm0, fmaxf(sacc[nt][0], sacc[nt][1]));
                rm1 = fmaxf(rm1, fmaxf(sacc[nt][2], sacc[nt][3]));
            }
        }
        rm0 = fmaxf(rm0, __shfl_xor_sync(0xffffffffu, rm0, 1));
        rm0 = fmaxf(rm0, __shfl_xor_sync(0xffffffffu, rm0, 2));
        rm1 = fmaxf(rm1, __shfl_xor_sync(0xffffffffu, rm1, 1));
        rm1 = fmaxf(rm1, __shfl_xor_sync(0xffffffffu, rm1, 2));

        float mn0 = fmaxf(m0, rm0), mn1 = fmaxf(m1, rm1);
        float corr0 = __expf(m0 - mn0), corr1 = __expf(m1 - mn1);
        m0 = mn0; m1 = mn1;

        float rs0 = 0.0f, rs1 = 0.0f;
#pragma unroll
        for (int nt = 0; nt < 8; nt++) {
            sacc[nt][0] = __expf(sacc[nt][0] - mn0);
            sacc[nt][1] = __expf(sacc[nt][1] - mn0);
            sacc[nt][2] = __expf(sacc[nt][2] - mn1);
            sacc[nt][3] = __expf(sacc[nt][3] - mn1);
            rs0 += sacc[nt][0] + sacc[nt][1];
            rs1 += sacc[nt][2] + sacc[nt][3];
        }
        rs0 += __shfl_xor_sync(0xffffffffu, rs0, 1);
        rs0 += __shfl_xor_sync(0xffffffffu, rs0, 2);
        rs1 += __shfl_xor_sync(0xffffffffu, rs1, 1);
        rs1 += __shfl_xor_sync(0xffffffffu, rs1, 2);
        l0 = l0 * corr0 + rs0;
        l1 = l1 * corr1 + rs1;
#pragma unroll
        for (int ns = 0; ns < 8; ns++) {
            oP[ns][0] *= corr0; oP[ns][1] *= corr0;
            oP[ns][2] *= corr1; oP[ns][3] *= corr1;
            oS[ns][0] *= corr0; oS[ns][1] *= corr0;
            oS[ns][2] *= corr1; oS[ns][3] *= corr1;
        }

#pragma unroll
        for (int ks = 0; ks < 4; ks++) {
            uint32_t ph[4], pu[4];
            split2h(sacc[2 * ks][0],     sacc[2 * ks][1],     ph[0], pu[0]);
            split2h(sacc[2 * ks][2],     sacc[2 * ks][3],     ph[1], pu[1]);
            split2h(sacc[2 * ks + 1][0], sacc[2 * ks + 1][1], ph[2], pu[2]);
            split2h(sacc[2 * ks + 1][2], sacc[2 * ks + 1][3], ph[3], pu[3]);

            int rowv = ks * 16 + (ml & 1) * 8 + lr;
#pragma unroll
            for (int np = 0; np < 4; np++) {
                int u = np * 2 + (ml >> 1);
                uint32_t off = off128(rowv, u);
                uint32_t vh[4], vv[4];
                LDSM_X4_T(vh[0], vh[1], vh[2], vh[3], sVh + off);
                LDSM_X4_T(vv[0], vv[1], vv[2], vv[3], sVv + off);
                MMA16816H(oP[2 * np],     ph[0], ph[1], ph[2], ph[3], vh[0], vh[1]);
                MMA16816H(oP[2 * np + 1], ph[0], ph[1], ph[2], ph[3], vh[2], vh[3]);
                MMA16816H(oS[2 * np],     pu[0], pu[1], pu[2], pu[3], vv[0], vv[1]);
                MMA16816H(oS[2 * np + 1], pu[0], pu[1], pu[2], pu[3], vv[2], vv[3]);
            }
        }

        BAR_G(barid);
        issue_g(t + 4);
    }

    float oacc[8][4];
#pragma unroll
    for (int ns = 0; ns < 8; ns++)
#pragma unroll
        for (int r = 0; r < 4; r++)
            oacc[ns][r] = fmaf(BETA_C, oP[ns][r], oS[ns][r]);

    float* XM = (float*)(sbuf + XCH_M);
    float* XL = (float*)(sbuf + XCH_L);
    float* XO = (float*)(sbuf + XCH_O);
    const int rl = (w & 3) * 16 + (lane >> 2);

    if (g == 1) {
        if ((lane & 3) == 0) {
            XM[rl] = m0; XM[rl + 8] = m1;
            XL[rl] = l0; XL[rl + 8] = l1;
        }
#pragma unroll
        for (int ns = 0; ns < 8; ns++) {
            int col = ns * 8 + cloc;
            *(float2*)&XO[rl * 64 + col]       = make_float2(oacc[ns][0], oacc[ns][1]);
            *(float2*)&XO[(rl + 8) * 64 + col] = make_float2(oacc[ns][2], oacc[ns][3]);
        }
    }
    __syncthreads();
    if (g == 0) {
        float mB0 = XM[rl], mB1 = XM[rl + 8];
        float lB0 = XL[rl], lB1 = XL[rl + 8];
        float mm0 = fmaxf(m0, mB0), mm1 = fmaxf(m1, mB1);
        float a0 = __expf(m0 - mm0), b0f = __expf(mB0 - mm0);
        float a1 = __expf(m1 - mm1), b1f = __expf(mB1 - mm1);
        float li0 = 1.0f / (l0 * a0 + lB0 * b0f);
        float li1 = 1.0f / (l1 * a1 + lB1 * b1f);
#pragma unroll
        for (int ns = 0; ns < 8; ns++) {
            int col = ns * 8 + cloc;
            float2 ob0 = *(const float2*)&XO[rl * 64 + col];
            float2 ob1 = *(const float2*)&XO[(rl + 8) * 64 + col];
            float o00 = (oacc[ns][0] * a0 + ob0.x * b0f) * li0;
            float o01 = (oacc[ns][1] * a0 + ob0.y * b0f) * li0;
            float o10 = (oacc[ns][2] * a1 + ob1.x * b1f) * li1;
            float o11 = (oacc[ns][3] * a1 + ob1.y * b1f) * li1;
            uint32_t hh, uu;
            split2h(o00, o01, hh, uu);
            *(uint32_t*)(Ahp + base + (size_t)(q0 + rl) * HID + col) = hh;
            *(uint32_t*)(Aup + base + (size_t)(q0 + rl) * HID + col) = uu;
            split2h(o10, o11, hh, uu);
            *(uint32_t*)(Ahp + base + (size_t)(q0 + rl + 8) * HID + col) = hh;
            *(uint32_t*)(Aup + base + (size_t)(q0 + rl + 8) * HID + col) = uu;
        }
    }
}

// ---------------------------------------------------------------------------
extern "C" void kernel_launch(void* const* d_in, const int* in_sizes, int n_in,
                              void* d_out, int out_size)
{
    const float* q    = (const float*)d_in[0];
    const float* k    = (const float*)d_in[1];
    const float* v    = (const float*)d_in[2];
    const float* mask = (const float*)d_in[3];
    const float* Wq   = (const float*)d_in[4];
    const float* bq   = (const float*)d_in[5];
    const float* Wk   = (const float*)d_in[6];
    const float* bk   = (const float*)d_in[7];
    const float* Wv   = (const float*)d_in[8];
    const float* bv   = (const float*)d_in[9];
    const float* Wo   = (const float*)d_in[10];
    const float* bo   = (const float*)d_in[11];
    float* out = (float*)d_out;

    __half *xqh, *xqu, *xkh, *xku, *xvh, *xvu;
    __half *wqh, *wqv, *wkh, *wkv, *wvh, *wvv, *woh, *wov;
    __half *Q16h, *Q16u, *K16h, *K16v, *V16h, *V16v, *A16h, *A16u;
    cudaGetSymbolAddress((void**)&xqh, g_xqh); cudaGetSymbolAddress((void**)&xqu, g_xqu);
    cudaGetSymbolAddress((void**)&xkh, g_xkh); cudaGetSymbolAddress((void**)&xku, g_xku);
    cudaGetSymbolAddress((void**)&xvh, g_xvh); cudaGetSymbolAddress((void**)&xvu, g_xvu);
    cudaGetSymbolAddress((void**)&wqh, g_wqh); cudaGetSymbolAddress((void**)&wqv, g_wqv);
    cudaGetSymbolAddress((void**)&wkh, g_wkh); cudaGetSymbolAddress((void**)&wkv, g_wkv);
    cudaGetSymbolAddress((void**)&wvh, g_wvh); cudaGetSymbolAddress((void**)&wvv, g_wvv);
    cudaGetSymbolAddress((void**)&woh, g_woh); cudaGetSymbolAddress((void**)&wov, g_wov);
    cudaGetSymbolAddress((void**)&Q16h, g_Q16h); cudaGetSymbolAddress((void**)&Q16u, g_Q16u);
    cudaGetSymbolAddress((void**)&K16h, g_K16h); cudaGetSymbolAddress((void**)&K16v, g_K16v);
    cudaGetSymbolAddress((void**)&V16h, g_V16h); cudaGetSymbolAddress((void**)&V16v, g_V16v);
    cudaGetSymbolAddress((void**)&A16h, g_A16h); cudaGetSymbolAddress((void**)&A16u, g_A16u);

    cudaFuncSetAttribute(flash_sk, cudaFuncAttributeMaxDynamicSharedMemorySize,
                         FLASH_SMEM);
    cudaFuncSetAttribute(gemm_h4, cudaFuncAttributeMaxDynamicSharedMemorySize,
                         GEMM_SMEM3);

    const int n4x = M_TOT * HID / 4;
    const int n4w = HID * HID / 4;

    SplitBatch sbt;
    sbt.src[0] = q;  sbt.dh[0] = xqh; sbt.du[0] = xqu; sbt.n4[0] = n4x;
    sbt.src[1] = k;  sbt.dh[1] = xkh; sbt.du[1] = xku; sbt.n4[1] = n4x;
    sbt.src[2] = v;  sbt.dh[2] = xvh; sbt.du[2] = xvu; sbt.n4[2] = n4x;
    sbt.src[3] = Wq; sbt.dh[3] = wqh; sbt.du[3] = wqv; sbt.n4[3] = n4w;
    sbt.src[4] = Wk; sbt.dh[4] = wkh; sbt.du[4] = wkv; sbt.n4[4] = n4w;
    sbt.src[5] = Wv; sbt.dh[5] = wvh; sbt.du[5] = wvv; sbt.n4[5] = n4w;
    sbt.src[6] = Wo; sbt.dh[6] = woh; sbt.du[6] = wov; sbt.n4[6] = n4w;
    split_all<<<dim3(n4x / 256, 7), 256>>>(sbt);

    GemmBatch gqkv = {};
    gqkv.ah[0] = xqh; gqkv.au[0] = xqu; gqkv.wh[0] = wqh; gqkv.wv[0] = wqv;
    gqkv.bias[0] = bq; gqkv.ch[0] = Q16h; gqkv.cu[0] = Q16u;
    gqkv.sc[0] = 0.125f; gqkv.mode[0] = 1;    // Q: A-side pair
    gqkv.ah[1] = xkh; gqkv.au[1] = xku; gqkv.wh[1] = wkh; gqkv.wv[1] = wkv;
    gqkv.bias[1] = bk; gqkv.ch[1] = K16h; gqkv.cu[1] = K16v;
    gqkv.sc[1] = 1.0f; gqkv.mode[1] = 2;      // K: B-side pair
    gqkv.ah[2] = xvh; gqkv.au[2] = xvu; gqkv.wh[2] = wvh; gqkv.wv[2] = wvv;
    gqkv.bias[2] = bv; gqkv.ch[2] = V16h; gqkv.cu[2] = V16v;
    gqkv.sc[2] = 1.0f; gqkv.mode[2] = 2;      // V: B-side pair
    gemm_h4<<<dim3(HID / 64, M_TOT / 128, 3), 256, GEMM_SMEM3>>>(gqkv);

    flash_sk<<<dim3(S_LEN / 64, NH, BATCH), 256, FLASH_SMEM>>>(
        Q16h, Q16u, K16h, K16v, V16h, V16v, mask, A16h, A16u);

    GemmBatch gout = {};
    gout.ah[0] = A16h; gout.au[0] = A16u; gout.wh[0] = woh; gout.wv[0] = wov;
    gout.bias[0] = bo; gout.c32[0] = out; gout.sc[0] = 1.0f; gout.mode[0] = 0;
    gemm_h4<<<dim3(HID / 64, M_TOT / 128, 1), 256, GEMM_SMEM3>>>(gout);
}